// round 12
// baseline (speedup 1.0000x reference)
#include <cuda_runtime.h>
#include <cuda_bf16.h>
#include <cstdint>

// ---------------------------------------------------------------------------
// MultiScaleMambaEncoder — mma.sync bf16 hi/lo x3 GEMMs + single-pass
// decoupled-lookback chunked scan with fused dt-proj/softplus.
// Layer-0 in_proj on 4096 unique rows; z-half of in_proj on a side stream.
// ---------------------------------------------------------------------------

#define BB 4
#define CC 512
#define DIN 1024
#define RTOK 8192

// fp32 scratch
__device__ float g_xz[RTOK * 2 * DIN];
__device__ float g_x[RTOK * DIN];          // conv output, then ylin
__device__ float g_xdbl[RTOK * 64];
__device__ float g_xdblp[8 * RTOK * 64];   // split-K partials
__device__ float g_hch[16 * 128 * 1024];   // published h_out per chunk
__device__ float g_delta[RTOK * DIN];      // written by scanF pass A
__device__ float g_o[RTOK * CC];
__device__ int   g_flag[1024];             // lookback flags
// bf16 hi/lo scratch (GEMM A operands)
__device__ __nv_bfloat16 g_ah[RTOK * DIN];
__device__ __nv_bfloat16 g_al[RTOK * DIN];
__device__ __nv_bfloat16 g_wih[6 * 2048 * 512];
__device__ __nv_bfloat16 g_wil[6 * 2048 * 512];
__device__ __nv_bfloat16 g_woh[6 * 512 * 1024];
__device__ __nv_bfloat16 g_wol[6 * 512 * 1024];

__device__ __forceinline__ int wsel4(int ml, int w0, int w1, int w2, int w3) {
    return ml == 0 ? w0 : ml == 1 ? w1 : ml == 2 ? w2 : w3;
}

#define FMA2(d, a, b) asm("fma.rn.f32x2 %0, %1, %2, %0;" : "+l"(d) : "l"(a), "l"(b))
#define DUP2(d, s)    asm("mov.b64 %0, {%1, %1};" : "=l"(d) : "f"(s))

__device__ __forceinline__ uint32_t smem_u32(const void* p) {
    uint32_t a;
    asm("{ .reg .u64 t; cvta.to.shared.u64 t, %1; cvt.u32.u64 %0, t; }" : "=r"(a) : "l"(p));
    return a;
}
#define CP16(dst, src)  asm volatile("cp.async.cg.shared.global [%0], [%1], 16;" :: "r"(dst), "l"(src))
#define CP_COMMIT()     asm volatile("cp.async.commit_group;" ::: "memory")
#define CP_WAIT0()      asm volatile("cp.async.wait_group 0;" ::: "memory")

#define LDM4(r0, r1, r2, r3, a) \
    asm volatile("ldmatrix.sync.aligned.m8n8.x4.shared.b16 {%0,%1,%2,%3}, [%4];" \
                 : "=r"(r0), "=r"(r1), "=r"(r2), "=r"(r3) : "r"(a))
#define LDM2(r0, r1, a) \
    asm volatile("ldmatrix.sync.aligned.m8n8.x2.shared.b16 {%0,%1}, [%2];" \
                 : "=r"(r0), "=r"(r1) : "r"(a))
#define MMA16816(d, a, b) \
    asm volatile("mma.sync.aligned.m16n8k16.row.col.f32.bf16.bf16.f32 " \
                 "{%0,%1,%2,%3},{%4,%5,%6,%7},{%8,%9},{%0,%1,%2,%3};" \
                 : "+f"((d)[0]), "+f"((d)[1]), "+f"((d)[2]), "+f"((d)[3]) \
                 : "r"((a)[0]), "r"((a)[1]), "r"((a)[2]), "r"((a)[3]), \
                   "r"((b)[0]), "r"((b)[1]))

__device__ __forceinline__ void hilo(float v, __nv_bfloat16& h, __nv_bfloat16& l) {
    h = __float2bfloat16(v);
    l = __float2bfloat16(v - __bfloat162float(h));
}
// powers: p[s] = e1^(s+1), depth-4 ladder
__device__ __forceinline__ void powers16(float e1, float* p) {
    float e2 = e1 * e1, e4 = e2 * e2, e8 = e4 * e4;
    p[0] = e1;        p[1] = e2;        p[2] = e2 * e1;   p[3] = e4;
    p[4] = e4 * e1;   p[5] = e4 * e2;   p[6] = e4 * p[2]; p[7] = e8;
    p[8] = e8 * e1;   p[9] = e8 * e2;   p[10] = e8 * p[2]; p[11] = e8 * e4;
    p[12] = e8 * p[4]; p[13] = e8 * p[5]; p[14] = e8 * p[6]; p[15] = e8 * e8;
}
// layer-0 xz row map: r in [0,8192) -> unique row in [0,4096)
__device__ __forceinline__ int xzrow(int r, int dup) {
    if (!dup) return r;
    int t = r & 511;
    int tt = t < 256 ? t : 511 - t;
    return ((r >> 9) << 8) + tt;
}

// ---------------------------------------------------------------------------
__global__ void k_cvt(const float* __restrict__ src, __nv_bfloat16* __restrict__ hi,
                      __nv_bfloat16* __restrict__ lo, int n) {
    int i = blockIdx.x * blockDim.x + threadIdx.x;
    if (i >= n) return;
    float v = src[i];
    hilo(v, hi[i], lo[i]);
}

// layer-0 compact inputs: 4096 unique rows = (slot, b, t<256)
__global__ void k_build4(const float* __restrict__ s0, const float* __restrict__ s1,
                         const float* __restrict__ s2, const float* __restrict__ s3) {
    int idx = blockIdx.x * blockDim.x + threadIdx.x;
    if (idx >= 4096 * CC) return;
    int c = idx & (CC - 1);
    int r = idx >> 9;
    int slot = r >> 10;
    const float* s = slot == 0 ? s0 : slot == 1 ? s1 : slot == 2 ? s2 : s3;
    float v = s[(r & 1023) * CC + c];
    hilo(v, g_ah[idx], g_al[idx]);
}

// ---------------------------------------------------------------------------
// mma.sync GEMM: C = A * W^T (bf16 hi/lo x3), 128x128 tile, BK=32,
// 2-stage cp.async double buffer, 2 CTAs/SM.
// ---------------------------------------------------------------------------
#define MM_STAGE 40960
#define MM_TILE  10240

__global__ __launch_bounds__(256, 2) void k_mma(
    const __nv_bfloat16* __restrict__ Ah, const __nv_bfloat16* __restrict__ Al,
    const __nv_bfloat16* __restrict__ WhB, const __nv_bfloat16* __restrict__ WlB,
    float* __restrict__ C, int K, int ldc,
    int rpg, int wstride, int w0, int w1, int w2, int w3) {
    extern __shared__ __align__(128) uint8_t smraw[];
    const uint32_t smb = smem_u32(smraw);
    const int tid = threadIdx.x;
    const int wid = tid >> 5;
    const int lane = tid & 31;
    const int wm = wid >> 2;
    const int wn = wid & 3;
    const int row0 = blockIdx.y * 128;
    const int col0 = blockIdx.x * 128;
    const int wsel = wsel4(row0 / rpg, w0, w1, w2, w3);
    const __nv_bfloat16* Wh = WhB + (size_t)wsel * wstride;
    const __nv_bfloat16* Wl = WlB + (size_t)wsel * wstride;
    const int nc = K >> 5;

    float acc[4][4][4];
#pragma unroll
    for (int i = 0; i < 4; i++)
#pragma unroll
        for (int j = 0; j < 4; j++)
#pragma unroll
            for (int q = 0; q < 4; q++) acc[i][j][q] = 0.f;

    auto load_stage = [&](int kc, int st) {
        const int k0 = kc << 5;
        const uint32_t sb = smb + st * MM_STAGE;
#pragma unroll
        for (int p = 0; p < 8; p++) {
            int u = tid + (p << 8);
            int tile = u >> 9;
            int v = u & 511;
            int r = v >> 2, seg = v & 3;
            const __nv_bfloat16* src;
            if (tile == 0)      src = Ah + (size_t)(row0 + r) * K;
            else if (tile == 1) src = Al + (size_t)(row0 + r) * K;
            else if (tile == 2) src = Wh + (size_t)(col0 + r) * K;
            else                src = Wl + (size_t)(col0 + r) * K;
            CP16(sb + tile * MM_TILE + r * 80 + seg * 16, src + k0 + seg * 8);
        }
        CP_COMMIT();
    };

    load_stage(0, 0);
    CP_WAIT0();
    __syncthreads();

    const uint32_t aRowByte = (uint32_t)(wm * 64 + (lane & 15)) * 80 + ((lane >> 4) << 4);
    const uint32_t bRowByte = (uint32_t)(wn * 32 + (lane & 7)) * 80 + (((lane >> 3) & 1) << 4);

    for (int c = 0; c < nc; c++) {
        const int st = c & 1;
        if (c + 1 < nc) load_stage(c + 1, st ^ 1);
        const uint32_t sb = smb + st * MM_STAGE;
#pragma unroll
        for (int ks = 0; ks < 2; ks++) {
            uint32_t ah[4][4], al[4][4], bh[4][2], bl[4][2];
            const uint32_t kb = ks * 32;
#pragma unroll
            for (int mi = 0; mi < 4; mi++) {
                uint32_t ra = sb + aRowByte + (uint32_t)mi * 16 * 80 + kb;
                LDM4(ah[mi][0], ah[mi][1], ah[mi][2], ah[mi][3], ra);
                LDM4(al[mi][0], al[mi][1], al[mi][2], al[mi][3], ra + MM_TILE);
            }
#pragma unroll
            for (int ni = 0; ni < 4; ni++) {
                uint32_t rb = sb + 2 * MM_TILE + bRowByte + (uint32_t)ni * 8 * 80 + kb;
                LDM2(bh[ni][0], bh[ni][1], rb);
                LDM2(bl[ni][0], bl[ni][1], rb + MM_TILE);
            }
#pragma unroll
            for (int mi = 0; mi < 4; mi++)
#pragma unroll
                for (int ni = 0; ni < 4; ni++) {
                    MMA16816(acc[mi][ni], ah[mi], bh[ni]);
                    MMA16816(acc[mi][ni], ah[mi], bl[ni]);
                    MMA16816(acc[mi][ni], al[mi], bh[ni]);
                }
        }
        if (c + 1 < nc) CP_WAIT0();
        __syncthreads();
    }

    const int gr = lane >> 2;
    const int gc = (lane & 3) * 2;
#pragma unroll
    for (int mi = 0; mi < 4; mi++)
#pragma unroll
        for (int ni = 0; ni < 4; ni++) {
            int row = row0 + wm * 64 + mi * 16 + gr;
            int col = col0 + wn * 32 + ni * 8 + gc;
            float* p0 = C + (size_t)row * ldc + col;
            float* p1 = C + (size_t)(row + 8) * ldc + col;
            *(float2*)p0 = make_float2(acc[mi][ni][0], acc[mi][ni][1]);
            *(float2*)p1 = make_float2(acc[mi][ni][2], acc[mi][ni][3]);
        }
}

// ---------------------------------------------------------------------------
// 64x64 FFMA2 GEMM body (x_proj split-K)
// ---------------------------------------------------------------------------
__device__ __forceinline__ void gemm64_accum(
    const float* A, const float* W, unsigned long long acc[4][2],
    int K, int lda, int ldb, int row0, int col0) {
    __shared__ float As[16][68];
    __shared__ float Bs[16][68];
    const int tid = threadIdx.x;
    const int tx = tid & 15, ty = tid >> 4;
    for (int k0 = 0; k0 < K; k0 += 16) {
        __syncthreads();
#pragma unroll
        for (int i = 0; i < 4; i++) {
            int idx = tid + i * 256;
            int kk = idx & 15, rr = idx >> 4;
            As[kk][rr] = A[(size_t)(row0 + rr) * lda + k0 + kk];
            Bs[kk][rr] = W[(size_t)(col0 + rr) * ldb + k0 + kk];
        }
        __syncthreads();
#pragma unroll
        for (int kk = 0; kk < 16; kk++) {
            float a[4];
            *(float4*)a = *(const float4*)&As[kk][ty * 4];
            unsigned long long b2[2];
            *(float4*)b2 = *(const float4*)&Bs[kk][tx * 4];
#pragma unroll
            for (int i = 0; i < 4; i++) {
                unsigned long long ad;
                DUP2(ad, a[i]);
                FMA2(acc[i][0], ad, b2[0]);
                FMA2(acc[i][1], ad, b2[1]);
            }
        }
    }
}

// x_proj split-K (8 slices of K=128)
__global__ __launch_bounds__(256) void k_gemm64sk(
    const float* __restrict__ A, const float* __restrict__ Wb,
    int rpg, int wstride, int w0, int w1, int w2, int w3) {
    const int row0 = blockIdx.y * 64;
    const int z = blockIdx.z;
    const int wsel = wsel4(row0 / rpg, w0, w1, w2, w3);
    const float* W = Wb + (size_t)wsel * wstride + z * 128;
    unsigned long long acc[4][2];
#pragma unroll
    for (int i = 0; i < 4; i++) { acc[i][0] = 0ull; acc[i][1] = 0ull; }
    gemm64_accum(A + z * 128, W, acc, 128, 1024, 1024, row0, 0);
    float* Cout = g_xdblp + (size_t)z * RTOK * 64;
    const int tx = threadIdx.x & 15, ty = threadIdx.x >> 4;
#pragma unroll
    for (int i = 0; i < 4; i++) {
        float* cp = Cout + (size_t)(row0 + ty * 4 + i) * 64 + tx * 4;
        *(ulonglong2*)cp = make_ulonglong2(acc[i][0], acc[i][1]);
    }
}

// reduce split-K partials; also zero lookback flags for the next scan
__global__ void k_reduce8() {
    int idx = blockIdx.x * blockDim.x + threadIdx.x;
    if (idx < 1024) g_flag[idx] = 0;
    if (idx >= RTOK * 64) return;
    const int S = RTOK * 64;
    float a0 = g_xdblp[idx] + g_xdblp[idx + S];
    float a1 = g_xdblp[idx + 2 * S] + g_xdblp[idx + 3 * S];
    float a2 = g_xdblp[idx + 4 * S] + g_xdblp[idx + 5 * S];
    float a3 = g_xdblp[idx + 6 * S] + g_xdblp[idx + 7 * S];
    g_xdbl[idx] = (a0 + a1) + (a2 + a3);
}

// ---------------------------------------------------------------------------
// causal depthwise conv (4 taps) + bias + SiLU. dup=1: layer-0 compact-xz map.
// ---------------------------------------------------------------------------
__global__ void k_conv(const float* __restrict__ cw, const float* __restrict__ cb,
                       int T, int rpg, int w0, int w1, int w2, int w3, int dup) {
    int idx = blockIdx.x * blockDim.x + threadIdx.x;
    if (idx >= RTOK * DIN) return;
    int d = idx & (DIN - 1);
    int r = idx >> 10;
    int t = r & (T - 1);
    int m = wsel4(r / rpg, w0, w1, w2, w3);
    const float* cwp = cw + ((size_t)m * DIN + d) * 4;
    float acc = cb[m * DIN + d];
#pragma unroll
    for (int k = 0; k < 4; k++) {
        int tt = t - 3 + k;
        if (tt >= 0) {
            int row = xzrow(r + tt - t, dup);
            acc = fmaf(cwp[k], g_xz[(size_t)row * (2 * DIN) + d], acc);
        }
    }
    float e = __expf(-acc);
    g_x[idx] = __fdividef(acc, 1.f + e);
}

// ---------------------------------------------------------------------------
// Fused chunked scan with decoupled lookback + fused dt-proj/softplus.
// Pass A: delta computed inline from xdbl[0:32]·dtw + dtb (stored for pass C);
// local scan; publish h_out; spin for predecessor; correction + gate.
// ---------------------------------------------------------------------------
template <bool CHAIN>
__device__ __forceinline__ void scanF_body(int rbase, int d, int g, int j,
                                           int blk, int dup,
                                           const float* __restrict__ dtwv,
                                           float dtbv,
                                           const float Av[16], float Dv) {
    const int tid = threadIdx.x;
    // dtw row: 32 floats, coalesced per-thread 128B
    float wv[32];
#pragma unroll
    for (int q = 0; q < 8; q++) *(float4*)(wv + q * 4) = ((const float4*)dtwv)[q];

    float h[16];
#pragma unroll
    for (int s = 0; s < 16; s++) h[s] = 0.f;
    float dsum = 0.f;
    // ---- local scan (h0 = 0); ylin (incl. D*x) overwrites g_x
#pragma unroll 2
    for (int t = 0; t < 64; t++) {
        int r = rbase + t;
        float xv = g_x[(size_t)r * DIN + d];
        const float4* xr = (const float4*)(g_xdbl + (size_t)r * 64);
        float4 Dq[8], Bq[4], Cq[4];
#pragma unroll
        for (int q = 0; q < 8; q++) Dq[q] = xr[q];
#pragma unroll
        for (int q = 0; q < 4; q++) { Bq[q] = xr[q + 8]; Cq[q] = xr[q + 12]; }
        const float* dtv = (const float*)Dq;
        const float* Bv = (const float*)Bq;
        const float* Cv = (const float*)Cq;
        // delta = softplus(dot32 + dtb)
        float a0 = 0.f, a1 = 0.f, a2 = 0.f, a3 = 0.f;
#pragma unroll
        for (int q = 0; q < 8; q++) {
            a0 = fmaf(dtv[q * 4 + 0], wv[q * 4 + 0], a0);
            a1 = fmaf(dtv[q * 4 + 1], wv[q * 4 + 1], a1);
            a2 = fmaf(dtv[q * 4 + 2], wv[q * 4 + 2], a2);
            a3 = fmaf(dtv[q * 4 + 3], wv[q * 4 + 3], a3);
        }
        float dpre = ((a0 + a1) + (a2 + a3)) + dtbv;
        float delta = (dpre > 15.f) ? dpre : __logf(1.f + __expf(dpre));
        g_delta[(size_t)r * DIN + d] = delta;
        dsum += delta;
        float p[16];
        if (CHAIN) powers16(__expf(delta * Av[0]), p);
        else {
#pragma unroll
            for (int s = 0; s < 16; s++) p[s] = __expf(delta * Av[s]);
        }
        float dx = delta * xv;
        float y0 = 0.f, y1 = 0.f, y2 = 0.f, y3 = 0.f;
#pragma unroll
        for (int s = 0; s < 16; s++) {
            h[s] = fmaf(h[s], p[s], dx * Bv[s]);
            float hv = h[s] * Cv[s];
            if ((s & 3) == 0) y0 += hv;
            else if ((s & 3) == 1) y1 += hv;
            else if ((s & 3) == 2) y2 += hv;
            else y3 += hv;
        }
        g_x[(size_t)r * DIN + d] = fmaf(Dv, xv, (y0 + y1) + (y2 + y3));
    }

    float hin[16];
    if (j == 0) {
#pragma unroll
        for (int s = 0; s < 16; s++)
            g_hch[((size_t)(s * 128 + g) << 10) + d] = h[s];
        __threadfence();
        __syncthreads();
        if (tid == 0) atomicExch(&g_flag[blk], 1);
#pragma unroll 2
        for (int t = 0; t < 64; t++) {
            int r = rbase + t;
            float zv = g_xz[(size_t)xzrow(r, dup) * 2048 + 1024 + d];
            float ylin = g_x[(size_t)r * DIN + d];
            float sg = __fdividef(zv, 1.f + __expf(-zv));
            float yv = ylin * sg;
            hilo(yv, g_ah[(size_t)r * DIN + d], g_al[(size_t)r * DIN + d]);
        }
        return;
    }

    float P[16];
    if (CHAIN) powers16(__expf(dsum * Av[0]), P);
    else {
#pragma unroll
        for (int s = 0; s < 16; s++) P[s] = __expf(dsum * Av[s]);
    }
    if (tid == 0) {
        while (atomicAdd(&g_flag[blk - 8], 0) == 0) __nanosleep(32);
    }
    __syncthreads();
    __threadfence();
#pragma unroll
    for (int s = 0; s < 16; s++)
        hin[s] = g_hch[((size_t)(s * 128 + (g - 1)) << 10) + d];
#pragma unroll
    for (int s = 0; s < 16; s++)
        g_hch[((size_t)(s * 128 + g) << 10) + d] = fmaf(P[s], hin[s], h[s]);
    __threadfence();
    __syncthreads();
    if (tid == 0) atomicExch(&g_flag[blk], 1);

    // ---- correction + gate (delta from pass A, L2-hot)
    float q[16];
#pragma unroll
    for (int s = 0; s < 16; s++) q[s] = hin[s];
#pragma unroll 2
    for (int t = 0; t < 64; t++) {
        int r = rbase + t;
        float delta = g_delta[(size_t)r * DIN + d];
        float zv = g_xz[(size_t)xzrow(r, dup) * 2048 + 1024 + d];
        float ylin = g_x[(size_t)r * DIN + d];
        const float4* cp = (const float4*)(g_xdbl + (size_t)r * 64 + 48);
        float4 Cq[4];
#pragma unroll
        for (int u = 0; u < 4; u++) Cq[u] = cp[u];
        const float* Cv = (const float*)Cq;
        float p[16];
        if (CHAIN) powers16(__expf(delta * Av[0]), p);
        else {
#pragma unroll
            for (int s = 0; s < 16; s++) p[s] = __expf(delta * Av[s]);
        }
        float c0 = 0.f, c1 = 0.f, c2 = 0.f, c3 = 0.f;
#pragma unroll
        for (int s = 0; s < 16; s++) {
            q[s] *= p[s];
            float hv = q[s] * Cv[s];
            if ((s & 3) == 0) c0 += hv;
            else if ((s & 3) == 1) c1 += hv;
            else if ((s & 3) == 2) c2 += hv;
            else c3 += hv;
        }
        float y = ylin + (c0 + c1) + (c2 + c3);
        float sg = __fdividef(zv, 1.f + __expf(-zv));
        float yv = y * sg;
        hilo(yv, g_ah[(size_t)r * DIN + d], g_al[(size_t)r * DIN + d]);
    }
}

__global__ __launch_bounds__(128) void k_scanF(const float* __restrict__ Alog,
                                               const float* __restrict__ Dp,
                                               const float* __restrict__ dtw,
                                               const float* __restrict__ dtb,
                                               int lgNCH, int w0, int w1, int w2, int w3,
                                               int dup) {
    int blk = blockIdx.x;
    int dg = blk & 7;
    int g = blk >> 3;
    int seq = g >> lgNCH;
    int j = g & ((1 << lgNCH) - 1);
    int d = (dg << 7) | threadIdx.x;
    int m = wsel4(seq >> 2, w0, w1, w2, w3);
    float Av[16];
    const float* ap = Alog + ((size_t)m * DIN + d) * 16;
#pragma unroll
    for (int s = 0; s < 16; s++) Av[s] = -__expf(ap[s]);
    bool chain = true;
#pragma unroll
    for (int s = 1; s < 16; s++)
        chain = chain &&
                (fabsf(Av[s] - (float)(s + 1) * Av[0]) <=
                 1e-3f * (float)(s + 1) * fabsf(Av[0]) + 1e-7f);
    float Dv = Dp[m * DIN + d];
    const float* dtwv = dtw + ((size_t)m * DIN + d) * 32;
    float dtbv = dtb[m * DIN + d];
    int rbase = g << 6;
    if (chain) scanF_body<true>(rbase, d, g, j, blk, dup, dtwv, dtbv, Av, Dv);
    else       scanF_body<false>(rbase, d, g, j, blk, dup, dtwv, dtbv, Av, Dv);
}

// ---------------------------------------------------------------------------
// layer-0 epilogue: fold halves, layernorm, residual; emit layer-1 GEMM input
// (forward + reversed copies) directly as bf16 hi/lo.
// ---------------------------------------------------------------------------
__global__ __launch_bounds__(128) void k_combine(
    const float* __restrict__ s0, const float* __restrict__ s1,
    const float* __restrict__ s2, const float* __restrict__ s3,
    const float* __restrict__ lnw, const float* __restrict__ lnb) {
    int blk = blockIdx.x;
    int t = blk & 255;
    int b = (blk >> 8) & 3;
    int slot = blk >> 10;
    const float* src = slot == 0 ? s0 : slot == 1 ? s1 : slot == 2 ? s2 : s3;
    int rowA = ((slot * 4 + b) * 512 + t) * CC;
    int rowB = ((slot * 4 + b) * 512 + (511 - t)) * CC;
    int tid = threadIdx.x;
    float v[4];
#pragma unroll
    for (int j = 0; j < 4; j++) {
        int c = tid + j * 128;
        v[j] = 0.5f * (g_o[rowA + c] + g_o[rowB + c]);
    }
    __shared__ float red[8];
    int wid = tid >> 5, lane = tid & 31;
    float s = (v[0] + v[1]) + (v[2] + v[3]);
#pragma unroll
    for (int o = 16; o; o >>= 1) s += __shfl_xor_sync(~0u, s, o);
    if (lane == 0) red[wid] = s;
    __syncthreads();
    float mean = (red[0] + red[1] + red[2] + red[3]) * (1.f / 512.f);
    float q = 0.f;
#pragma unroll
    for (int j = 0; j < 4; j++) { float dd = v[j] - mean; q = fmaf(dd, dd, q); }
#pragma unroll
    for (int o = 16; o; o >>= 1) q += __shfl_xor_sync(~0u, q, o);
    if (lane == 0) red[4 + wid] = q;
    __syncthreads();
    float var = (red[4] + red[5] + red[6] + red[7]) * (1.f / 512.f);
    float rstd = rsqrtf(var + 1e-5f);
    int tau = slot * 256 + t;
#pragma unroll
    for (int j = 0; j < 4; j++) {
        int c = tid + j * 128;
        float o = (v[j] - mean) * rstd * lnw[c] + lnb[c] + src[(b * 256 + t) * CC + c];
        __nv_bfloat16 hh, ll;
        hilo(o, hh, ll);
        int idxF = ((b * 1024) + tau) * CC + c;
        int idxR = (((4 + b) * 1024) + (1023 - tau)) * CC + c;
        g_ah[idxF] = hh; g_al[idxF] = ll;
        g_ah[idxR] = hh; g_al[idxR] = ll;
    }
}

__global__ void k_final(float* __restrict__ out) {
    int idx = blockIdx.x * blockDim.x + threadIdx.x;
    if (idx >= BB * 1024 * CC) return;
    int c = idx & (CC - 1);
    int rest = idx >> 9;
    int tau = rest & 1023;
    int b = rest >> 10;
    float f = 0.5f * (g_o[((b * 1024) + tau) * CC + c] +
                      g_o[(((4 + b) * 1024) + (1023 - tau)) * CC + c]);
    int i = tau >> 8;
    int t = tau & 255;
    out[(((i * 4 + b) * 256 + t) << 9) + c] = f;
}

// ---------------------------------------------------------------------------
extern "C" void kernel_launch(void* const* d_in, const int* in_sizes, int n_in,
                              void* d_out, int out_size) {
    const float* x0hw = (const float*)d_in[0];
    const float* x1hw = (const float*)d_in[1];
    const float* x0wh = (const float*)d_in[2];
    const float* x1wh = (const float*)d_in[3];
    const float* in_w = (const float*)d_in[4];
    const float* cw   = (const float*)d_in[5];
    const float* cb   = (const float*)d_in[6];
    const float* xw   = (const float*)d_in[7];
    const float* dtw  = (const float*)d_in[8];
    const float* dtb  = (const float*)d_in[9];
    const float* alog = (const float*)d_in[10];
    const float* Dp   = (const float*)d_in[11];
    const float* ow   = (const float*)d_in[12];
    const float* lnw  = (const float*)d_in[13];
    const float* lnb  = (const float*)d_in[14];
    float* out = (float*)d_out;

    float *pxz, *px, *po;
    cudaGetSymbolAddress((void**)&pxz, g_xz);
    cudaGetSymbolAddress((void**)&px, g_x);
    cudaGetSymbolAddress((void**)&po, g_o);
    __nv_bfloat16 *pah, *pal, *pwih, *pwil, *pwoh, *pwol;
    cudaGetSymbolAddress((void**)&pah, g_ah);
    cudaGetSymbolAddress((void**)&pal, g_al);
    cudaGetSymbolAddress((void**)&pwih, g_wih);
    cudaGetSymbolAddress((void**)&pwil, g_wil);
    cudaGetSymbolAddress((void**)&pwoh, g_woh);
    cudaGetSymbolAddress((void**)&pwol, g_wol);

    static int inited = 0;
    static cudaStream_t s2;
    static cudaEvent_t evX0, evZ0, evX1, evZ1;
    if (!inited) {
        cudaFuncSetAttribute(k_mma, cudaFuncAttributeMaxDynamicSharedMemorySize,
                             2 * MM_STAGE);
        cudaStreamCreateWithFlags(&s2, cudaStreamNonBlocking);
        cudaEventCreateWithFlags(&evX0, cudaEventDisableTiming);
        cudaEventCreateWithFlags(&evZ0, cudaEventDisableTiming);
        cudaEventCreateWithFlags(&evX1, cudaEventDisableTiming);
        cudaEventCreateWithFlags(&evZ1, cudaEventDisableTiming);
        inited = 1;
    }
    const int MMSMEM = 2 * MM_STAGE;

    const int EL = RTOK * DIN;
    const int ELF = BB * 1024 * CC;
    const size_t ZW = (size_t)1024 * 512;

    // weights -> bf16 hi/lo
    k_cvt<<<(6 * 2048 * 512 + 255) / 256, 256>>>(in_w, pwih, pwil, 6 * 2048 * 512);
    k_cvt<<<(6 * 512 * 1024 + 255) / 256, 256>>>(ow, pwoh, pwol, 6 * 512 * 1024);

    // ---------------- layer 0 (T=512, NCH=8; compact in_proj) ---------------
    {
        const int w0 = 0, w1 = 2, w2 = 1, w3 = 3, rpg = 2048, T = 512, lg = 3;
        k_build4<<<(4096 * CC + 255) / 256, 256>>>(x0hw, x1hw, x0wh, x1wh);
        k_mma<<<dim3(8, 32), 256, MMSMEM>>>(
            pah, pal, pwih, pwil, pxz, 512, 2048, 1024, 2048 * 512, w0, w1, w2, w3);
        cudaEventRecord(evX0, 0);
        cudaStreamWaitEvent(s2, evX0, 0);
        k_mma<<<dim3(8, 32), 256, MMSMEM, s2>>>(
            pah, pal, pwih + ZW, pwil + ZW, pxz + 1024, 512, 2048,
            1024, 2048 * 512, w0, w1, w2, w3);
        cudaEventRecord(evZ0, s2);
        k_conv<<<(EL + 255) / 256, 256>>>(cw, cb, T, rpg, w0, w1, w2, w3, 1);
        k_gemm64sk<<<dim3(1, RTOK / 64, 8), 256>>>(px, xw, rpg, 64 * 1024, w0, w1, w2, w3);
        k_reduce8<<<(RTOK * 64 + 255) / 256, 256>>>();
        cudaStreamWaitEvent(0, evZ0, 0);   // scanF gates with z
        k_scanF<<<1024, 128>>>(alog, Dp, dtw, dtb, lg, w0, w1, w2, w3, 1);
        k_mma<<<dim3(4, 64), 256, MMSMEM>>>(
            pah, pal, pwoh, pwol, po, 1024, 512, rpg, 512 * 1024, w0, w1, w2, w3);
        k_combine<<<4096, 128>>>(x0hw, x1hw, x0wh, x1wh, lnw, lnb);
    }

    // ---------------- layer 1 (T=1024, NCH=16) ----------------
    {
        const int w0 = 4, w1 = 5, w2 = 4, w3 = 5, rpg = 4096, T = 1024, lg = 4;
        k_mma<<<dim3(8, 64), 256, MMSMEM>>>(
            pah, pal, pwih, pwil, pxz, 512, 2048, rpg, 2048 * 512, w0, w1, w2, w3);
        cudaEventRecord(evX1, 0);
        cudaStreamWaitEvent(s2, evX1, 0);
        k_mma<<<dim3(8, 64), 256, MMSMEM, s2>>>(
            pah, pal, pwih + ZW, pwil + ZW, pxz + 1024, 512, 2048,
            rpg, 2048 * 512, w0, w1, w2, w3);
        cudaEventRecord(evZ1, s2);
        k_conv<<<(EL + 255) / 256, 256>>>(cw, cb, T, rpg, w0, w1, w2, w3, 0);
        k_gemm64sk<<<dim3(1, RTOK / 64, 8), 256>>>(px, xw, rpg, 64 * 1024, w0, w1, w2, w3);
        k_reduce8<<<(RTOK * 64 + 255) / 256, 256>>>();
        cudaStreamWaitEvent(0, evZ1, 0);
        k_scanF<<<1024, 128>>>(alog, Dp, dtw, dtb, lg, w0, w1, w2, w3, 0);
        k_mma<<<dim3(4, 64), 256, MMSMEM>>>(
            pah, pal, pwoh, pwol, po, 1024, 512, rpg, 512 * 1024, w0, w1, w2, w3);
        k_final<<<(ELF + 255) / 256, 256>>>(out);
    }
}

// round 13
// speedup vs baseline: 1.0958x; 1.0958x over previous
#include <cuda_runtime.h>
#include <cuda_bf16.h>
#include <cstdint>

// ---------------------------------------------------------------------------
// MultiScaleMambaEncoder — mma.sync bf16 hi/lo x3 GEMMs + single-pass
// decoupled-lookback chunked scan. Layer-0 in_proj on 4096 unique rows;
// z-half of in_proj on a side stream. (R11 structure + e1-caching in scanF.)
// ---------------------------------------------------------------------------

#define BB 4
#define CC 512
#define DIN 1024
#define RTOK 8192

// fp32 scratch
__device__ float g_xz[RTOK * 2 * DIN];
__device__ float g_x[RTOK * DIN];          // conv output, then ylin
__device__ float g_xdbl[RTOK * 64];
__device__ float g_xdblp[8 * RTOK * 64];   // split-K partials
__device__ float g_hch[16 * 128 * 1024];   // published h_out per chunk
__device__ float g_delta[RTOK * DIN];      // delta; pass A rewrites e1 (chain)
__device__ float g_o[RTOK * CC];
__device__ int   g_flag[1024];             // lookback flags
// bf16 hi/lo scratch (GEMM A operands)
__device__ __nv_bfloat16 g_ah[RTOK * DIN];
__device__ __nv_bfloat16 g_al[RTOK * DIN];
__device__ __nv_bfloat16 g_wih[6 * 2048 * 512];
__device__ __nv_bfloat16 g_wil[6 * 2048 * 512];
__device__ __nv_bfloat16 g_woh[6 * 512 * 1024];
__device__ __nv_bfloat16 g_wol[6 * 512 * 1024];

__device__ __forceinline__ int wsel4(int ml, int w0, int w1, int w2, int w3) {
    return ml == 0 ? w0 : ml == 1 ? w1 : ml == 2 ? w2 : w3;
}

#define FMA2(d, a, b) asm("fma.rn.f32x2 %0, %1, %2, %0;" : "+l"(d) : "l"(a), "l"(b))
#define DUP2(d, s)    asm("mov.b64 %0, {%1, %1};" : "=l"(d) : "f"(s))

__device__ __forceinline__ uint32_t smem_u32(const void* p) {
    uint32_t a;
    asm("{ .reg .u64 t; cvta.to.shared.u64 t, %1; cvt.u32.u64 %0, t; }" : "=r"(a) : "l"(p));
    return a;
}
#define CP16(dst, src)  asm volatile("cp.async.cg.shared.global [%0], [%1], 16;" :: "r"(dst), "l"(src))
#define CP_COMMIT()     asm volatile("cp.async.commit_group;" ::: "memory")
#define CP_WAIT0()      asm volatile("cp.async.wait_group 0;" ::: "memory")

#define LDM4(r0, r1, r2, r3, a) \
    asm volatile("ldmatrix.sync.aligned.m8n8.x4.shared.b16 {%0,%1,%2,%3}, [%4];" \
                 : "=r"(r0), "=r"(r1), "=r"(r2), "=r"(r3) : "r"(a))
#define LDM2(r0, r1, a) \
    asm volatile("ldmatrix.sync.aligned.m8n8.x2.shared.b16 {%0,%1}, [%2];" \
                 : "=r"(r0), "=r"(r1) : "r"(a))
#define MMA16816(d, a, b) \
    asm volatile("mma.sync.aligned.m16n8k16.row.col.f32.bf16.bf16.f32 " \
                 "{%0,%1,%2,%3},{%4,%5,%6,%7},{%8,%9},{%0,%1,%2,%3};" \
                 : "+f"((d)[0]), "+f"((d)[1]), "+f"((d)[2]), "+f"((d)[3]) \
                 : "r"((a)[0]), "r"((a)[1]), "r"((a)[2]), "r"((a)[3]), \
                   "r"((b)[0]), "r"((b)[1]))

__device__ __forceinline__ void hilo(float v, __nv_bfloat16& h, __nv_bfloat16& l) {
    h = __float2bfloat16(v);
    l = __float2bfloat16(v - __bfloat162float(h));
}
// powers: p[s] = e1^(s+1), depth-4 ladder
__device__ __forceinline__ void powers16(float e1, float* p) {
    float e2 = e1 * e1, e4 = e2 * e2, e8 = e4 * e4;
    p[0] = e1;        p[1] = e2;        p[2] = e2 * e1;   p[3] = e4;
    p[4] = e4 * e1;   p[5] = e4 * e2;   p[6] = e4 * p[2]; p[7] = e8;
    p[8] = e8 * e1;   p[9] = e8 * e2;   p[10] = e8 * p[2]; p[11] = e8 * e4;
    p[12] = e8 * p[4]; p[13] = e8 * p[5]; p[14] = e8 * p[6]; p[15] = e8 * e8;
}
// layer-0 xz row map: r in [0,8192) -> unique row in [0,4096)
__device__ __forceinline__ int xzrow(int r, int dup) {
    if (!dup) return r;
    int t = r & 511;
    int tt = t < 256 ? t : 511 - t;
    return ((r >> 9) << 8) + tt;
}

// ---------------------------------------------------------------------------
__global__ void k_cvt(const float* __restrict__ src, __nv_bfloat16* __restrict__ hi,
                      __nv_bfloat16* __restrict__ lo, int n) {
    int i = blockIdx.x * blockDim.x + threadIdx.x;
    if (i >= n) return;
    float v = src[i];
    hilo(v, hi[i], lo[i]);
}

// layer-0 compact inputs: 4096 unique rows = (slot, b, t<256)
__global__ void k_build4(const float* __restrict__ s0, const float* __restrict__ s1,
                         const float* __restrict__ s2, const float* __restrict__ s3) {
    int idx = blockIdx.x * blockDim.x + threadIdx.x;
    if (idx >= 4096 * CC) return;
    int c = idx & (CC - 1);
    int r = idx >> 9;
    int slot = r >> 10;
    const float* s = slot == 0 ? s0 : slot == 1 ? s1 : slot == 2 ? s2 : s3;
    float v = s[(r & 1023) * CC + c];
    hilo(v, g_ah[idx], g_al[idx]);
}

// ---------------------------------------------------------------------------
// mma.sync GEMM: C = A * W^T (bf16 hi/lo x3), 128x128 tile, BK=32,
// 2-stage cp.async double buffer, 2 CTAs/SM.
// ---------------------------------------------------------------------------
#define MM_STAGE 40960
#define MM_TILE  10240

__global__ __launch_bounds__(256, 2) void k_mma(
    const __nv_bfloat16* __restrict__ Ah, const __nv_bfloat16* __restrict__ Al,
    const __nv_bfloat16* __restrict__ WhB, const __nv_bfloat16* __restrict__ WlB,
    float* __restrict__ C, int K, int ldc,
    int rpg, int wstride, int w0, int w1, int w2, int w3) {
    extern __shared__ __align__(128) uint8_t smraw[];
    const uint32_t smb = smem_u32(smraw);
    const int tid = threadIdx.x;
    const int wid = tid >> 5;
    const int lane = tid & 31;
    const int wm = wid >> 2;
    const int wn = wid & 3;
    const int row0 = blockIdx.y * 128;
    const int col0 = blockIdx.x * 128;
    const int wsel = wsel4(row0 / rpg, w0, w1, w2, w3);
    const __nv_bfloat16* Wh = WhB + (size_t)wsel * wstride;
    const __nv_bfloat16* Wl = WlB + (size_t)wsel * wstride;
    const int nc = K >> 5;

    float acc[4][4][4];
#pragma unroll
    for (int i = 0; i < 4; i++)
#pragma unroll
        for (int j = 0; j < 4; j++)
#pragma unroll
            for (int q = 0; q < 4; q++) acc[i][j][q] = 0.f;

    auto load_stage = [&](int kc, int st) {
        const int k0 = kc << 5;
        const uint32_t sb = smb + st * MM_STAGE;
#pragma unroll
        for (int p = 0; p < 8; p++) {
            int u = tid + (p << 8);
            int tile = u >> 9;
            int v = u & 511;
            int r = v >> 2, seg = v & 3;
            const __nv_bfloat16* src;
            if (tile == 0)      src = Ah + (size_t)(row0 + r) * K;
            else if (tile == 1) src = Al + (size_t)(row0 + r) * K;
            else if (tile == 2) src = Wh + (size_t)(col0 + r) * K;
            else                src = Wl + (size_t)(col0 + r) * K;
            CP16(sb + tile * MM_TILE + r * 80 + seg * 16, src + k0 + seg * 8);
        }
        CP_COMMIT();
    };

    load_stage(0, 0);
    CP_WAIT0();
    __syncthreads();

    const uint32_t aRowByte = (uint32_t)(wm * 64 + (lane & 15)) * 80 + ((lane >> 4) << 4);
    const uint32_t bRowByte = (uint32_t)(wn * 32 + (lane & 7)) * 80 + (((lane >> 3) & 1) << 4);

    for (int c = 0; c < nc; c++) {
        const int st = c & 1;
        if (c + 1 < nc) load_stage(c + 1, st ^ 1);
        const uint32_t sb = smb + st * MM_STAGE;
#pragma unroll
        for (int ks = 0; ks < 2; ks++) {
            uint32_t ah[4][4], al[4][4], bh[4][2], bl[4][2];
            const uint32_t kb = ks * 32;
#pragma unroll
            for (int mi = 0; mi < 4; mi++) {
                uint32_t ra = sb + aRowByte + (uint32_t)mi * 16 * 80 + kb;
                LDM4(ah[mi][0], ah[mi][1], ah[mi][2], ah[mi][3], ra);
                LDM4(al[mi][0], al[mi][1], al[mi][2], al[mi][3], ra + MM_TILE);
            }
#pragma unroll
            for (int ni = 0; ni < 4; ni++) {
                uint32_t rb = sb + 2 * MM_TILE + bRowByte + (uint32_t)ni * 8 * 80 + kb;
                LDM2(bh[ni][0], bh[ni][1], rb);
                LDM2(bl[ni][0], bl[ni][1], rb + MM_TILE);
            }
#pragma unroll
            for (int mi = 0; mi < 4; mi++)
#pragma unroll
                for (int ni = 0; ni < 4; ni++) {
                    MMA16816(acc[mi][ni], ah[mi], bh[ni]);
                    MMA16816(acc[mi][ni], ah[mi], bl[ni]);
                    MMA16816(acc[mi][ni], al[mi], bh[ni]);
                }
        }
        if (c + 1 < nc) CP_WAIT0();
        __syncthreads();
    }

    const int gr = lane >> 2;
    const int gc = (lane & 3) * 2;
#pragma unroll
    for (int mi = 0; mi < 4; mi++)
#pragma unroll
        for (int ni = 0; ni < 4; ni++) {
            int row = row0 + wm * 64 + mi * 16 + gr;
            int col = col0 + wn * 32 + ni * 8 + gc;
            float* p0 = C + (size_t)row * ldc + col;
            float* p1 = C + (size_t)(row + 8) * ldc + col;
            *(float2*)p0 = make_float2(acc[mi][ni][0], acc[mi][ni][1]);
            *(float2*)p1 = make_float2(acc[mi][ni][2], acc[mi][ni][3]);
        }
}

// ---------------------------------------------------------------------------
// 64x64 FFMA2 GEMM body (x_proj split-K, dt-proj)
// ---------------------------------------------------------------------------
__device__ __forceinline__ void gemm64_accum(
    const float* A, const float* W, unsigned long long acc[4][2],
    int K, int lda, int ldb, int row0, int col0) {
    __shared__ float As[16][68];
    __shared__ float Bs[16][68];
    const int tid = threadIdx.x;
    const int tx = tid & 15, ty = tid >> 4;
    for (int k0 = 0; k0 < K; k0 += 16) {
        __syncthreads();
#pragma unroll
        for (int i = 0; i < 4; i++) {
            int idx = tid + i * 256;
            int kk = idx & 15, rr = idx >> 4;
            As[kk][rr] = A[(size_t)(row0 + rr) * lda + k0 + kk];
            Bs[kk][rr] = W[(size_t)(col0 + rr) * ldb + k0 + kk];
        }
        __syncthreads();
#pragma unroll
        for (int kk = 0; kk < 16; kk++) {
            float a[4];
            *(float4*)a = *(const float4*)&As[kk][ty * 4];
            unsigned long long b2[2];
            *(float4*)b2 = *(const float4*)&Bs[kk][tx * 4];
#pragma unroll
            for (int i = 0; i < 4; i++) {
                unsigned long long ad;
                DUP2(ad, a[i]);
                FMA2(acc[i][0], ad, b2[0]);
                FMA2(acc[i][1], ad, b2[1]);
            }
        }
    }
}

// x_proj split-K (8 slices of K=128)
__global__ __launch_bounds__(256) void k_gemm64sk(
    const float* __restrict__ A, const float* __restrict__ Wb,
    int rpg, int wstride, int w0, int w1, int w2, int w3) {
    const int row0 = blockIdx.y * 64;
    const int z = blockIdx.z;
    const int wsel = wsel4(row0 / rpg, w0, w1, w2, w3);
    const float* W = Wb + (size_t)wsel * wstride + z * 128;
    unsigned long long acc[4][2];
#pragma unroll
    for (int i = 0; i < 4; i++) { acc[i][0] = 0ull; acc[i][1] = 0ull; }
    gemm64_accum(A + z * 128, W, acc, 128, 1024, 1024, row0, 0);
    float* Cout = g_xdblp + (size_t)z * RTOK * 64;
    const int tx = threadIdx.x & 15, ty = threadIdx.x >> 4;
#pragma unroll
    for (int i = 0; i < 4; i++) {
        float* cp = Cout + (size_t)(row0 + ty * 4 + i) * 64 + tx * 4;
        *(ulonglong2*)cp = make_ulonglong2(acc[i][0], acc[i][1]);
    }
}

// reduce split-K partials; also zero lookback flags for the next scan
__global__ void k_reduce8() {
    int idx = blockIdx.x * blockDim.x + threadIdx.x;
    if (idx < 1024) g_flag[idx] = 0;
    if (idx >= RTOK * 64) return;
    const int S = RTOK * 64;
    float a0 = g_xdblp[idx] + g_xdblp[idx + S];
    float a1 = g_xdblp[idx + 2 * S] + g_xdblp[idx + 3 * S];
    float a2 = g_xdblp[idx + 4 * S] + g_xdblp[idx + 5 * S];
    float a3 = g_xdblp[idx + 6 * S] + g_xdblp[idx + 7 * S];
    g_xdbl[idx] = (a0 + a1) + (a2 + a3);
}

// dt-proj with fused +dtb and softplus -> g_delta
__global__ __launch_bounds__(256) void k_gemm64dt(
    const float* __restrict__ dtw, const float* __restrict__ dtb,
    int rpg, int w0, int w1, int w2, int w3) {
    const int row0 = blockIdx.y * 64;
    const int col0 = blockIdx.x * 64;
    const int m = wsel4(row0 / rpg, w0, w1, w2, w3);
    const float* W = dtw + (size_t)m * DIN * 32;
    unsigned long long acc[4][2];
#pragma unroll
    for (int i = 0; i < 4; i++) { acc[i][0] = 0ull; acc[i][1] = 0ull; }
    gemm64_accum(g_xdbl, W, acc, 32, 64, 32, row0, col0);
    const int tx = threadIdx.x & 15, ty = threadIdx.x >> 4;
#pragma unroll
    for (int i = 0; i < 4; i++) {
        const float* av = (const float*)acc[i];
        float r[4];
#pragma unroll
        for (int j = 0; j < 4; j++) {
            int col = col0 + tx * 4 + j;
            float x = av[j] + dtb[m * DIN + col];
            r[j] = (x > 15.f) ? x : __logf(1.f + __expf(x));
        }
        float* cp = g_delta + (size_t)(row0 + ty * 4 + i) * DIN + col0 + tx * 4;
        *(float4*)cp = make_float4(r[0], r[1], r[2], r[3]);
    }
}

// ---------------------------------------------------------------------------
// causal depthwise conv (4 taps) + bias + SiLU. dup=1: layer-0 compact-xz map.
// ---------------------------------------------------------------------------
__global__ void k_conv(const float* __restrict__ cw, const float* __restrict__ cb,
                       int T, int rpg, int w0, int w1, int w2, int w3, int dup) {
    int idx = blockIdx.x * blockDim.x + threadIdx.x;
    if (idx >= RTOK * DIN) return;
    int d = idx & (DIN - 1);
    int r = idx >> 10;
    int t = r & (T - 1);
    int m = wsel4(r / rpg, w0, w1, w2, w3);
    const float* cwp = cw + ((size_t)m * DIN + d) * 4;
    float acc = cb[m * DIN + d];
#pragma unroll
    for (int k = 0; k < 4; k++) {
        int tt = t - 3 + k;
        if (tt >= 0) {
            int row = xzrow(r + tt - t, dup);
            acc = fmaf(cwp[k], g_xz[(size_t)row * (2 * DIN) + d], acc);
        }
    }
    float e = __expf(-acc);
    g_x[idx] = __fdividef(acc, 1.f + e);
}

// ---------------------------------------------------------------------------
// Fused chunked scan with decoupled lookback (passes A+B+C in one kernel).
// CHAIN: pass A rewrites g_delta with e1=exp(delta*Av[0]); pass C skips exp.
// ---------------------------------------------------------------------------
template <bool CHAIN>
__device__ __forceinline__ void scanF_body(int rbase, int d, int g, int j,
                                           int blk, int dup,
                                           const float Av[16], float Dv) {
    const int tid = threadIdx.x;
    float h[16];
#pragma unroll
    for (int s = 0; s < 16; s++) h[s] = 0.f;
    float dsum = 0.f;
    // ---- local scan (h0 = 0); ylin (incl. D*x) overwrites g_x
#pragma unroll 2
    for (int t = 0; t < 64; t++) {
        int r = rbase + t;
        float delta = g_delta[(size_t)r * DIN + d];
        float xv = g_x[(size_t)r * DIN + d];
        const float4* bc = (const float4*)(g_xdbl + (size_t)r * 64 + 32);
        float4 Bq[4], Cq[4];
#pragma unroll
        for (int q = 0; q < 4; q++) { Bq[q] = bc[q]; Cq[q] = bc[q + 4]; }
        const float* Bv = (const float*)Bq;
        const float* Cv = (const float*)Cq;
        dsum += delta;
        float p[16];
        if (CHAIN) {
            float e1 = __expf(delta * Av[0]);
            powers16(e1, p);
            g_delta[(size_t)r * DIN + d] = e1;   // cache e1 for pass C
        } else {
#pragma unroll
            for (int s = 0; s < 16; s++) p[s] = __expf(delta * Av[s]);
        }
        float dx = delta * xv;
        float y0 = 0.f, y1 = 0.f, y2 = 0.f, y3 = 0.f;
#pragma unroll
        for (int s = 0; s < 16; s++) {
            h[s] = fmaf(h[s], p[s], dx * Bv[s]);
            float hv = h[s] * Cv[s];
            if ((s & 3) == 0) y0 += hv;
            else if ((s & 3) == 1) y1 += hv;
            else if ((s & 3) == 2) y2 += hv;
            else y3 += hv;
        }
        g_x[(size_t)r * DIN + d] = fmaf(Dv, xv, (y0 + y1) + (y2 + y3));
    }

    float hin[16];
    if (j == 0) {
#pragma unroll
        for (int s = 0; s < 16; s++)
            g_hch[((size_t)(s * 128 + g) << 10) + d] = h[s];
        __threadfence();
        __syncthreads();
        if (tid == 0) atomicExch(&g_flag[blk], 1);
#pragma unroll 2
        for (int t = 0; t < 64; t++) {
            int r = rbase + t;
            float zv = g_xz[(size_t)xzrow(r, dup) * 2048 + 1024 + d];
            float ylin = g_x[(size_t)r * DIN + d];
            float sg = __fdividef(zv, 1.f + __expf(-zv));
            float yv = ylin * sg;
            hilo(yv, g_ah[(size_t)r * DIN + d], g_al[(size_t)r * DIN + d]);
        }
        return;
    }

    float P[16];
    if (CHAIN) powers16(__expf(dsum * Av[0]), P);
    else {
#pragma unroll
        for (int s = 0; s < 16; s++) P[s] = __expf(dsum * Av[s]);
    }
    if (tid == 0) {
        while (atomicAdd(&g_flag[blk - 8], 0) == 0) __nanosleep(32);
    }
    __syncthreads();
    __threadfence();
#pragma unroll
    for (int s = 0; s < 16; s++)
        hin[s] = g_hch[((size_t)(s * 128 + (g - 1)) << 10) + d];
#pragma unroll
    for (int s = 0; s < 16; s++)
        g_hch[((size_t)(s * 128 + g) << 10) + d] = fmaf(P[s], hin[s], h[s]);
    __threadfence();
    __syncthreads();
    if (tid == 0) atomicExch(&g_flag[blk], 1);

    // ---- correction + gate (data L2-hot from local pass)
    float q[16];
#pragma unroll
    for (int s = 0; s < 16; s++) q[s] = hin[s];
#pragma unroll 2
    for (int t = 0; t < 64; t++) {
        int r = rbase + t;
        float dval = g_delta[(size_t)r * DIN + d];   // e1 (chain) or delta
        float zv = g_xz[(size_t)xzrow(r, dup) * 2048 + 1024 + d];
        float ylin = g_x[(size_t)r * DIN + d];
        const float4* cp = (const float4*)(g_xdbl + (size_t)r * 64 + 48);
        float4 Cq[4];
#pragma unroll
        for (int u = 0; u < 4; u++) Cq[u] = cp[u];
        const float* Cv = (const float*)Cq;
        float p[16];
        if (CHAIN) powers16(dval, p);   // dval == e1, no exp needed
        else {
#pragma unroll
            for (int s = 0; s < 16; s++) p[s] = __expf(dval * Av[s]);
        }
        float c0 = 0.f, c1 = 0.f, c2 = 0.f, c3 = 0.f;
#pragma unroll
        for (int s = 0; s < 16; s++) {
            q[s] *= p[s];
            float hv = q[s] * Cv[s];
            if ((s & 3) == 0) c0 += hv;
            else if ((s & 3) == 1) c1 += hv;
            else if ((s & 3) == 2) c2 += hv;
            else c3 += hv;
        }
        float y = ylin + (c0 + c1) + (c2 + c3);
        float sg = __fdividef(zv, 1.f + __expf(-zv));
        float yv = y * sg;
        hilo(yv, g_ah[(size_t)r * DIN + d], g_al[(size_t)r * DIN + d]);
    }
}

__global__ __launch_bounds__(128) void k_scanF(const float* __restrict__ Alog,
                                               const float* __restrict__ Dp,
                                               int lgNCH, int w0, int w1, int w2, int w3,
                                               int dup) {
    int blk = blockIdx.x;
    int dg = blk & 7;
    int g = blk >> 3;
    int seq = g >> lgNCH;
    int j = g & ((1 << lgNCH) - 1);
    int d = (dg << 7) | threadIdx.x;
    int m = wsel4(seq >> 2, w0, w1, w2, w3);
    float Av[16];
    const float* ap = Alog + ((size_t)m * DIN + d) * 16;
#pragma unroll
    for (int s = 0; s < 16; s++) Av[s] = -__expf(ap[s]);
    bool chain = true;
#pragma unroll
    for (int s = 1; s < 16; s++)
        chain = chain &&
                (fabsf(Av[s] - (float)(s + 1) * Av[0]) <=
                 1e-3f * (float)(s + 1) * fabsf(Av[0]) + 1e-7f);
    float Dv = Dp[m * DIN + d];
    int rbase = g << 6;
    if (chain) scanF_body<true>(rbase, d, g, j, blk, dup, Av, Dv);
    else       scanF_body<false>(rbase, d, g, j, blk, dup, Av, Dv);
}

// ---------------------------------------------------------------------------
// layer-0 epilogue: fold halves, layernorm, residual; emit layer-1 GEMM input
// (forward + reversed copies) directly as bf16 hi/lo.
// ---------------------------------------------------------------------------
__global__ __launch_bounds__(128) void k_combine(
    const float* __restrict__ s0, const float* __restrict__ s1,
    const float* __restrict__ s2, const float* __restrict__ s3,
    const float* __restrict__ lnw, const float* __restrict__ lnb) {
    int blk = blockIdx.x;
    int t = blk & 255;
    int b = (blk >> 8) & 3;
    int slot = blk >> 10;
    const float* src = slot == 0 ? s0 : slot == 1 ? s1 : slot == 2 ? s2 : s3;
    int rowA = ((slot * 4 + b) * 512 + t) * CC;
    int rowB = ((slot * 4 + b) * 512 + (511 - t)) * CC;
    int tid = threadIdx.x;
    float v[4];
#pragma unroll
    for (int j = 0; j < 4; j++) {
        int c = tid + j * 128;
        v[j] = 0.5f * (g_o[rowA + c] + g_o[rowB + c]);
    }
    __shared__ float red[8];
    int wid = tid >> 5, lane = tid & 31;
    float s = (v[0] + v[1]) + (v[2] + v[3]);
#pragma unroll
    for (int o = 16; o; o >>= 1) s += __shfl_xor_sync(~0u, s, o);
    if (lane == 0) red[wid] = s;
    __syncthreads();
    float mean = (red[0] + red[1] + red[2] + red[3]) * (1.f / 512.f);
    float q = 0.f;
#pragma unroll
    for (int j = 0; j < 4; j++) { float dd = v[j] - mean; q = fmaf(dd, dd, q); }
#pragma unroll
    for (int o = 16; o; o >>= 1) q += __shfl_xor_sync(~0u, q, o);
    if (lane == 0) red[4 + wid] = q;
    __syncthreads();
    float var = (red[4] + red[5] + red[6] + red[7]) * (1.f / 512.f);
    float rstd = rsqrtf(var + 1e-5f);
    int tau = slot * 256 + t;
#pragma unroll
    for (int j = 0; j < 4; j++) {
        int c = tid + j * 128;
        float o = (v[j] - mean) * rstd * lnw[c] + lnb[c] + src[(b * 256 + t) * CC + c];
        __nv_bfloat16 hh, ll;
        hilo(o, hh, ll);
        int idxF = ((b * 1024) + tau) * CC + c;
        int idxR = (((4 + b) * 1024) + (1023 - tau)) * CC + c;
        g_ah[idxF] = hh; g_al[idxF] = ll;
        g_ah[idxR] = hh; g_al[idxR] = ll;
    }
}

__global__ void k_final(float* __restrict__ out) {
    int idx = blockIdx.x * blockDim.x + threadIdx.x;
    if (idx >= BB * 1024 * CC) return;
    int c = idx & (CC - 1);
    int rest = idx >> 9;
    int tau = rest & 1023;
    int b = rest >> 10;
    float f = 0.5f * (g_o[((b * 1024) + tau) * CC + c] +
                      g_o[(((4 + b) * 1024) + (1023 - tau)) * CC + c]);
    int i = tau >> 8;
    int t = tau & 255;
    out[(((i * 4 + b) * 256 + t) << 9) + c] = f;
}

// ---------------------------------------------------------------------------
extern "C" void kernel_launch(void* const* d_in, const int* in_sizes, int n_in,
                              void* d_out, int out_size) {
    const float* x0hw = (const float*)d_in[0];
    const float* x1hw = (const float*)d_in[1];
    const float* x0wh = (const float*)d_in[2];
    const float* x1wh = (const float*)d_in[3];
    const float* in_w = (const float*)d_in[4];
    const float* cw   = (const float*)d_in[5];
    const float* cb   = (const float*)d_in[6];
    const float* xw   = (const float*)d_in[7];
    const float* dtw  = (const float*)d_in[8];
    const float* dtb  = (const float*)d_in[9];
    const float* alog = (const float*)d_in[10];
    const float* Dp   = (const float*)d_in[11];
    const float* ow   = (const float*)d_in[12];
    const float* lnw  = (const float*)d_in[13];
    const float* lnb  = (const float*)d_in[14];
    float* out = (float*)d_out;

    float *pxz, *px, *po;
    cudaGetSymbolAddress((void**)&pxz, g_xz);
    cudaGetSymbolAddress((void**)&px, g_x);
    cudaGetSymbolAddress((void**)&po, g_o);
    __nv_bfloat16 *pah, *pal, *pwih, *pwil, *pwoh, *pwol;
    cudaGetSymbolAddress((void**)&pah, g_ah);
    cudaGetSymbolAddress((void**)&pal, g_al);
    cudaGetSymbolAddress((void**)&pwih, g_wih);
    cudaGetSymbolAddress((void**)&pwil, g_wil);
    cudaGetSymbolAddress((void**)&pwoh, g_woh);
    cudaGetSymbolAddress((void**)&pwol, g_wol);

    static int inited = 0;
    static cudaStream_t s2;
    static cudaEvent_t evX0, evZ0, evX1, evZ1;
    if (!inited) {
        cudaFuncSetAttribute(k_mma, cudaFuncAttributeMaxDynamicSharedMemorySize,
                             2 * MM_STAGE);
        cudaStreamCreateWithFlags(&s2, cudaStreamNonBlocking);
        cudaEventCreateWithFlags(&evX0, cudaEventDisableTiming);
        cudaEventCreateWithFlags(&evZ0, cudaEventDisableTiming);
        cudaEventCreateWithFlags(&evX1, cudaEventDisableTiming);
        cudaEventCreateWithFlags(&evZ1, cudaEventDisableTiming);
        inited = 1;
    }
    const int MMSMEM = 2 * MM_STAGE;

    const int EL = RTOK * DIN;
    const int ELF = BB * 1024 * CC;
    const size_t ZW = (size_t)1024 * 512;

    // weights -> bf16 hi/lo
    k_cvt<<<(6 * 2048 * 512 + 255) / 256, 256>>>(in_w, pwih, pwil, 6 * 2048 * 512);
    k_cvt<<<(6 * 512 * 1024 + 255) / 256, 256>>>(ow, pwoh, pwol, 6 * 512 * 1024);

    // ---------------- layer 0 (T=512, NCH=8; compact in_proj) ---------------
    {
        const int w0 = 0, w1 = 2, w2 = 1, w3 = 3, rpg = 2048, T = 512, lg = 3;
        k_build4<<<(4096 * CC + 255) / 256, 256>>>(x0hw, x1hw, x0wh, x1wh);
        k_mma<<<dim3(8, 32), 256, MMSMEM>>>(
            pah, pal, pwih, pwil, pxz, 512, 2048, 1024, 2048 * 512, w0, w1, w2, w3);
        cudaEventRecord(evX0, 0);
        cudaStreamWaitEvent(s2, evX0, 0);
        k_mma<<<dim3(8, 32), 256, MMSMEM, s2>>>(
            pah, pal, pwih + ZW, pwil + ZW, pxz + 1024, 512, 2048,
            1024, 2048 * 512, w0, w1, w2, w3);
        cudaEventRecord(evZ0, s2);
        k_conv<<<(EL + 255) / 256, 256>>>(cw, cb, T, rpg, w0, w1, w2, w3, 1);
        k_gemm64sk<<<dim3(1, RTOK / 64, 8), 256>>>(px, xw, rpg, 64 * 1024, w0, w1, w2, w3);
        k_reduce8<<<(RTOK * 64 + 255) / 256, 256>>>();
        k_gemm64dt<<<dim3(1024 / 64, RTOK / 64), 256>>>(dtw, dtb, rpg, w0, w1, w2, w3);
        cudaStreamWaitEvent(0, evZ0, 0);   // scanF gates with z
        k_scanF<<<1024, 128>>>(alog, Dp, lg, w0, w1, w2, w3, 1);
        k_mma<<<dim3(4, 64), 256, MMSMEM>>>(
            pah, pal, pwoh, pwol, po, 1024, 512, rpg, 512 * 1024, w0, w1, w2, w3);
        k_combine<<<4096, 128>>>(x0hw, x1hw, x0wh, x1wh, lnw, lnb);
    }

    // ---------------- layer 1 (T=1024, NCH=16) ----------------
    {
        const int w0 = 4, w1 = 5, w2 = 4, w3 = 5, rpg = 4096, T = 1024, lg = 4;
        k_mma<<<dim3(8, 64), 256, MMSMEM>>>(
            pah, pal, pwih, pwil, pxz, 512, 2048, rpg, 2048 * 512, w0, w1, w2, w3);
        cudaEventRecord(evX1, 0);
        cudaStreamWaitEvent(s2, evX1, 0);
        k_mma<<<dim3(8, 64), 256, MMSMEM, s2>>>(
            pah, pal, pwih + ZW, pwil + ZW, pxz + 1024, 512, 2048,
            rpg, 2048 * 512, w0, w1, w2, w3);
        cudaEventRecord(evZ1, s2);
        k_conv<<<(EL + 255) / 256, 256>>>(cw, cb, T, rpg, w0, w1, w2, w3, 0);
        k_gemm64sk<<<dim3(1, RTOK / 64, 8), 256>>>(px, xw, rpg, 64 * 1024, w0, w1, w2, w3);
        k_reduce8<<<(RTOK * 64 + 255) / 256, 256>>>();
        k_gemm64dt<<<dim3(1024 / 64, RTOK / 64), 256>>>(dtw, dtb, rpg, w0, w1, w2, w3);
        cudaStreamWaitEvent(0, evZ1, 0);
        k_scanF<<<1024, 128>>>(alog, Dp, lg, w0, w1, w2, w3, 0);
        k_mma<<<dim3(4, 64), 256, MMSMEM>>>(
            pah, pal, pwoh, pwol, po, 1024, 512, rpg, 512 * 1024, w0, w1, w2, w3);
        k_final<<<(ELF + 255) / 256, 256>>>(out);
    }
}

// round 14
// speedup vs baseline: 1.2528x; 1.1433x over previous
#include <cuda_runtime.h>
#include <cuda_bf16.h>
#include <cstdint>

// ---------------------------------------------------------------------------
// MultiScaleMambaEncoder — mma.sync bf16 hi/lo x3 GEMMs + single-pass
// decoupled-lookback chunked scan. Layer-0 in_proj on 4096 unique rows;
// z-half of in_proj on a side stream. (Exact R11 configuration.)
// ---------------------------------------------------------------------------

#define BB 4
#define CC 512
#define DIN 1024
#define RTOK 8192

// fp32 scratch
__device__ float g_xz[RTOK * 2 * DIN];
__device__ float g_x[RTOK * DIN];          // conv output, then ylin
__device__ float g_xdbl[RTOK * 64];
__device__ float g_xdblp[8 * RTOK * 64];   // split-K partials
__device__ float g_hch[16 * 128 * 1024];   // published h_out per chunk
__device__ float g_delta[RTOK * DIN];
__device__ float g_o[RTOK * CC];
__device__ int   g_flag[1024];             // lookback flags
// bf16 hi/lo scratch (GEMM A operands)
__device__ __nv_bfloat16 g_ah[RTOK * DIN];
__device__ __nv_bfloat16 g_al[RTOK * DIN];
__device__ __nv_bfloat16 g_wih[6 * 2048 * 512];
__device__ __nv_bfloat16 g_wil[6 * 2048 * 512];
__device__ __nv_bfloat16 g_woh[6 * 512 * 1024];
__device__ __nv_bfloat16 g_wol[6 * 512 * 1024];

__device__ __forceinline__ int wsel4(int ml, int w0, int w1, int w2, int w3) {
    return ml == 0 ? w0 : ml == 1 ? w1 : ml == 2 ? w2 : w3;
}

#define FMA2(d, a, b) asm("fma.rn.f32x2 %0, %1, %2, %0;" : "+l"(d) : "l"(a), "l"(b))
#define DUP2(d, s)    asm("mov.b64 %0, {%1, %1};" : "=l"(d) : "f"(s))

__device__ __forceinline__ uint32_t smem_u32(const void* p) {
    uint32_t a;
    asm("{ .reg .u64 t; cvta.to.shared.u64 t, %1; cvt.u32.u64 %0, t; }" : "=r"(a) : "l"(p));
    return a;
}
#define CP16(dst, src)  asm volatile("cp.async.cg.shared.global [%0], [%1], 16;" :: "r"(dst), "l"(src))
#define CP_COMMIT()     asm volatile("cp.async.commit_group;" ::: "memory")
#define CP_WAIT0()      asm volatile("cp.async.wait_group 0;" ::: "memory")

#define LDM4(r0, r1, r2, r3, a) \
    asm volatile("ldmatrix.sync.aligned.m8n8.x4.shared.b16 {%0,%1,%2,%3}, [%4];" \
                 : "=r"(r0), "=r"(r1), "=r"(r2), "=r"(r3) : "r"(a))
#define LDM2(r0, r1, a) \
    asm volatile("ldmatrix.sync.aligned.m8n8.x2.shared.b16 {%0,%1}, [%2];" \
                 : "=r"(r0), "=r"(r1) : "r"(a))
#define MMA16816(d, a, b) \
    asm volatile("mma.sync.aligned.m16n8k16.row.col.f32.bf16.bf16.f32 " \
                 "{%0,%1,%2,%3},{%4,%5,%6,%7},{%8,%9},{%0,%1,%2,%3};" \
                 : "+f"((d)[0]), "+f"((d)[1]), "+f"((d)[2]), "+f"((d)[3]) \
                 : "r"((a)[0]), "r"((a)[1]), "r"((a)[2]), "r"((a)[3]), \
                   "r"((b)[0]), "r"((b)[1]))

__device__ __forceinline__ void hilo(float v, __nv_bfloat16& h, __nv_bfloat16& l) {
    h = __float2bfloat16(v);
    l = __float2bfloat16(v - __bfloat162float(h));
}
// powers: p[s] = e1^(s+1), depth-4 ladder
__device__ __forceinline__ void powers16(float e1, float* p) {
    float e2 = e1 * e1, e4 = e2 * e2, e8 = e4 * e4;
    p[0] = e1;        p[1] = e2;        p[2] = e2 * e1;   p[3] = e4;
    p[4] = e4 * e1;   p[5] = e4 * e2;   p[6] = e4 * p[2]; p[7] = e8;
    p[8] = e8 * e1;   p[9] = e8 * e2;   p[10] = e8 * p[2]; p[11] = e8 * e4;
    p[12] = e8 * p[4]; p[13] = e8 * p[5]; p[14] = e8 * p[6]; p[15] = e8 * e8;
}
// layer-0 xz row map: r in [0,8192) -> unique row in [0,4096)
__device__ __forceinline__ int xzrow(int r, int dup) {
    if (!dup) return r;
    int t = r & 511;
    int tt = t < 256 ? t : 511 - t;
    return ((r >> 9) << 8) + tt;
}

// ---------------------------------------------------------------------------
__global__ void k_cvt(const float* __restrict__ src, __nv_bfloat16* __restrict__ hi,
                      __nv_bfloat16* __restrict__ lo, int n) {
    int i = blockIdx.x * blockDim.x + threadIdx.x;
    if (i >= n) return;
    float v = src[i];
    hilo(v, hi[i], lo[i]);
}

// layer-0 compact inputs: 4096 unique rows = (slot, b, t<256)
__global__ void k_build4(const float* __restrict__ s0, const float* __restrict__ s1,
                         const float* __restrict__ s2, const float* __restrict__ s3) {
    int idx = blockIdx.x * blockDim.x + threadIdx.x;
    if (idx >= 4096 * CC) return;
    int c = idx & (CC - 1);
    int r = idx >> 9;
    int slot = r >> 10;
    const float* s = slot == 0 ? s0 : slot == 1 ? s1 : slot == 2 ? s2 : s3;
    float v = s[(r & 1023) * CC + c];
    hilo(v, g_ah[idx], g_al[idx]);
}

// ---------------------------------------------------------------------------
// mma.sync GEMM: C = A * W^T (bf16 hi/lo x3), 128x128 tile, BK=32,
// 2-stage cp.async double buffer, 2 CTAs/SM.
// ---------------------------------------------------------------------------
#define MM_STAGE 40960
#define MM_TILE  10240

__global__ __launch_bounds__(256, 2) void k_mma(
    const __nv_bfloat16* __restrict__ Ah, const __nv_bfloat16* __restrict__ Al,
    const __nv_bfloat16* __restrict__ WhB, const __nv_bfloat16* __restrict__ WlB,
    float* __restrict__ C, int K, int ldc,
    int rpg, int wstride, int w0, int w1, int w2, int w3) {
    extern __shared__ __align__(128) uint8_t smraw[];
    const uint32_t smb = smem_u32(smraw);
    const int tid = threadIdx.x;
    const int wid = tid >> 5;
    const int lane = tid & 31;
    const int wm = wid >> 2;
    const int wn = wid & 3;
    const int row0 = blockIdx.y * 128;
    const int col0 = blockIdx.x * 128;
    const int wsel = wsel4(row0 / rpg, w0, w1, w2, w3);
    const __nv_bfloat16* Wh = WhB + (size_t)wsel * wstride;
    const __nv_bfloat16* Wl = WlB + (size_t)wsel * wstride;
    const int nc = K >> 5;

    float acc[4][4][4];
#pragma unroll
    for (int i = 0; i < 4; i++)
#pragma unroll
        for (int j = 0; j < 4; j++)
#pragma unroll
            for (int q = 0; q < 4; q++) acc[i][j][q] = 0.f;

    auto load_stage = [&](int kc, int st) {
        const int k0 = kc << 5;
        const uint32_t sb = smb + st * MM_STAGE;
#pragma unroll
        for (int p = 0; p < 8; p++) {
            int u = tid + (p << 8);
            int tile = u >> 9;
            int v = u & 511;
            int r = v >> 2, seg = v & 3;
            const __nv_bfloat16* src;
            if (tile == 0)      src = Ah + (size_t)(row0 + r) * K;
            else if (tile == 1) src = Al + (size_t)(row0 + r) * K;
            else if (tile == 2) src = Wh + (size_t)(col0 + r) * K;
            else                src = Wl + (size_t)(col0 + r) * K;
            CP16(sb + tile * MM_TILE + r * 80 + seg * 16, src + k0 + seg * 8);
        }
        CP_COMMIT();
    };

    load_stage(0, 0);
    CP_WAIT0();
    __syncthreads();

    const uint32_t aRowByte = (uint32_t)(wm * 64 + (lane & 15)) * 80 + ((lane >> 4) << 4);
    const uint32_t bRowByte = (uint32_t)(wn * 32 + (lane & 7)) * 80 + (((lane >> 3) & 1) << 4);

    for (int c = 0; c < nc; c++) {
        const int st = c & 1;
        if (c + 1 < nc) load_stage(c + 1, st ^ 1);
        const uint32_t sb = smb + st * MM_STAGE;
#pragma unroll
        for (int ks = 0; ks < 2; ks++) {
            uint32_t ah[4][4], al[4][4], bh[4][2], bl[4][2];
            const uint32_t kb = ks * 32;
#pragma unroll
            for (int mi = 0; mi < 4; mi++) {
                uint32_t ra = sb + aRowByte + (uint32_t)mi * 16 * 80 + kb;
                LDM4(ah[mi][0], ah[mi][1], ah[mi][2], ah[mi][3], ra);
                LDM4(al[mi][0], al[mi][1], al[mi][2], al[mi][3], ra + MM_TILE);
            }
#pragma unroll
            for (int ni = 0; ni < 4; ni++) {
                uint32_t rb = sb + 2 * MM_TILE + bRowByte + (uint32_t)ni * 8 * 80 + kb;
                LDM2(bh[ni][0], bh[ni][1], rb);
                LDM2(bl[ni][0], bl[ni][1], rb + MM_TILE);
            }
#pragma unroll
            for (int mi = 0; mi < 4; mi++)
#pragma unroll
                for (int ni = 0; ni < 4; ni++) {
                    MMA16816(acc[mi][ni], ah[mi], bh[ni]);
                    MMA16816(acc[mi][ni], ah[mi], bl[ni]);
                    MMA16816(acc[mi][ni], al[mi], bh[ni]);
                }
        }
        if (c + 1 < nc) CP_WAIT0();
        __syncthreads();
    }

    const int gr = lane >> 2;
    const int gc = (lane & 3) * 2;
#pragma unroll
    for (int mi = 0; mi < 4; mi++)
#pragma unroll
        for (int ni = 0; ni < 4; ni++) {
            int row = row0 + wm * 64 + mi * 16 + gr;
            int col = col0 + wn * 32 + ni * 8 + gc;
            float* p0 = C + (size_t)row * ldc + col;
            float* p1 = C + (size_t)(row + 8) * ldc + col;
            *(float2*)p0 = make_float2(acc[mi][ni][0], acc[mi][ni][1]);
            *(float2*)p1 = make_float2(acc[mi][ni][2], acc[mi][ni][3]);
        }
}

// ---------------------------------------------------------------------------
// 64x64 FFMA2 GEMM body (x_proj split-K, dt-proj)
// ---------------------------------------------------------------------------
__device__ __forceinline__ void gemm64_accum(
    const float* A, const float* W, unsigned long long acc[4][2],
    int K, int lda, int ldb, int row0, int col0) {
    __shared__ float As[16][68];
    __shared__ float Bs[16][68];
    const int tid = threadIdx.x;
    const int tx = tid & 15, ty = tid >> 4;
    for (int k0 = 0; k0 < K; k0 += 16) {
        __syncthreads();
#pragma unroll
        for (int i = 0; i < 4; i++) {
            int idx = tid + i * 256;
            int kk = idx & 15, rr = idx >> 4;
            As[kk][rr] = A[(size_t)(row0 + rr) * lda + k0 + kk];
            Bs[kk][rr] = W[(size_t)(col0 + rr) * ldb + k0 + kk];
        }
        __syncthreads();
#pragma unroll
        for (int kk = 0; kk < 16; kk++) {
            float a[4];
            *(float4*)a = *(const float4*)&As[kk][ty * 4];
            unsigned long long b2[2];
            *(float4*)b2 = *(const float4*)&Bs[kk][tx * 4];
#pragma unroll
            for (int i = 0; i < 4; i++) {
                unsigned long long ad;
                DUP2(ad, a[i]);
                FMA2(acc[i][0], ad, b2[0]);
                FMA2(acc[i][1], ad, b2[1]);
            }
        }
    }
}

// x_proj split-K (8 slices of K=128)
__global__ __launch_bounds__(256) void k_gemm64sk(
    const float* __restrict__ A, const float* __restrict__ Wb,
    int rpg, int wstride, int w0, int w1, int w2, int w3) {
    const int row0 = blockIdx.y * 64;
    const int z = blockIdx.z;
    const int wsel = wsel4(row0 / rpg, w0, w1, w2, w3);
    const float* W = Wb + (size_t)wsel * wstride + z * 128;
    unsigned long long acc[4][2];
#pragma unroll
    for (int i = 0; i < 4; i++) { acc[i][0] = 0ull; acc[i][1] = 0ull; }
    gemm64_accum(A + z * 128, W, acc, 128, 1024, 1024, row0, 0);
    float* Cout = g_xdblp + (size_t)z * RTOK * 64;
    const int tx = threadIdx.x & 15, ty = threadIdx.x >> 4;
#pragma unroll
    for (int i = 0; i < 4; i++) {
        float* cp = Cout + (size_t)(row0 + ty * 4 + i) * 64 + tx * 4;
        *(ulonglong2*)cp = make_ulonglong2(acc[i][0], acc[i][1]);
    }
}

// reduce split-K partials; also zero lookback flags for the next scan
__global__ void k_reduce8() {
    int idx = blockIdx.x * blockDim.x + threadIdx.x;
    if (idx < 1024) g_flag[idx] = 0;
    if (idx >= RTOK * 64) return;
    const int S = RTOK * 64;
    float a0 = g_xdblp[idx] + g_xdblp[idx + S];
    float a1 = g_xdblp[idx + 2 * S] + g_xdblp[idx + 3 * S];
    float a2 = g_xdblp[idx + 4 * S] + g_xdblp[idx + 5 * S];
    float a3 = g_xdblp[idx + 6 * S] + g_xdblp[idx + 7 * S];
    g_xdbl[idx] = (a0 + a1) + (a2 + a3);
}

// dt-proj with fused +dtb and softplus -> g_delta
__global__ __launch_bounds__(256) void k_gemm64dt(
    const float* __restrict__ dtw, const float* __restrict__ dtb,
    int rpg, int w0, int w1, int w2, int w3) {
    const int row0 = blockIdx.y * 64;
    const int col0 = blockIdx.x * 64;
    const int m = wsel4(row0 / rpg, w0, w1, w2, w3);
    const float* W = dtw + (size_t)m * DIN * 32;
    unsigned long long acc[4][2];
#pragma unroll
    for (int i = 0; i < 4; i++) { acc[i][0] = 0ull; acc[i][1] = 0ull; }
    gemm64_accum(g_xdbl, W, acc, 32, 64, 32, row0, col0);
    const int tx = threadIdx.x & 15, ty = threadIdx.x >> 4;
#pragma unroll
    for (int i = 0; i < 4; i++) {
        const float* av = (const float*)acc[i];
        float r[4];
#pragma unroll
        for (int j = 0; j < 4; j++) {
            int col = col0 + tx * 4 + j;
            float x = av[j] + dtb[m * DIN + col];
            r[j] = (x > 15.f) ? x : __logf(1.f + __expf(x));
        }
        float* cp = g_delta + (size_t)(row0 + ty * 4 + i) * DIN + col0 + tx * 4;
        *(float4*)cp = make_float4(r[0], r[1], r[2], r[3]);
    }
}

// ---------------------------------------------------------------------------
// causal depthwise conv (4 taps) + bias + SiLU. dup=1: layer-0 compact-xz map.
// ---------------------------------------------------------------------------
__global__ void k_conv(const float* __restrict__ cw, const float* __restrict__ cb,
                       int T, int rpg, int w0, int w1, int w2, int w3, int dup) {
    int idx = blockIdx.x * blockDim.x + threadIdx.x;
    if (idx >= RTOK * DIN) return;
    int d = idx & (DIN - 1);
    int r = idx >> 10;
    int t = r & (T - 1);
    int m = wsel4(r / rpg, w0, w1, w2, w3);
    const float* cwp = cw + ((size_t)m * DIN + d) * 4;
    float acc = cb[m * DIN + d];
#pragma unroll
    for (int k = 0; k < 4; k++) {
        int tt = t - 3 + k;
        if (tt >= 0) {
            int row = xzrow(r + tt - t, dup);
            acc = fmaf(cwp[k], g_xz[(size_t)row * (2 * DIN) + d], acc);
        }
    }
    float e = __expf(-acc);
    g_x[idx] = __fdividef(acc, 1.f + e);
}

// ---------------------------------------------------------------------------
// Fused chunked scan with decoupled lookback (passes A+B+C in one kernel).
// ---------------------------------------------------------------------------
template <bool CHAIN>
__device__ __forceinline__ void scanF_body(int rbase, int d, int g, int j,
                                           int blk, int dup,
                                           const float Av[16], float Dv) {
    const int tid = threadIdx.x;
    float h[16];
#pragma unroll
    for (int s = 0; s < 16; s++) h[s] = 0.f;
    float dsum = 0.f;
    // ---- local scan (h0 = 0); ylin (incl. D*x) overwrites g_x
#pragma unroll 2
    for (int t = 0; t < 64; t++) {
        int r = rbase + t;
        float delta = g_delta[(size_t)r * DIN + d];
        float xv = g_x[(size_t)r * DIN + d];
        const float4* bc = (const float4*)(g_xdbl + (size_t)r * 64 + 32);
        float4 Bq[4], Cq[4];
#pragma unroll
        for (int q = 0; q < 4; q++) { Bq[q] = bc[q]; Cq[q] = bc[q + 4]; }
        const float* Bv = (const float*)Bq;
        const float* Cv = (const float*)Cq;
        dsum += delta;
        float p[16];
        if (CHAIN) powers16(__expf(delta * Av[0]), p);
        else {
#pragma unroll
            for (int s = 0; s < 16; s++) p[s] = __expf(delta * Av[s]);
        }
        float dx = delta * xv;
        float y0 = 0.f, y1 = 0.f, y2 = 0.f, y3 = 0.f;
#pragma unroll
        for (int s = 0; s < 16; s++) {
            h[s] = fmaf(h[s], p[s], dx * Bv[s]);
            float hv = h[s] * Cv[s];
            if ((s & 3) == 0) y0 += hv;
            else if ((s & 3) == 1) y1 += hv;
            else if ((s & 3) == 2) y2 += hv;
            else y3 += hv;
        }
        g_x[(size_t)r * DIN + d] = fmaf(Dv, xv, (y0 + y1) + (y2 + y3));
    }

    float hin[16];
    if (j == 0) {
#pragma unroll
        for (int s = 0; s < 16; s++)
            g_hch[((size_t)(s * 128 + g) << 10) + d] = h[s];
        __threadfence();
        __syncthreads();
        if (tid == 0) atomicExch(&g_flag[blk], 1);
#pragma unroll 2
        for (int t = 0; t < 64; t++) {
            int r = rbase + t;
            float zv = g_xz[(size_t)xzrow(r, dup) * 2048 + 1024 + d];
            float ylin = g_x[(size_t)r * DIN + d];
            float sg = __fdividef(zv, 1.f + __expf(-zv));
            float yv = ylin * sg;
            hilo(yv, g_ah[(size_t)r * DIN + d], g_al[(size_t)r * DIN + d]);
        }
        return;
    }

    float P[16];
    if (CHAIN) powers16(__expf(dsum * Av[0]), P);
    else {
#pragma unroll
        for (int s = 0; s < 16; s++) P[s] = __expf(dsum * Av[s]);
    }
    if (tid == 0) {
        while (atomicAdd(&g_flag[blk - 8], 0) == 0) __nanosleep(32);
    }
    __syncthreads();
    __threadfence();
#pragma unroll
    for (int s = 0; s < 16; s++)
        hin[s] = g_hch[((size_t)(s * 128 + (g - 1)) << 10) + d];
#pragma unroll
    for (int s = 0; s < 16; s++)
        g_hch[((size_t)(s * 128 + g) << 10) + d] = fmaf(P[s], hin[s], h[s]);
    __threadfence();
    __syncthreads();
    if (tid == 0) atomicExch(&g_flag[blk], 1);

    // ---- correction + gate (data L2-hot from local pass)
    float q[16];
#pragma unroll
    for (int s = 0; s < 16; s++) q[s] = hin[s];
#pragma unroll 2
    for (int t = 0; t < 64; t++) {
        int r = rbase + t;
        float delta = g_delta[(size_t)r * DIN + d];
        float zv = g_xz[(size_t)xzrow(r, dup) * 2048 + 1024 + d];
        float ylin = g_x[(size_t)r * DIN + d];
        const float4* cp = (const float4*)(g_xdbl + (size_t)r * 64 + 48);
        float4 Cq[4];
#pragma unroll
        for (int u = 0; u < 4; u++) Cq[u] = cp[u];
        const float* Cv = (const float*)Cq;
        float p[16];
        if (CHAIN) powers16(__expf(delta * Av[0]), p);
        else {
#pragma unroll
            for (int s = 0; s < 16; s++) p[s] = __expf(delta * Av[s]);
        }
        float c0 = 0.f, c1 = 0.f, c2 = 0.f, c3 = 0.f;
#pragma unroll
        for (int s = 0; s < 16; s++) {
            q[s] *= p[s];
            float hv = q[s] * Cv[s];
            if ((s & 3) == 0) c0 += hv;
            else if ((s & 3) == 1) c1 += hv;
            else if ((s & 3) == 2) c2 += hv;
            else c3 += hv;
        }
        float y = ylin + (c0 + c1) + (c2 + c3);
        float sg = __fdividef(zv, 1.f + __expf(-zv));
        float yv = y * sg;
        hilo(yv, g_ah[(size_t)r * DIN + d], g_al[(size_t)r * DIN + d]);
    }
}

__global__ __launch_bounds__(128) void k_scanF(const float* __restrict__ Alog,
                                               const float* __restrict__ Dp,
                                               int lgNCH, int w0, int w1, int w2, int w3,
                                               int dup) {
    int blk = blockIdx.x;
    int dg = blk & 7;
    int g = blk >> 3;
    int seq = g >> lgNCH;
    int j = g & ((1 << lgNCH) - 1);
    int d = (dg << 7) | threadIdx.x;
    int m = wsel4(seq >> 2, w0, w1, w2, w3);
    float Av[16];
    const float* ap = Alog + ((size_t)m * DIN + d) * 16;
#pragma unroll
    for (int s = 0; s < 16; s++) Av[s] = -__expf(ap[s]);
    bool chain = true;
#pragma unroll
    for (int s = 1; s < 16; s++)
        chain = chain &&
                (fabsf(Av[s] - (float)(s + 1) * Av[0]) <=
                 1e-3f * (float)(s + 1) * fabsf(Av[0]) + 1e-7f);
    float Dv = Dp[m * DIN + d];
    int rbase = g << 6;
    if (chain) scanF_body<true>(rbase, d, g, j, blk, dup, Av, Dv);
    else       scanF_body<false>(rbase, d, g, j, blk, dup, Av, Dv);
}

// ---------------------------------------------------------------------------
// layer-0 epilogue: fold halves, layernorm, residual; emit layer-1 GEMM input
// (forward + reversed copies) directly as bf16 hi/lo.
// ---------------------------------------------------------------------------
__global__ __launch_bounds__(128) void k_combine(
    const float* __restrict__ s0, const float* __restrict__ s1,
    const float* __restrict__ s2, const float* __restrict__ s3,
    const float* __restrict__ lnw, const float* __restrict__ lnb) {
    int blk = blockIdx.x;
    int t = blk & 255;
    int b = (blk >> 8) & 3;
    int slot = blk >> 10;
    const float* src = slot == 0 ? s0 : slot == 1 ? s1 : slot == 2 ? s2 : s3;
    int rowA = ((slot * 4 + b) * 512 + t) * CC;
    int rowB = ((slot * 4 + b) * 512 + (511 - t)) * CC;
    int tid = threadIdx.x;
    float v[4];
#pragma unroll
    for (int j = 0; j < 4; j++) {
        int c = tid + j * 128;
        v[j] = 0.5f * (g_o[rowA + c] + g_o[rowB + c]);
    }
    __shared__ float red[8];
    int wid = tid >> 5, lane = tid & 31;
    float s = (v[0] + v[1]) + (v[2] + v[3]);
#pragma unroll
    for (int o = 16; o; o >>= 1) s += __shfl_xor_sync(~0u, s, o);
    if (lane == 0) red[wid] = s;
    __syncthreads();
    float mean = (red[0] + red[1] + red[2] + red[3]) * (1.f / 512.f);
    float q = 0.f;
#pragma unroll
    for (int j = 0; j < 4; j++) { float dd = v[j] - mean; q = fmaf(dd, dd, q); }
#pragma unroll
    for (int o = 16; o; o >>= 1) q += __shfl_xor_sync(~0u, q, o);
    if (lane == 0) red[4 + wid] = q;
    __syncthreads();
    float var = (red[4] + red[5] + red[6] + red[7]) * (1.f / 512.f);
    float rstd = rsqrtf(var + 1e-5f);
    int tau = slot * 256 + t;
#pragma unroll
    for (int j = 0; j < 4; j++) {
        int c = tid + j * 128;
        float o = (v[j] - mean) * rstd * lnw[c] + lnb[c] + src[(b * 256 + t) * CC + c];
        __nv_bfloat16 hh, ll;
        hilo(o, hh, ll);
        int idxF = ((b * 1024) + tau) * CC + c;
        int idxR = (((4 + b) * 1024) + (1023 - tau)) * CC + c;
        g_ah[idxF] = hh; g_al[idxF] = ll;
        g_ah[idxR] = hh; g_al[idxR] = ll;
    }
}

__global__ void k_final(float* __restrict__ out) {
    int idx = blockIdx.x * blockDim.x + threadIdx.x;
    if (idx >= BB * 1024 * CC) return;
    int c = idx & (CC - 1);
    int rest = idx >> 9;
    int tau = rest & 1023;
    int b = rest >> 10;
    float f = 0.5f * (g_o[((b * 1024) + tau) * CC + c] +
                      g_o[(((4 + b) * 1024) + (1023 - tau)) * CC + c]);
    int i = tau >> 8;
    int t = tau & 255;
    out[(((i * 4 + b) * 256 + t) << 9) + c] = f;
}

// ---------------------------------------------------------------------------
extern "C" void kernel_launch(void* const* d_in, const int* in_sizes, int n_in,
                              void* d_out, int out_size) {
    const float* x0hw = (const float*)d_in[0];
    const float* x1hw = (const float*)d_in[1];
    const float* x0wh = (const float*)d_in[2];
    const float* x1wh = (const float*)d_in[3];
    const float* in_w = (const float*)d_in[4];
    const float* cw   = (const float*)d_in[5];
    const float* cb   = (const float*)d_in[6];
    const float* xw   = (const float*)d_in[7];
    const float* dtw  = (const float*)d_in[8];
    const float* dtb  = (const float*)d_in[9];
    const float* alog = (const float*)d_in[10];
    const float* Dp   = (const float*)d_in[11];
    const float* ow   = (const float*)d_in[12];
    const float* lnw  = (const float*)d_in[13];
    const float* lnb  = (const float*)d_in[14];
    float* out = (float*)d_out;

    float *pxz, *px, *po;
    cudaGetSymbolAddress((void**)&pxz, g_xz);
    cudaGetSymbolAddress((void**)&px, g_x);
    cudaGetSymbolAddress((void**)&po, g_o);
    __nv_bfloat16 *pah, *pal, *pwih, *pwil, *pwoh, *pwol;
    cudaGetSymbolAddress((void**)&pah, g_ah);
    cudaGetSymbolAddress((void**)&pal, g_al);
    cudaGetSymbolAddress((void**)&pwih, g_wih);
    cudaGetSymbolAddress((void**)&pwil, g_wil);
    cudaGetSymbolAddress((void**)&pwoh, g_woh);
    cudaGetSymbolAddress((void**)&pwol, g_wol);

    static int inited = 0;
    static cudaStream_t s2;
    static cudaEvent_t evX0, evZ0, evX1, evZ1;
    if (!inited) {
        cudaFuncSetAttribute(k_mma, cudaFuncAttributeMaxDynamicSharedMemorySize,
                             2 * MM_STAGE);
        cudaStreamCreateWithFlags(&s2, cudaStreamNonBlocking);
        cudaEventCreateWithFlags(&evX0, cudaEventDisableTiming);
        cudaEventCreateWithFlags(&evZ0, cudaEventDisableTiming);
        cudaEventCreateWithFlags(&evX1, cudaEventDisableTiming);
        cudaEventCreateWithFlags(&evZ1, cudaEventDisableTiming);
        inited = 1;
    }
    const int MMSMEM = 2 * MM_STAGE;

    const int EL = RTOK * DIN;
    const int ELF = BB * 1024 * CC;
    const size_t ZW = (size_t)1024 * 512;

    // weights -> bf16 hi/lo
    k_cvt<<<(6 * 2048 * 512 + 255) / 256, 256>>>(in_w, pwih, pwil, 6 * 2048 * 512);
    k_cvt<<<(6 * 512 * 1024 + 255) / 256, 256>>>(ow, pwoh, pwol, 6 * 512 * 1024);

    // ---------------- layer 0 (T=512, NCH=8; compact in_proj) ---------------
    {
        const int w0 = 0, w1 = 2, w2 = 1, w3 = 3, rpg = 2048, T = 512, lg = 3;
        k_build4<<<(4096 * CC + 255) / 256, 256>>>(x0hw, x1hw, x0wh, x1wh);
        k_mma<<<dim3(8, 32), 256, MMSMEM>>>(
            pah, pal, pwih, pwil, pxz, 512, 2048, 1024, 2048 * 512, w0, w1, w2, w3);
        cudaEventRecord(evX0, 0);
        cudaStreamWaitEvent(s2, evX0, 0);
        k_mma<<<dim3(8, 32), 256, MMSMEM, s2>>>(
            pah, pal, pwih + ZW, pwil + ZW, pxz + 1024, 512, 2048,
            1024, 2048 * 512, w0, w1, w2, w3);
        cudaEventRecord(evZ0, s2);
        k_conv<<<(EL + 255) / 256, 256>>>(cw, cb, T, rpg, w0, w1, w2, w3, 1);
        k_gemm64sk<<<dim3(1, RTOK / 64, 8), 256>>>(px, xw, rpg, 64 * 1024, w0, w1, w2, w3);
        k_reduce8<<<(RTOK * 64 + 255) / 256, 256>>>();
        k_gemm64dt<<<dim3(1024 / 64, RTOK / 64), 256>>>(dtw, dtb, rpg, w0, w1, w2, w3);
        cudaStreamWaitEvent(0, evZ0, 0);   // scanF gates with z
        k_scanF<<<1024, 128>>>(alog, Dp, lg, w0, w1, w2, w3, 1);
        k_mma<<<dim3(4, 64), 256, MMSMEM>>>(
            pah, pal, pwoh, pwol, po, 1024, 512, rpg, 512 * 1024, w0, w1, w2, w3);
        k_combine<<<4096, 128>>>(x0hw, x1hw, x0wh, x1wh, lnw, lnb);
    }

    // ---------------- layer 1 (T=1024, NCH=16) ----------------
    {
        const int w0 = 4, w1 = 5, w2 = 4, w3 = 5, rpg = 4096, T = 1024, lg = 4;
        k_mma<<<dim3(8, 64), 256, MMSMEM>>>(
            pah, pal, pwih, pwil, pxz, 512, 2048, rpg, 2048 * 512, w0, w1, w2, w3);
        cudaEventRecord(evX1, 0);
        cudaStreamWaitEvent(s2, evX1, 0);
        k_mma<<<dim3(8, 64), 256, MMSMEM, s2>>>(
            pah, pal, pwih + ZW, pwil + ZW, pxz + 1024, 512, 2048,
            rpg, 2048 * 512, w0, w1, w2, w3);
        cudaEventRecord(evZ1, s2);
        k_conv<<<(EL + 255) / 256, 256>>>(cw, cb, T, rpg, w0, w1, w2, w3, 0);
        k_gemm64sk<<<dim3(1, RTOK / 64, 8), 256>>>(px, xw, rpg, 64 * 1024, w0, w1, w2, w3);
        k_reduce8<<<(RTOK * 64 + 255) / 256, 256>>>();
        k_gemm64dt<<<dim3(1024 / 64, RTOK / 64), 256>>>(dtw, dtb, rpg, w0, w1, w2, w3);
        cudaStreamWaitEvent(0, evZ1, 0);
        k_scanF<<<1024, 128>>>(alog, Dp, lg, w0, w1, w2, w3, 0);
        k_mma<<<dim3(4, 64), 256, MMSMEM>>>(
            pah, pal, pwoh, pwol, po, 1024, 512, rpg, 512 * 1024, w0, w1, w2, w3);
        k_final<<<(ELF + 255) / 256, 256>>>(out);
    }
}

// round 15
// speedup vs baseline: 1.3201x; 1.0537x over previous
#include <cuda_runtime.h>
#include <cuda_bf16.h>
#include <cstdint>

// ---------------------------------------------------------------------------
// MultiScaleMambaEncoder — mma.sync bf16 hi/lo x3 GEMMs + single-pass
// decoupled-lookback chunked scan. Layer-0 in_proj on 4096 unique rows;
// z-half of in_proj on a side stream. R11 structure + vectorized glue.
// ---------------------------------------------------------------------------

#define BB 4
#define CC 512
#define DIN 1024
#define RTOK 8192

// fp32 scratch
__device__ float g_xz[RTOK * 2 * DIN];
__device__ float g_x[RTOK * DIN];          // conv output, then ylin
__device__ float g_xdbl[RTOK * 64];
__device__ float g_xdblp[8 * RTOK * 64];   // split-K partials
__device__ float g_hch[16 * 128 * 1024];   // published h_out per chunk
__device__ float g_delta[RTOK * DIN];
__device__ float g_o[RTOK * CC];
__device__ int   g_flag[1024];             // lookback flags
// bf16 hi/lo scratch (GEMM A operands)
__device__ __nv_bfloat16 g_ah[RTOK * DIN];
__device__ __nv_bfloat16 g_al[RTOK * DIN];
__device__ __nv_bfloat16 g_wih[6 * 2048 * 512];
__device__ __nv_bfloat16 g_wil[6 * 2048 * 512];
__device__ __nv_bfloat16 g_woh[6 * 512 * 1024];
__device__ __nv_bfloat16 g_wol[6 * 512 * 1024];

__device__ __forceinline__ int wsel4(int ml, int w0, int w1, int w2, int w3) {
    return ml == 0 ? w0 : ml == 1 ? w1 : ml == 2 ? w2 : w3;
}

#define FMA2(d, a, b) asm("fma.rn.f32x2 %0, %1, %2, %0;" : "+l"(d) : "l"(a), "l"(b))
#define DUP2(d, s)    asm("mov.b64 %0, {%1, %1};" : "=l"(d) : "f"(s))

__device__ __forceinline__ uint32_t smem_u32(const void* p) {
    uint32_t a;
    asm("{ .reg .u64 t; cvta.to.shared.u64 t, %1; cvt.u32.u64 %0, t; }" : "=r"(a) : "l"(p));
    return a;
}
#define CP16(dst, src)  asm volatile("cp.async.cg.shared.global [%0], [%1], 16;" :: "r"(dst), "l"(src))
#define CP_COMMIT()     asm volatile("cp.async.commit_group;" ::: "memory")
#define CP_WAIT0()      asm volatile("cp.async.wait_group 0;" ::: "memory")

#define LDM4(r0, r1, r2, r3, a) \
    asm volatile("ldmatrix.sync.aligned.m8n8.x4.shared.b16 {%0,%1,%2,%3}, [%4];" \
                 : "=r"(r0), "=r"(r1), "=r"(r2), "=r"(r3) : "r"(a))
#define LDM2(r0, r1, a) \
    asm volatile("ldmatrix.sync.aligned.m8n8.x2.shared.b16 {%0,%1}, [%2];" \
                 : "=r"(r0), "=r"(r1) : "r"(a))
#define MMA16816(d, a, b) \
    asm volatile("mma.sync.aligned.m16n8k16.row.col.f32.bf16.bf16.f32 " \
                 "{%0,%1,%2,%3},{%4,%5,%6,%7},{%8,%9},{%0,%1,%2,%3};" \
                 : "+f"((d)[0]), "+f"((d)[1]), "+f"((d)[2]), "+f"((d)[3]) \
                 : "r"((a)[0]), "r"((a)[1]), "r"((a)[2]), "r"((a)[3]), \
                   "r"((b)[0]), "r"((b)[1]))

__device__ __forceinline__ void hilo(float v, __nv_bfloat16& h, __nv_bfloat16& l) {
    h = __float2bfloat16(v);
    l = __float2bfloat16(v - __bfloat162float(h));
}
__device__ __forceinline__ unsigned short bfbits(__nv_bfloat16 h) {
    return *reinterpret_cast<unsigned short*>(&h);
}
// powers: p[s] = e1^(s+1), depth-4 ladder
__device__ __forceinline__ void powers16(float e1, float* p) {
    float e2 = e1 * e1, e4 = e2 * e2, e8 = e4 * e4;
    p[0] = e1;        p[1] = e2;        p[2] = e2 * e1;   p[3] = e4;
    p[4] = e4 * e1;   p[5] = e4 * e2;   p[6] = e4 * p[2]; p[7] = e8;
    p[8] = e8 * e1;   p[9] = e8 * e2;   p[10] = e8 * p[2]; p[11] = e8 * e4;
    p[12] = e8 * p[4]; p[13] = e8 * p[5]; p[14] = e8 * p[6]; p[15] = e8 * e8;
}
// layer-0 xz row map: r in [0,8192) -> unique row in [0,4096)
__device__ __forceinline__ int xzrow(int r, int dup) {
    if (!dup) return r;
    int t = r & 511;
    int tt = t < 256 ? t : 511 - t;
    return ((r >> 9) << 8) + tt;
}

// ---------------------------------------------------------------------------
// fp32 -> bf16 hi/lo, vectorized (4 elems/thread)
__global__ void k_cvt(const float* __restrict__ src, __nv_bfloat16* __restrict__ hi,
                      __nv_bfloat16* __restrict__ lo, int n4) {
    int i = blockIdx.x * blockDim.x + threadIdx.x;
    if (i >= n4) return;
    float4 v = ((const float4*)src)[i];
    __nv_bfloat16 h0, l0, h1, l1, h2, l2, h3, l3;
    hilo(v.x, h0, l0); hilo(v.y, h1, l1); hilo(v.z, h2, l2); hilo(v.w, h3, l3);
    ushort4 ph = make_ushort4(bfbits(h0), bfbits(h1), bfbits(h2), bfbits(h3));
    ushort4 pl = make_ushort4(bfbits(l0), bfbits(l1), bfbits(l2), bfbits(l3));
    ((ushort4*)hi)[i] = ph;
    ((ushort4*)lo)[i] = pl;
}

// layer-0 compact inputs: 4096 unique rows, 4 c per thread
__global__ void k_build4(const float* __restrict__ s0, const float* __restrict__ s1,
                         const float* __restrict__ s2, const float* __restrict__ s3) {
    int idx = blockIdx.x * blockDim.x + threadIdx.x;
    if (idx >= 4096 * CC / 4) return;
    int r = idx >> 7;                    // 0..4095 (128 float4 per row)
    int slot = r >> 10;
    const float* s = slot == 0 ? s0 : slot == 1 ? s1 : slot == 2 ? s2 : s3;
    float4 v = ((const float4*)(s + (size_t)(r & 1023) * CC))[idx & 127];
    __nv_bfloat16 h0, l0, h1, l1, h2, l2, h3, l3;
    hilo(v.x, h0, l0); hilo(v.y, h1, l1); hilo(v.z, h2, l2); hilo(v.w, h3, l3);
    ((ushort4*)g_ah)[idx] = make_ushort4(bfbits(h0), bfbits(h1), bfbits(h2), bfbits(h3));
    ((ushort4*)g_al)[idx] = make_ushort4(bfbits(l0), bfbits(l1), bfbits(l2), bfbits(l3));
}

// ---------------------------------------------------------------------------
// mma.sync GEMM: C = A * W^T (bf16 hi/lo x3), 128x128 tile, BK=32,
// 2-stage cp.async double buffer, 2 CTAs/SM.
// ---------------------------------------------------------------------------
#define MM_STAGE 40960
#define MM_TILE  10240

__global__ __launch_bounds__(256, 2) void k_mma(
    const __nv_bfloat16* __restrict__ Ah, const __nv_bfloat16* __restrict__ Al,
    const __nv_bfloat16* __restrict__ WhB, const __nv_bfloat16* __restrict__ WlB,
    float* __restrict__ C, int K, int ldc,
    int rpg, int wstride, int w0, int w1, int w2, int w3) {
    extern __shared__ __align__(128) uint8_t smraw[];
    const uint32_t smb = smem_u32(smraw);
    const int tid = threadIdx.x;
    const int wid = tid >> 5;
    const int lane = tid & 31;
    const int wm = wid >> 2;
    const int wn = wid & 3;
    const int row0 = blockIdx.y * 128;
    const int col0 = blockIdx.x * 128;
    const int wsel = wsel4(row0 / rpg, w0, w1, w2, w3);
    const __nv_bfloat16* Wh = WhB + (size_t)wsel * wstride;
    const __nv_bfloat16* Wl = WlB + (size_t)wsel * wstride;
    const int nc = K >> 5;

    float acc[4][4][4];
#pragma unroll
    for (int i = 0; i < 4; i++)
#pragma unroll
        for (int j = 0; j < 4; j++)
#pragma unroll
            for (int q = 0; q < 4; q++) acc[i][j][q] = 0.f;

    auto load_stage = [&](int kc, int st) {
        const int k0 = kc << 5;
        const uint32_t sb = smb + st * MM_STAGE;
#pragma unroll
        for (int p = 0; p < 8; p++) {
            int u = tid + (p << 8);
            int tile = u >> 9;
            int v = u & 511;
            int r = v >> 2, seg = v & 3;
            const __nv_bfloat16* src;
            if (tile == 0)      src = Ah + (size_t)(row0 + r) * K;
            else if (tile == 1) src = Al + (size_t)(row0 + r) * K;
            else if (tile == 2) src = Wh + (size_t)(col0 + r) * K;
            else                src = Wl + (size_t)(col0 + r) * K;
            CP16(sb + tile * MM_TILE + r * 80 + seg * 16, src + k0 + seg * 8);
        }
        CP_COMMIT();
    };

    load_stage(0, 0);
    CP_WAIT0();
    __syncthreads();

    const uint32_t aRowByte = (uint32_t)(wm * 64 + (lane & 15)) * 80 + ((lane >> 4) << 4);
    const uint32_t bRowByte = (uint32_t)(wn * 32 + (lane & 7)) * 80 + (((lane >> 3) & 1) << 4);

    for (int c = 0; c < nc; c++) {
        const int st = c & 1;
        if (c + 1 < nc) load_stage(c + 1, st ^ 1);
        const uint32_t sb = smb + st * MM_STAGE;
#pragma unroll
        for (int ks = 0; ks < 2; ks++) {
            uint32_t ah[4][4], al[4][4], bh[4][2], bl[4][2];
            const uint32_t kb = ks * 32;
#pragma unroll
            for (int mi = 0; mi < 4; mi++) {
                uint32_t ra = sb + aRowByte + (uint32_t)mi * 16 * 80 + kb;
                LDM4(ah[mi][0], ah[mi][1], ah[mi][2], ah[mi][3], ra);
                LDM4(al[mi][0], al[mi][1], al[mi][2], al[mi][3], ra + MM_TILE);
            }
#pragma unroll
            for (int ni = 0; ni < 4; ni++) {
                uint32_t rb = sb + 2 * MM_TILE + bRowByte + (uint32_t)ni * 8 * 80 + kb;
                LDM2(bh[ni][0], bh[ni][1], rb);
                LDM2(bl[ni][0], bl[ni][1], rb + MM_TILE);
            }
#pragma unroll
            for (int mi = 0; mi < 4; mi++)
#pragma unroll
                for (int ni = 0; ni < 4; ni++) {
                    MMA16816(acc[mi][ni], ah[mi], bh[ni]);
                    MMA16816(acc[mi][ni], ah[mi], bl[ni]);
                    MMA16816(acc[mi][ni], al[mi], bh[ni]);
                }
        }
        if (c + 1 < nc) CP_WAIT0();
        __syncthreads();
    }

    const int gr = lane >> 2;
    const int gc = (lane & 3) * 2;
#pragma unroll
    for (int mi = 0; mi < 4; mi++)
#pragma unroll
        for (int ni = 0; ni < 4; ni++) {
            int row = row0 + wm * 64 + mi * 16 + gr;
            int col = col0 + wn * 32 + ni * 8 + gc;
            float* p0 = C + (size_t)row * ldc + col;
            float* p1 = C + (size_t)(row + 8) * ldc + col;
            *(float2*)p0 = make_float2(acc[mi][ni][0], acc[mi][ni][1]);
            *(float2*)p1 = make_float2(acc[mi][ni][2], acc[mi][ni][3]);
        }
}

// ---------------------------------------------------------------------------
// 64x64 FFMA2 GEMM body (x_proj split-K, dt-proj)
// ---------------------------------------------------------------------------
__device__ __forceinline__ void gemm64_accum(
    const float* A, const float* W, unsigned long long acc[4][2],
    int K, int lda, int ldb, int row0, int col0) {
    __shared__ float As[16][68];
    __shared__ float Bs[16][68];
    const int tid = threadIdx.x;
    const int tx = tid & 15, ty = tid >> 4;
    for (int k0 = 0; k0 < K; k0 += 16) {
        __syncthreads();
#pragma unroll
        for (int i = 0; i < 4; i++) {
            int idx = tid + i * 256;
            int kk = idx & 15, rr = idx >> 4;
            As[kk][rr] = A[(size_t)(row0 + rr) * lda + k0 + kk];
            Bs[kk][rr] = W[(size_t)(col0 + rr) * ldb + k0 + kk];
        }
        __syncthreads();
#pragma unroll
        for (int kk = 0; kk < 16; kk++) {
            float a[4];
            *(float4*)a = *(const float4*)&As[kk][ty * 4];
            unsigned long long b2[2];
            *(float4*)b2 = *(const float4*)&Bs[kk][tx * 4];
#pragma unroll
            for (int i = 0; i < 4; i++) {
                unsigned long long ad;
                DUP2(ad, a[i]);
                FMA2(acc[i][0], ad, b2[0]);
                FMA2(acc[i][1], ad, b2[1]);
            }
        }
    }
}

// x_proj split-K (8 slices of K=128)
__global__ __launch_bounds__(256) void k_gemm64sk(
    const float* __restrict__ A, const float* __restrict__ Wb,
    int rpg, int wstride, int w0, int w1, int w2, int w3) {
    const int row0 = blockIdx.y * 64;
    const int z = blockIdx.z;
    const int wsel = wsel4(row0 / rpg, w0, w1, w2, w3);
    const float* W = Wb + (size_t)wsel * wstride + z * 128;
    unsigned long long acc[4][2];
#pragma unroll
    for (int i = 0; i < 4; i++) { acc[i][0] = 0ull; acc[i][1] = 0ull; }
    gemm64_accum(A + z * 128, W, acc, 128, 1024, 1024, row0, 0);
    float* Cout = g_xdblp + (size_t)z * RTOK * 64;
    const int tx = threadIdx.x & 15, ty = threadIdx.x >> 4;
#pragma unroll
    for (int i = 0; i < 4; i++) {
        float* cp = Cout + (size_t)(row0 + ty * 4 + i) * 64 + tx * 4;
        *(ulonglong2*)cp = make_ulonglong2(acc[i][0], acc[i][1]);
    }
}

// reduce split-K partials; also zero lookback flags for the next scan
__global__ void k_reduce8() {
    int idx = blockIdx.x * blockDim.x + threadIdx.x;
    if (idx < 1024) g_flag[idx] = 0;
    if (idx >= RTOK * 64) return;
    const int S = RTOK * 64;
    float a0 = g_xdblp[idx] + g_xdblp[idx + S];
    float a1 = g_xdblp[idx + 2 * S] + g_xdblp[idx + 3 * S];
    float a2 = g_xdblp[idx + 4 * S] + g_xdblp[idx + 5 * S];
    float a3 = g_xdblp[idx + 6 * S] + g_xdblp[idx + 7 * S];
    g_xdbl[idx] = (a0 + a1) + (a2 + a3);
}

// dt-proj with fused +dtb and softplus -> g_delta
__global__ __launch_bounds__(256) void k_gemm64dt(
    const float* __restrict__ dtw, const float* __restrict__ dtb,
    int rpg, int w0, int w1, int w2, int w3) {
    const int row0 = blockIdx.y * 64;
    const int col0 = blockIdx.x * 64;
    const int m = wsel4(row0 / rpg, w0, w1, w2, w3);
    const float* W = dtw + (size_t)m * DIN * 32;
    unsigned long long acc[4][2];
#pragma unroll
    for (int i = 0; i < 4; i++) { acc[i][0] = 0ull; acc[i][1] = 0ull; }
    gemm64_accum(g_xdbl, W, acc, 32, 64, 32, row0, col0);
    const int tx = threadIdx.x & 15, ty = threadIdx.x >> 4;
#pragma unroll
    for (int i = 0; i < 4; i++) {
        const float* av = (const float*)acc[i];
        float r[4];
#pragma unroll
        for (int j = 0; j < 4; j++) {
            int col = col0 + tx * 4 + j;
            float x = av[j] + dtb[m * DIN + col];
            r[j] = (x > 15.f) ? x : __logf(1.f + __expf(x));
        }
        float* cp = g_delta + (size_t)(row0 + ty * 4 + i) * DIN + col0 + tx * 4;
        *(float4*)cp = make_float4(r[0], r[1], r[2], r[3]);
    }
}

// ---------------------------------------------------------------------------
// causal depthwise conv (4 taps) + bias + SiLU, 4 d per thread (float4).
// dup=1: layer-0 compact-xz map.
// ---------------------------------------------------------------------------
__global__ void k_conv(const float* __restrict__ cw, const float* __restrict__ cb,
                       int T, int rpg, int w0, int w1, int w2, int w3, int dup) {
    int idx = blockIdx.x * blockDim.x + threadIdx.x;
    if (idx >= RTOK * DIN / 4) return;
    int d4 = (idx & 255) << 2;
    int r = idx >> 8;
    int t = r & (T - 1);
    int m = wsel4(r / rpg, w0, w1, w2, w3);
    const float4* cwp = (const float4*)(cw + ((size_t)m * DIN + d4) * 4);
    float4 wv0 = cwp[0], wv1 = cwp[1], wv2 = cwp[2], wv3 = cwp[3];
    float4 acc = *(const float4*)(cb + m * DIN + d4);
    const float* w0p = (const float*)&wv0;
    const float* w1p = (const float*)&wv1;
    const float* w2p = (const float*)&wv2;
    const float* w3p = (const float*)&wv3;
#pragma unroll
    for (int k = 0; k < 4; k++) {
        int tt = t - 3 + k;
        if (tt >= 0) {
            int row = xzrow(r + tt - t, dup);
            float4 xv = *(const float4*)(g_xz + (size_t)row * (2 * DIN) + d4);
            acc.x = fmaf(w0p[k], xv.x, acc.x);
            acc.y = fmaf(w1p[k], xv.y, acc.y);
            acc.z = fmaf(w2p[k], xv.z, acc.z);
            acc.w = fmaf(w3p[k], xv.w, acc.w);
        }
    }
    float4 o;
    o.x = __fdividef(acc.x, 1.f + __expf(-acc.x));
    o.y = __fdividef(acc.y, 1.f + __expf(-acc.y));
    o.z = __fdividef(acc.z, 1.f + __expf(-acc.z));
    o.w = __fdividef(acc.w, 1.f + __expf(-acc.w));
    *(float4*)(g_x + (size_t)r * DIN + d4) = o;
}

// ---------------------------------------------------------------------------
// Fused chunked scan with decoupled lookback (passes A+B+C in one kernel).
// ---------------------------------------------------------------------------
template <bool CHAIN>
__device__ __forceinline__ void scanF_body(int rbase, int d, int g, int j,
                                           int blk, int dup,
                                           const float Av[16], float Dv) {
    const int tid = threadIdx.x;
    float h[16];
#pragma unroll
    for (int s = 0; s < 16; s++) h[s] = 0.f;
    float dsum = 0.f;
    // ---- local scan (h0 = 0); ylin (incl. D*x) overwrites g_x
#pragma unroll 2
    for (int t = 0; t < 64; t++) {
        int r = rbase + t;
        float delta = g_delta[(size_t)r * DIN + d];
        float xv = g_x[(size_t)r * DIN + d];
        const float4* bc = (const float4*)(g_xdbl + (size_t)r * 64 + 32);
        float4 Bq[4], Cq[4];
#pragma unroll
        for (int q = 0; q < 4; q++) { Bq[q] = bc[q]; Cq[q] = bc[q + 4]; }
        const float* Bv = (const float*)Bq;
        const float* Cv = (const float*)Cq;
        dsum += delta;
        float p[16];
        if (CHAIN) powers16(__expf(delta * Av[0]), p);
        else {
#pragma unroll
            for (int s = 0; s < 16; s++) p[s] = __expf(delta * Av[s]);
        }
        float dx = delta * xv;
        float y0 = 0.f, y1 = 0.f, y2 = 0.f, y3 = 0.f;
#pragma unroll
        for (int s = 0; s < 16; s++) {
            h[s] = fmaf(h[s], p[s], dx * Bv[s]);
            float hv = h[s] * Cv[s];
            if ((s & 3) == 0) y0 += hv;
            else if ((s & 3) == 1) y1 += hv;
            else if ((s & 3) == 2) y2 += hv;
            else y3 += hv;
        }
        g_x[(size_t)r * DIN + d] = fmaf(Dv, xv, (y0 + y1) + (y2 + y3));
    }

    float hin[16];
    if (j == 0) {
#pragma unroll
        for (int s = 0; s < 16; s++)
            g_hch[((size_t)(s * 128 + g) << 10) + d] = h[s];
        __threadfence();
        __syncthreads();
        if (tid == 0) atomicExch(&g_flag[blk], 1);
#pragma unroll 2
        for (int t = 0; t < 64; t++) {
            int r = rbase + t;
            float zv = g_xz[(size_t)xzrow(r, dup) * 2048 + 1024 + d];
            float ylin = g_x[(size_t)r * DIN + d];
            float sg = __fdividef(zv, 1.f + __expf(-zv));
            float yv = ylin * sg;
            hilo(yv, g_ah[(size_t)r * DIN + d], g_al[(size_t)r * DIN + d]);
        }
        return;
    }

    float P[16];
    if (CHAIN) powers16(__expf(dsum * Av[0]), P);
    else {
#pragma unroll
        for (int s = 0; s < 16; s++) P[s] = __expf(dsum * Av[s]);
    }
    if (tid == 0) {
        while (atomicAdd(&g_flag[blk - 8], 0) == 0) __nanosleep(32);
    }
    __syncthreads();
    __threadfence();
#pragma unroll
    for (int s = 0; s < 16; s++)
        hin[s] = g_hch[((size_t)(s * 128 + (g - 1)) << 10) + d];
#pragma unroll
    for (int s = 0; s < 16; s++)
        g_hch[((size_t)(s * 128 + g) << 10) + d] = fmaf(P[s], hin[s], h[s]);
    __threadfence();
    __syncthreads();
    if (tid == 0) atomicExch(&g_flag[blk], 1);

    // ---- correction + gate (data L2-hot from local pass)
    float q[16];
#pragma unroll
    for (int s = 0; s < 16; s++) q[s] = hin[s];
#pragma unroll 2
    for (int t = 0; t < 64; t++) {
        int r = rbase + t;
        float delta = g_delta[(size_t)r * DIN + d];
        float zv = g_xz[(size_t)xzrow(r, dup) * 2048 + 1024 + d];
        float ylin = g_x[(size_t)r * DIN + d];
        const float4* cp = (const float4*)(g_xdbl + (size_t)r * 64 + 48);
        float4 Cq[4];
#pragma unroll
        for (int u = 0; u < 4; u++) Cq[u] = cp[u];
        const float* Cv = (const float*)Cq;
        float p[16];
        if (CHAIN) powers16(__expf(delta * Av[0]), p);
        else {
#pragma unroll
            for (int s = 0; s < 16; s++) p[s] = __expf(delta * Av[s]);
        }
        float c0 = 0.f, c1 = 0.f, c2 = 0.f, c3 = 0.f;
#pragma unroll
        for (int s = 0; s < 16; s++) {
            q[s] *= p[s];
            float hv = q[s] * Cv[s];
            if ((s & 3) == 0) c0 += hv;
            else if ((s & 3) == 1) c1 += hv;
            else if ((s & 3) == 2) c2 += hv;
            else c3 += hv;
        }
        float y = ylin + (c0 + c1) + (c2 + c3);
        float sg = __fdividef(zv, 1.f + __expf(-zv));
        float yv = y * sg;
        hilo(yv, g_ah[(size_t)r * DIN + d], g_al[(size_t)r * DIN + d]);
    }
}

__global__ __launch_bounds__(128) void k_scanF(const float* __restrict__ Alog,
                                               const float* __restrict__ Dp,
                                               int lgNCH, int w0, int w1, int w2, int w3,
                                               int dup) {
    int blk = blockIdx.x;
    int dg = blk & 7;
    int g = blk >> 3;
    int seq = g >> lgNCH;
    int j = g & ((1 << lgNCH) - 1);
    int d = (dg << 7) | threadIdx.x;
    int m = wsel4(seq >> 2, w0, w1, w2, w3);
    float Av[16];
    const float* ap = Alog + ((size_t)m * DIN + d) * 16;
#pragma unroll
    for (int s = 0; s < 16; s++) Av[s] = -__expf(ap[s]);
    bool chain = true;
#pragma unroll
    for (int s = 1; s < 16; s++)
        chain = chain &&
                (fabsf(Av[s] - (float)(s + 1) * Av[0]) <=
                 1e-3f * (float)(s + 1) * fabsf(Av[0]) + 1e-7f);
    float Dv = Dp[m * DIN + d];
    int rbase = g << 6;
    if (chain) scanF_body<true>(rbase, d, g, j, blk, dup, Av, Dv);
    else       scanF_body<false>(rbase, d, g, j, blk, dup, Av, Dv);
}

// ---------------------------------------------------------------------------
// layer-0 epilogue: fold halves, layernorm, residual; emit layer-1 GEMM input
// (forward + reversed copies) directly as bf16 hi/lo.
// ---------------------------------------------------------------------------
__global__ __launch_bounds__(128) void k_combine(
    const float* __restrict__ s0, const float* __restrict__ s1,
    const float* __restrict__ s2, const float* __restrict__ s3,
    const float* __restrict__ lnw, const float* __restrict__ lnb) {
    int blk = blockIdx.x;
    int t = blk & 255;
    int b = (blk >> 8) & 3;
    int slot = blk >> 10;
    const float* src = slot == 0 ? s0 : slot == 1 ? s1 : slot == 2 ? s2 : s3;
    int rowA = ((slot * 4 + b) * 512 + t) * CC;
    int rowB = ((slot * 4 + b) * 512 + (511 - t)) * CC;
    int tid = threadIdx.x;
    float v[4];
#pragma unroll
    for (int j = 0; j < 4; j++) {
        int c = tid + j * 128;
        v[j] = 0.5f * (g_o[rowA + c] + g_o[rowB + c]);
    }
    __shared__ float red[8];
    int wid = tid >> 5, lane = tid & 31;
    float s = (v[0] + v[1]) + (v[2] + v[3]);
#pragma unroll
    for (int o = 16; o; o >>= 1) s += __shfl_xor_sync(~0u, s, o);
    if (lane == 0) red[wid] = s;
    __syncthreads();
    float mean = (red[0] + red[1] + red[2] + red[3]) * (1.f / 512.f);
    float q = 0.f;
#pragma unroll
    for (int j = 0; j < 4; j++) { float dd = v[j] - mean; q = fmaf(dd, dd, q); }
#pragma unroll
    for (int o = 16; o; o >>= 1) q += __shfl_xor_sync(~0u, q, o);
    if (lane == 0) red[4 + wid] = q;
    __syncthreads();
    float var = (red[4] + red[5] + red[6] + red[7]) * (1.f / 512.f);
    float rstd = rsqrtf(var + 1e-5f);
    int tau = slot * 256 + t;
#pragma unroll
    for (int j = 0; j < 4; j++) {
        int c = tid + j * 128;
        float o = (v[j] - mean) * rstd * lnw[c] + lnb[c] + src[(b * 256 + t) * CC + c];
        __nv_bfloat16 hh, ll;
        hilo(o, hh, ll);
        int idxF = ((b * 1024) + tau) * CC + c;
        int idxR = (((4 + b) * 1024) + (1023 - tau)) * CC + c;
        g_ah[idxF] = hh; g_al[idxF] = ll;
        g_ah[idxR] = hh; g_al[idxR] = ll;
    }
}

// final: fused = 0.5*(o4 + reverse(o5)); float4 per thread
__global__ void k_final(float* __restrict__ out) {
    int idx = blockIdx.x * blockDim.x + threadIdx.x;
    if (idx >= BB * 1024 * CC / 4) return;
    int c4 = (idx & 127) << 2;
    int rest = idx >> 7;
    int tau = rest & 1023;
    int b = rest >> 10;
    float4 a = *(const float4*)(g_o + ((size_t)(b * 1024) + tau) * CC + c4);
    float4 bb = *(const float4*)(g_o + ((size_t)((4 + b) * 1024) + (1023 - tau)) * CC + c4);
    float4 f = make_float4(0.5f * (a.x + bb.x), 0.5f * (a.y + bb.y),
                           0.5f * (a.z + bb.z), 0.5f * (a.w + bb.w));
    int i = tau >> 8;
    int t = tau & 255;
    *(float4*)(out + (((size_t)(i * 4 + b) * 256 + t) << 9) + c4) = f;
}

// ---------------------------------------------------------------------------
extern "C" void kernel_launch(void* const* d_in, const int* in_sizes, int n_in,
                              void* d_out, int out_size) {
    const float* x0hw = (const float*)d_in[0];
    const float* x1hw = (const float*)d_in[1];
    const float* x0wh = (const float*)d_in[2];
    const float* x1wh = (const float*)d_in[3];
    const float* in_w = (const float*)d_in[4];
    const float* cw   = (const float*)d_in[5];
    const float* cb   = (const float*)d_in[6];
    const float* xw   = (const float*)d_in[7];
    const float* dtw  = (const float*)d_in[8];
    const float* dtb  = (const float*)d_in[9];
    const float* alog = (const float*)d_in[10];
    const float* Dp   = (const float*)d_in[11];
    const float* ow   = (const float*)d_in[12];
    const float* lnw  = (const float*)d_in[13];
    const float* lnb  = (const float*)d_in[14];
    float* out = (float*)d_out;

    float *pxz, *px, *po;
    cudaGetSymbolAddress((void**)&pxz, g_xz);
    cudaGetSymbolAddress((void**)&px, g_x);
    cudaGetSymbolAddress((void**)&po, g_o);
    __nv_bfloat16 *pah, *pal, *pwih, *pwil, *pwoh, *pwol;
    cudaGetSymbolAddress((void**)&pah, g_ah);
    cudaGetSymbolAddress((void**)&pal, g_al);
    cudaGetSymbolAddress((void**)&pwih, g_wih);
    cudaGetSymbolAddress((void**)&pwil, g_wil);
    cudaGetSymbolAddress((void**)&pwoh, g_woh);
    cudaGetSymbolAddress((void**)&pwol, g_wol);

    static int inited = 0;
    static cudaStream_t s2;
    static cudaEvent_t evX0, evZ0, evX1, evZ1;
    if (!inited) {
        cudaFuncSetAttribute(k_mma, cudaFuncAttributeMaxDynamicSharedMemorySize,
                             2 * MM_STAGE);
        cudaStreamCreateWithFlags(&s2, cudaStreamNonBlocking);
        cudaEventCreateWithFlags(&evX0, cudaEventDisableTiming);
        cudaEventCreateWithFlags(&evZ0, cudaEventDisableTiming);
        cudaEventCreateWithFlags(&evX1, cudaEventDisableTiming);
        cudaEventCreateWithFlags(&evZ1, cudaEventDisableTiming);
        inited = 1;
    }
    const int MMSMEM = 2 * MM_STAGE;

    const int EL = RTOK * DIN;
    const int ELF = BB * 1024 * CC;
    const size_t ZW = (size_t)1024 * 512;

    // weights -> bf16 hi/lo (vectorized: n/4 threads)
    k_cvt<<<(6 * 2048 * 512 / 4 + 255) / 256, 256>>>(in_w, pwih, pwil, 6 * 2048 * 512 / 4);
    k_cvt<<<(6 * 512 * 1024 / 4 + 255) / 256, 256>>>(ow, pwoh, pwol, 6 * 512 * 1024 / 4);

    // ---------------- layer 0 (T=512, NCH=8; compact in_proj) ---------------
    {
        const int w0 = 0, w1 = 2, w2 = 1, w3 = 3, rpg = 2048, T = 512, lg = 3;
        k_build4<<<(4096 * CC / 4 + 255) / 256, 256>>>(x0hw, x1hw, x0wh, x1wh);
        k_mma<<<dim3(8, 32), 256, MMSMEM>>>(
            pah, pal, pwih, pwil, pxz, 512, 2048, 1024, 2048 * 512, w0, w1, w2, w3);
        cudaEventRecord(evX0, 0);
        cudaStreamWaitEvent(s2, evX0, 0);
        k_mma<<<dim3(8, 32), 256, MMSMEM, s2>>>(
            pah, pal, pwih + ZW, pwil + ZW, pxz + 1024, 512, 2048,
            1024, 2048 * 512, w0, w1, w2, w3);
        cudaEventRecord(evZ0, s2);
        k_conv<<<(EL / 4 + 255) / 256, 256>>>(cw, cb, T, rpg, w0, w1, w2, w3, 1);
        k_gemm64sk<<<dim3(1, RTOK / 64, 8), 256>>>(px, xw, rpg, 64 * 1024, w0, w1, w2, w3);
        k_reduce8<<<(RTOK * 64 + 255) / 256, 256>>>();
        k_gemm64dt<<<dim3(1024 / 64, RTOK / 64), 256>>>(dtw, dtb, rpg, w0, w1, w2, w3);
        cudaStreamWaitEvent(0, evZ0, 0);   // scanF gates with z
        k_scanF<<<1024, 128>>>(alog, Dp, lg, w0, w1, w2, w3, 1);
        k_mma<<<dim3(4, 64), 256, MMSMEM>>>(
            pah, pal, pwoh, pwol, po, 1024, 512, rpg, 512 * 1024, w0, w1, w2, w3);
        k_combine<<<4096, 128>>>(x0hw, x1hw, x0wh, x1wh, lnw, lnb);
    }

    // ---------------- layer 1 (T=1024, NCH=16) ----------------
    {
        const int w0 = 4, w1 = 5, w2 = 4, w3 = 5, rpg = 4096, T = 1024, lg = 4;
        k_mma<<<dim3(8, 64), 256, MMSMEM>>>(
            pah, pal, pwih, pwil, pxz, 512, 2048, rpg, 2048 * 512, w0, w1, w2, w3);
        cudaEventRecord(evX1, 0);
        cudaStreamWaitEvent(s2, evX1, 0);
        k_mma<<<dim3(8, 64), 256, MMSMEM, s2>>>(
            pah, pal, pwih + ZW, pwil + ZW, pxz + 1024, 512, 2048,
            rpg, 2048 * 512, w0, w1, w2, w3);
        cudaEventRecord(evZ1, s2);
        k_conv<<<(EL / 4 + 255) / 256, 256>>>(cw, cb, T, rpg, w0, w1, w2, w3, 0);
        k_gemm64sk<<<dim3(1, RTOK / 64, 8), 256>>>(px, xw, rpg, 64 * 1024, w0, w1, w2, w3);
        k_reduce8<<<(RTOK * 64 + 255) / 256, 256>>>();
        k_gemm64dt<<<dim3(1024 / 64, RTOK / 64), 256>>>(dtw, dtb, rpg, w0, w1, w2, w3);
        cudaStreamWaitEvent(0, evZ1, 0);
        k_scanF<<<1024, 128>>>(alog, Dp, lg, w0, w1, w2, w3, 0);
        k_mma<<<dim3(4, 64), 256, MMSMEM>>>(
            pah, pal, pwoh, pwol, po, 1024, 512, rpg, 512 * 1024, w0, w1, w2, w3);
        k_final<<<(ELF / 4 + 255) / 256, 256>>>(out);
    }
}

// round 16
// speedup vs baseline: 1.3295x; 1.0071x over previous
#include <cuda_runtime.h>
#include <cuda_bf16.h>
#include <cstdint>

// ---------------------------------------------------------------------------
// MultiScaleMambaEncoder — mma.sync bf16 hi/lo x3 GEMMs (128x256 tile, 3-stage
// cp.async, wait_group<=1) + single-pass decoupled-lookback chunked scan.
// Layer-0 in_proj on 4096 unique rows; z-half of in_proj on a side stream.
// ---------------------------------------------------------------------------

#define BB 4
#define CC 512
#define DIN 1024
#define RTOK 8192

// fp32 scratch
__device__ float g_xz[RTOK * 2 * DIN];
__device__ float g_x[RTOK * DIN];          // conv output, then ylin
__device__ float g_xdbl[RTOK * 64];
__device__ float g_xdblp[8 * RTOK * 64];   // split-K partials
__device__ float g_hch[16 * 128 * 1024];   // published h_out per chunk
__device__ float g_delta[RTOK * DIN];
__device__ float g_o[RTOK * CC];
__device__ int   g_flag[1024];             // lookback flags
// bf16 hi/lo scratch (GEMM A operands)
__device__ __nv_bfloat16 g_ah[RTOK * DIN];
__device__ __nv_bfloat16 g_al[RTOK * DIN];
__device__ __nv_bfloat16 g_wih[6 * 2048 * 512];
__device__ __nv_bfloat16 g_wil[6 * 2048 * 512];
__device__ __nv_bfloat16 g_woh[6 * 512 * 1024];
__device__ __nv_bfloat16 g_wol[6 * 512 * 1024];

__device__ __forceinline__ int wsel4(int ml, int w0, int w1, int w2, int w3) {
    return ml == 0 ? w0 : ml == 1 ? w1 : ml == 2 ? w2 : w3;
}

#define FMA2(d, a, b) asm("fma.rn.f32x2 %0, %1, %2, %0;" : "+l"(d) : "l"(a), "l"(b))
#define DUP2(d, s)    asm("mov.b64 %0, {%1, %1};" : "=l"(d) : "f"(s))

__device__ __forceinline__ uint32_t smem_u32(const void* p) {
    uint32_t a;
    asm("{ .reg .u64 t; cvta.to.shared.u64 t, %1; cvt.u32.u64 %0, t; }" : "=r"(a) : "l"(p));
    return a;
}
#define CP16(dst, src)  asm volatile("cp.async.cg.shared.global [%0], [%1], 16;" :: "r"(dst), "l"(src))
#define CP_COMMIT()     asm volatile("cp.async.commit_group;" ::: "memory")
#define CP_WAIT0()      asm volatile("cp.async.wait_group 0;" ::: "memory")
#define CP_WAIT1()      asm volatile("cp.async.wait_group 1;" ::: "memory")

#define LDM4(r0, r1, r2, r3, a) \
    asm volatile("ldmatrix.sync.aligned.m8n8.x4.shared.b16 {%0,%1,%2,%3}, [%4];" \
                 : "=r"(r0), "=r"(r1), "=r"(r2), "=r"(r3) : "r"(a))
#define LDM2(r0, r1, a) \
    asm volatile("ldmatrix.sync.aligned.m8n8.x2.shared.b16 {%0,%1}, [%2];" \
                 : "=r"(r0), "=r"(r1) : "r"(a))
#define MMA16816(d, a, b) \
    asm volatile("mma.sync.aligned.m16n8k16.row.col.f32.bf16.bf16.f32 " \
                 "{%0,%1,%2,%3},{%4,%5,%6,%7},{%8,%9},{%0,%1,%2,%3};" \
                 : "+f"((d)[0]), "+f"((d)[1]), "+f"((d)[2]), "+f"((d)[3]) \
                 : "r"((a)[0]), "r"((a)[1]), "r"((a)[2]), "r"((a)[3]), \
                   "r"((b)[0]), "r"((b)[1]))

__device__ __forceinline__ void hilo(float v, __nv_bfloat16& h, __nv_bfloat16& l) {
    h = __float2bfloat16(v);
    l = __float2bfloat16(v - __bfloat162float(h));
}
__device__ __forceinline__ unsigned short bfbits(__nv_bfloat16 h) {
    return *reinterpret_cast<unsigned short*>(&h);
}
// powers: p[s] = e1^(s+1), depth-4 ladder
__device__ __forceinline__ void powers16(float e1, float* p) {
    float e2 = e1 * e1, e4 = e2 * e2, e8 = e4 * e4;
    p[0] = e1;        p[1] = e2;        p[2] = e2 * e1;   p[3] = e4;
    p[4] = e4 * e1;   p[5] = e4 * e2;   p[6] = e4 * p[2]; p[7] = e8;
    p[8] = e8 * e1;   p[9] = e8 * e2;   p[10] = e8 * p[2]; p[11] = e8 * e4;
    p[12] = e8 * p[4]; p[13] = e8 * p[5]; p[14] = e8 * p[6]; p[15] = e8 * e8;
}
// layer-0 xz row map: r in [0,8192) -> unique row in [0,4096)
__device__ __forceinline__ int xzrow(int r, int dup) {
    if (!dup) return r;
    int t = r & 511;
    int tt = t < 256 ? t : 511 - t;
    return ((r >> 9) << 8) + tt;
}

// ---------------------------------------------------------------------------
// fp32 -> bf16 hi/lo, vectorized (4 elems/thread)
__global__ void k_cvt(const float* __restrict__ src, __nv_bfloat16* __restrict__ hi,
                      __nv_bfloat16* __restrict__ lo, int n4) {
    int i = blockIdx.x * blockDim.x + threadIdx.x;
    if (i >= n4) return;
    float4 v = ((const float4*)src)[i];
    __nv_bfloat16 h0, l0, h1, l1, h2, l2, h3, l3;
    hilo(v.x, h0, l0); hilo(v.y, h1, l1); hilo(v.z, h2, l2); hilo(v.w, h3, l3);
    ((ushort4*)hi)[i] = make_ushort4(bfbits(h0), bfbits(h1), bfbits(h2), bfbits(h3));
    ((ushort4*)lo)[i] = make_ushort4(bfbits(l0), bfbits(l1), bfbits(l2), bfbits(l3));
}

// layer-0 compact inputs: 4096 unique rows, 4 c per thread
__global__ void k_build4(const float* __restrict__ s0, const float* __restrict__ s1,
                         const float* __restrict__ s2, const float* __restrict__ s3) {
    int idx = blockIdx.x * blockDim.x + threadIdx.x;
    if (idx >= 4096 * CC / 4) return;
    int r = idx >> 7;
    int slot = r >> 10;
    const float* s = slot == 0 ? s0 : slot == 1 ? s1 : slot == 2 ? s2 : s3;
    float4 v = ((const float4*)(s + (size_t)(r & 1023) * CC))[idx & 127];
    __nv_bfloat16 h0, l0, h1, l1, h2, l2, h3, l3;
    hilo(v.x, h0, l0); hilo(v.y, h1, l1); hilo(v.z, h2, l2); hilo(v.w, h3, l3);
    ((ushort4*)g_ah)[idx] = make_ushort4(bfbits(h0), bfbits(h1), bfbits(h2), bfbits(h3));
    ((ushort4*)g_al)[idx] = make_ushort4(bfbits(l0), bfbits(l1), bfbits(l2), bfbits(l3));
}

// ---------------------------------------------------------------------------
// mma.sync GEMM: C = A * W^T (bf16 hi/lo x3). CTA tile 128x256, 512 threads
// (16 warps, warp tile 64x32), BK=32, 3-stage cp.async, wait_group<=1.
// Stage layout: Ah 10240 | Al 10240 | Wh 20480 | Wl 20480 = 61440 B.
// ---------------------------------------------------------------------------
#define M2_STAGE 61440
#define M2_ATILE 10240
#define M2_WTILE 20480

__global__ __launch_bounds__(512, 1) void k_mma(
    const __nv_bfloat16* __restrict__ Ah, const __nv_bfloat16* __restrict__ Al,
    const __nv_bfloat16* __restrict__ WhB, const __nv_bfloat16* __restrict__ WlB,
    float* __restrict__ C, int K, int ldc,
    int rpg, int wstride, int w0, int w1, int w2, int w3) {
    extern __shared__ __align__(128) uint8_t smraw[];
    const uint32_t smb = smem_u32(smraw);
    const int tid = threadIdx.x;
    const int wid = tid >> 5;
    const int lane = tid & 31;
    const int wm = wid & 1;             // 0..1 -> m 0/64
    const int wn = wid >> 1;            // 0..7 -> n 0..224
    const int row0 = blockIdx.y * 128;
    const int col0 = blockIdx.x * 256;
    const int wsel = wsel4(row0 / rpg, w0, w1, w2, w3);
    const __nv_bfloat16* Wh = WhB + (size_t)wsel * wstride;
    const __nv_bfloat16* Wl = WlB + (size_t)wsel * wstride;
    const int nc = K >> 5;

    float acc[4][4][4];
#pragma unroll
    for (int i = 0; i < 4; i++)
#pragma unroll
        for (int j = 0; j < 4; j++)
#pragma unroll
            for (int q = 0; q < 4; q++) acc[i][j][q] = 0.f;

    // 3072 CP16 per stage over 512 threads = 6 each
    auto load_stage = [&](int kc, int st) {
        const int k0 = kc << 5;
        const uint32_t sb = smb + st * M2_STAGE;
#pragma unroll
        for (int p = 0; p < 6; p++) {
            int u = tid + (p << 9);
            if (u < 1024) {                       // A: 2 tiles x 128 rows x 4 segs
                int tile = u >> 9;
                int v = u & 511;
                int r = v >> 2, seg = v & 3;
                const __nv_bfloat16* src = (tile ? Al : Ah) + (size_t)(row0 + r) * K;
                CP16(sb + tile * M2_ATILE + r * 80 + seg * 16, src + k0 + seg * 8);
            } else {                              // W: 2 tiles x 256 rows x 4 segs
                int u2 = u - 1024;
                int tile = u2 >> 10;
                int v = u2 & 1023;
                int r = v >> 2, seg = v & 3;
                const __nv_bfloat16* src = (tile ? Wl : Wh) + (size_t)(col0 + r) * K;
                CP16(sb + 2 * M2_ATILE + tile * M2_WTILE + r * 80 + seg * 16,
                     src + k0 + seg * 8);
            }
        }
        CP_COMMIT();
    };

    load_stage(0, 0);
    if (nc > 1) load_stage(1, 1);

    const uint32_t aRowByte = (uint32_t)(wm * 64 + (lane & 15)) * 80 + ((lane >> 4) << 4);
    const uint32_t bRowByte = (uint32_t)(wn * 32 + (lane & 7)) * 80 + (((lane >> 3) & 1) << 4);

    int st = 0;
    for (int c = 0; c < nc; c++) {
        if (c + 1 < nc) CP_WAIT1(); else CP_WAIT0();   // stage c complete
        __syncthreads();                                // safe to read c, overwrite c-1
        if (c + 2 < nc) {
            int ns = st + 2; if (ns >= 3) ns -= 3;
            load_stage(c + 2, ns);
        }
        const uint32_t sb = smb + st * M2_STAGE;
        st = st + 1 == 3 ? 0 : st + 1;
#pragma unroll
        for (int ks = 0; ks < 2; ks++) {
            uint32_t ah[4][4], al[4][4], bh[4][2], bl[4][2];
            const uint32_t kb = ks * 32;
#pragma unroll
            for (int mi = 0; mi < 4; mi++) {
                uint32_t ra = sb + aRowByte + (uint32_t)mi * 16 * 80 + kb;
                LDM4(ah[mi][0], ah[mi][1], ah[mi][2], ah[mi][3], ra);
                LDM4(al[mi][0], al[mi][1], al[mi][2], al[mi][3], ra + M2_ATILE);
            }
#pragma unroll
            for (int ni = 0; ni < 4; ni++) {
                uint32_t rb = sb + 2 * M2_ATILE + bRowByte + (uint32_t)ni * 8 * 80 + kb;
                LDM2(bh[ni][0], bh[ni][1], rb);
                LDM2(bl[ni][0], bl[ni][1], rb + M2_WTILE);
            }
#pragma unroll
            for (int mi = 0; mi < 4; mi++)
#pragma unroll
                for (int ni = 0; ni < 4; ni++) {
                    MMA16816(acc[mi][ni], ah[mi], bh[ni]);
                    MMA16816(acc[mi][ni], ah[mi], bl[ni]);
                    MMA16816(acc[mi][ni], al[mi], bh[ni]);
                }
        }
    }

    const int gr = lane >> 2;
    const int gc = (lane & 3) * 2;
#pragma unroll
    for (int mi = 0; mi < 4; mi++)
#pragma unroll
        for (int ni = 0; ni < 4; ni++) {
            int row = row0 + wm * 64 + mi * 16 + gr;
            int col = col0 + wn * 32 + ni * 8 + gc;
            float* p0 = C + (size_t)row * ldc + col;
            float* p1 = C + (size_t)(row + 8) * ldc + col;
            *(float2*)p0 = make_float2(acc[mi][ni][0], acc[mi][ni][1]);
            *(float2*)p1 = make_float2(acc[mi][ni][2], acc[mi][ni][3]);
        }
}

// ---------------------------------------------------------------------------
// 64x64 FFMA2 GEMM body (x_proj split-K, dt-proj)
// ---------------------------------------------------------------------------
__device__ __forceinline__ void gemm64_accum(
    const float* A, const float* W, unsigned long long acc[4][2],
    int K, int lda, int ldb, int row0, int col0) {
    __shared__ float As[16][68];
    __shared__ float Bs[16][68];
    const int tid = threadIdx.x;
    const int tx = tid & 15, ty = tid >> 4;
    for (int k0 = 0; k0 < K; k0 += 16) {
        __syncthreads();
#pragma unroll
        for (int i = 0; i < 4; i++) {
            int idx = tid + i * 256;
            int kk = idx & 15, rr = idx >> 4;
            As[kk][rr] = A[(size_t)(row0 + rr) * lda + k0 + kk];
            Bs[kk][rr] = W[(size_t)(col0 + rr) * ldb + k0 + kk];
        }
        __syncthreads();
#pragma unroll
        for (int kk = 0; kk < 16; kk++) {
            float a[4];
            *(float4*)a = *(const float4*)&As[kk][ty * 4];
            unsigned long long b2[2];
            *(float4*)b2 = *(const float4*)&Bs[kk][tx * 4];
#pragma unroll
            for (int i = 0; i < 4; i++) {
                unsigned long long ad;
                DUP2(ad, a[i]);
                FMA2(acc[i][0], ad, b2[0]);
                FMA2(acc[i][1], ad, b2[1]);
            }
        }
    }
}

// x_proj split-K (8 slices of K=128)
__global__ __launch_bounds__(256) void k_gemm64sk(
    const float* __restrict__ A, const float* __restrict__ Wb,
    int rpg, int wstride, int w0, int w1, int w2, int w3) {
    const int row0 = blockIdx.y * 64;
    const int z = blockIdx.z;
    const int wsel = wsel4(row0 / rpg, w0, w1, w2, w3);
    const float* W = Wb + (size_t)wsel * wstride + z * 128;
    unsigned long long acc[4][2];
#pragma unroll
    for (int i = 0; i < 4; i++) { acc[i][0] = 0ull; acc[i][1] = 0ull; }
    gemm64_accum(A + z * 128, W, acc, 128, 1024, 1024, row0, 0);
    float* Cout = g_xdblp + (size_t)z * RTOK * 64;
    const int tx = threadIdx.x & 15, ty = threadIdx.x >> 4;
#pragma unroll
    for (int i = 0; i < 4; i++) {
        float* cp = Cout + (size_t)(row0 + ty * 4 + i) * 64 + tx * 4;
        *(ulonglong2*)cp = make_ulonglong2(acc[i][0], acc[i][1]);
    }
}

// reduce split-K partials; also zero lookback flags for the next scan
__global__ void k_reduce8() {
    int idx = blockIdx.x * blockDim.x + threadIdx.x;
    if (idx < 1024) g_flag[idx] = 0;
    if (idx >= RTOK * 64) return;
    const int S = RTOK * 64;
    float a0 = g_xdblp[idx] + g_xdblp[idx + S];
    float a1 = g_xdblp[idx + 2 * S] + g_xdblp[idx + 3 * S];
    float a2 = g_xdblp[idx + 4 * S] + g_xdblp[idx + 5 * S];
    float a3 = g_xdblp[idx + 6 * S] + g_xdblp[idx + 7 * S];
    g_xdbl[idx] = (a0 + a1) + (a2 + a3);
}

// dt-proj with fused +dtb and softplus -> g_delta
__global__ __launch_bounds__(256) void k_gemm64dt(
    const float* __restrict__ dtw, const float* __restrict__ dtb,
    int rpg, int w0, int w1, int w2, int w3) {
    const int row0 = blockIdx.y * 64;
    const int col0 = blockIdx.x * 64;
    const int m = wsel4(row0 / rpg, w0, w1, w2, w3);
    const float* W = dtw + (size_t)m * DIN * 32;
    unsigned long long acc[4][2];
#pragma unroll
    for (int i = 0; i < 4; i++) { acc[i][0] = 0ull; acc[i][1] = 0ull; }
    gemm64_accum(g_xdbl, W, acc, 32, 64, 32, row0, col0);
    const int tx = threadIdx.x & 15, ty = threadIdx.x >> 4;
#pragma unroll
    for (int i = 0; i < 4; i++) {
        const float* av = (const float*)acc[i];
        float r[4];
#pragma unroll
        for (int j = 0; j < 4; j++) {
            int col = col0 + tx * 4 + j;
            float x = av[j] + dtb[m * DIN + col];
            r[j] = (x > 15.f) ? x : __logf(1.f + __expf(x));
        }
        float* cp = g_delta + (size_t)(row0 + ty * 4 + i) * DIN + col0 + tx * 4;
        *(float4*)cp = make_float4(r[0], r[1], r[2], r[3]);
    }
}

// ---------------------------------------------------------------------------
// causal depthwise conv (4 taps) + bias + SiLU, 4 d per thread (float4).
// ---------------------------------------------------------------------------
__global__ void k_conv(const float* __restrict__ cw, const float* __restrict__ cb,
                       int T, int rpg, int w0, int w1, int w2, int w3, int dup) {
    int idx = blockIdx.x * blockDim.x + threadIdx.x;
    if (idx >= RTOK * DIN / 4) return;
    int d4 = (idx & 255) << 2;
    int r = idx >> 8;
    int t = r & (T - 1);
    int m = wsel4(r / rpg, w0, w1, w2, w3);
    const float4* cwp = (const float4*)(cw + ((size_t)m * DIN + d4) * 4);
    float4 wv0 = cwp[0], wv1 = cwp[1], wv2 = cwp[2], wv3 = cwp[3];
    float4 acc = *(const float4*)(cb + m * DIN + d4);
    const float* w0p = (const float*)&wv0;
    const float* w1p = (const float*)&wv1;
    const float* w2p = (const float*)&wv2;
    const float* w3p = (const float*)&wv3;
#pragma unroll
    for (int k = 0; k < 4; k++) {
        int tt = t - 3 + k;
        if (tt >= 0) {
            int row = xzrow(r + tt - t, dup);
            float4 xv = *(const float4*)(g_xz + (size_t)row * (2 * DIN) + d4);
            acc.x = fmaf(w0p[k], xv.x, acc.x);
            acc.y = fmaf(w1p[k], xv.y, acc.y);
            acc.z = fmaf(w2p[k], xv.z, acc.z);
            acc.w = fmaf(w3p[k], xv.w, acc.w);
        }
    }
    float4 o;
    o.x = __fdividef(acc.x, 1.f + __expf(-acc.x));
    o.y = __fdividef(acc.y, 1.f + __expf(-acc.y));
    o.z = __fdividef(acc.z, 1.f + __expf(-acc.z));
    o.w = __fdividef(acc.w, 1.f + __expf(-acc.w));
    *(float4*)(g_x + (size_t)r * DIN + d4) = o;
}

// ---------------------------------------------------------------------------
// Fused chunked scan with decoupled lookback (passes A+B+C in one kernel).
// ---------------------------------------------------------------------------
template <bool CHAIN>
__device__ __forceinline__ void scanF_body(int rbase, int d, int g, int j,
                                           int blk, int dup,
                                           const float Av[16], float Dv) {
    const int tid = threadIdx.x;
    float h[16];
#pragma unroll
    for (int s = 0; s < 16; s++) h[s] = 0.f;
    float dsum = 0.f;
#pragma unroll 2
    for (int t = 0; t < 64; t++) {
        int r = rbase + t;
        float delta = g_delta[(size_t)r * DIN + d];
        float xv = g_x[(size_t)r * DIN + d];
        const float4* bc = (const float4*)(g_xdbl + (size_t)r * 64 + 32);
        float4 Bq[4], Cq[4];
#pragma unroll
        for (int q = 0; q < 4; q++) { Bq[q] = bc[q]; Cq[q] = bc[q + 4]; }
        const float* Bv = (const float*)Bq;
        const float* Cv = (const float*)Cq;
        dsum += delta;
        float p[16];
        if (CHAIN) powers16(__expf(delta * Av[0]), p);
        else {
#pragma unroll
            for (int s = 0; s < 16; s++) p[s] = __expf(delta * Av[s]);
        }
        float dx = delta * xv;
        float y0 = 0.f, y1 = 0.f, y2 = 0.f, y3 = 0.f;
#pragma unroll
        for (int s = 0; s < 16; s++) {
            h[s] = fmaf(h[s], p[s], dx * Bv[s]);
            float hv = h[s] * Cv[s];
            if ((s & 3) == 0) y0 += hv;
            else if ((s & 3) == 1) y1 += hv;
            else if ((s & 3) == 2) y2 += hv;
            else y3 += hv;
        }
        g_x[(size_t)r * DIN + d] = fmaf(Dv, xv, (y0 + y1) + (y2 + y3));
    }

    float hin[16];
    if (j == 0) {
#pragma unroll
        for (int s = 0; s < 16; s++)
            g_hch[((size_t)(s * 128 + g) << 10) + d] = h[s];
        __threadfence();
        __syncthreads();
        if (tid == 0) atomicExch(&g_flag[blk], 1);
#pragma unroll 2
        for (int t = 0; t < 64; t++) {
            int r = rbase + t;
            float zv = g_xz[(size_t)xzrow(r, dup) * 2048 + 1024 + d];
            float ylin = g_x[(size_t)r * DIN + d];
            float sg = __fdividef(zv, 1.f + __expf(-zv));
            float yv = ylin * sg;
            hilo(yv, g_ah[(size_t)r * DIN + d], g_al[(size_t)r * DIN + d]);
        }
        return;
    }

    float P[16];
    if (CHAIN) powers16(__expf(dsum * Av[0]), P);
    else {
#pragma unroll
        for (int s = 0; s < 16; s++) P[s] = __expf(dsum * Av[s]);
    }
    if (tid == 0) {
        while (atomicAdd(&g_flag[blk - 8], 0) == 0) __nanosleep(32);
    }
    __syncthreads();
    __threadfence();
#pragma unroll
    for (int s = 0; s < 16; s++)
        hin[s] = g_hch[((size_t)(s * 128 + (g - 1)) << 10) + d];
#pragma unroll
    for (int s = 0; s < 16; s++)
        g_hch[((size_t)(s * 128 + g) << 10) + d] = fmaf(P[s], hin[s], h[s]);
    __threadfence();
    __syncthreads();
    if (tid == 0) atomicExch(&g_flag[blk], 1);

    float q[16];
#pragma unroll
    for (int s = 0; s < 16; s++) q[s] = hin[s];
#pragma unroll 2
    for (int t = 0; t < 64; t++) {
        int r = rbase + t;
        float delta = g_delta[(size_t)r * DIN + d];
        float zv = g_xz[(size_t)xzrow(r, dup) * 2048 + 1024 + d];
        float ylin = g_x[(size_t)r * DIN + d];
        const float4* cp = (const float4*)(g_xdbl + (size_t)r * 64 + 48);
        float4 Cq[4];
#pragma unroll
        for (int u = 0; u < 4; u++) Cq[u] = cp[u];
        const float* Cv = (const float*)Cq;
        float p[16];
        if (CHAIN) powers16(__expf(delta * Av[0]), p);
        else {
#pragma unroll
            for (int s = 0; s < 16; s++) p[s] = __expf(delta * Av[s]);
        }
        float c0 = 0.f, c1 = 0.f, c2 = 0.f, c3 = 0.f;
#pragma unroll
        for (int s = 0; s < 16; s++) {
            q[s] *= p[s];
            float hv = q[s] * Cv[s];
            if ((s & 3) == 0) c0 += hv;
            else if ((s & 3) == 1) c1 += hv;
            else if ((s & 3) == 2) c2 += hv;
            else c3 += hv;
        }
        float y = ylin + (c0 + c1) + (c2 + c3);
        float sg = __fdividef(zv, 1.f + __expf(-zv));
        float yv = y * sg;
        hilo(yv, g_ah[(size_t)r * DIN + d], g_al[(size_t)r * DIN + d]);
    }
}

__global__ __launch_bounds__(128) void k_scanF(const float* __restrict__ Alog,
                                               const float* __restrict__ Dp,
                                               int lgNCH, int w0, int w1, int w2, int w3,
                                               int dup) {
    int blk = blockIdx.x;
    int dg = blk & 7;
    int g = blk >> 3;
    int seq = g >> lgNCH;
    int j = g & ((1 << lgNCH) - 1);
    int d = (dg << 7) | threadIdx.x;
    int m = wsel4(seq >> 2, w0, w1, w2, w3);
    float Av[16];
    const float* ap = Alog + ((size_t)m * DIN + d) * 16;
#pragma unroll
    for (int s = 0; s < 16; s++) Av[s] = -__expf(ap[s]);
    bool chain = true;
#pragma unroll
    for (int s = 1; s < 16; s++)
        chain = chain &&
                (fabsf(Av[s] - (float)(s + 1) * Av[0]) <=
                 1e-3f * (float)(s + 1) * fabsf(Av[0]) + 1e-7f);
    float Dv = Dp[m * DIN + d];
    int rbase = g << 6;
    if (chain) scanF_body<true>(rbase, d, g, j, blk, dup, Av, Dv);
    else       scanF_body<false>(rbase, d, g, j, blk, dup, Av, Dv);
}

// ---------------------------------------------------------------------------
__global__ __launch_bounds__(128) void k_combine(
    const float* __restrict__ s0, const float* __restrict__ s1,
    const float* __restrict__ s2, const float* __restrict__ s3,
    const float* __restrict__ lnw, const float* __restrict__ lnb) {
    int blk = blockIdx.x;
    int t = blk & 255;
    int b = (blk >> 8) & 3;
    int slot = blk >> 10;
    const float* src = slot == 0 ? s0 : slot == 1 ? s1 : slot == 2 ? s2 : s3;
    int rowA = ((slot * 4 + b) * 512 + t) * CC;
    int rowB = ((slot * 4 + b) * 512 + (511 - t)) * CC;
    int tid = threadIdx.x;
    float v[4];
#pragma unroll
    for (int j = 0; j < 4; j++) {
        int c = tid + j * 128;
        v[j] = 0.5f * (g_o[rowA + c] + g_o[rowB + c]);
    }
    __shared__ float red[8];
    int wid = tid >> 5, lane = tid & 31;
    float s = (v[0] + v[1]) + (v[2] + v[3]);
#pragma unroll
    for (int o = 16; o; o >>= 1) s += __shfl_xor_sync(~0u, s, o);
    if (lane == 0) red[wid] = s;
    __syncthreads();
    float mean = (red[0] + red[1] + red[2] + red[3]) * (1.f / 512.f);
    float q = 0.f;
#pragma unroll
    for (int j = 0; j < 4; j++) { float dd = v[j] - mean; q = fmaf(dd, dd, q); }
#pragma unroll
    for (int o = 16; o; o >>= 1) q += __shfl_xor_sync(~0u, q, o);
    if (lane == 0) red[4 + wid] = q;
    __syncthreads();
    float var = (red[4] + red[5] + red[6] + red[7]) * (1.f / 512.f);
    float rstd = rsqrtf(var + 1e-5f);
    int tau = slot * 256 + t;
#pragma unroll
    for (int j = 0; j < 4; j++) {
        int c = tid + j * 128;
        float o = (v[j] - mean) * rstd * lnw[c] + lnb[c] + src[(b * 256 + t) * CC + c];
        __nv_bfloat16 hh, ll;
        hilo(o, hh, ll);
        int idxF = ((b * 1024) + tau) * CC + c;
        int idxR = (((4 + b) * 1024) + (1023 - tau)) * CC + c;
        g_ah[idxF] = hh; g_al[idxF] = ll;
        g_ah[idxR] = hh; g_al[idxR] = ll;
    }
}

// final: fused = 0.5*(o4 + reverse(o5)); float4 per thread
__global__ void k_final(float* __restrict__ out) {
    int idx = blockIdx.x * blockDim.x + threadIdx.x;
    if (idx >= BB * 1024 * CC / 4) return;
    int c4 = (idx & 127) << 2;
    int rest = idx >> 7;
    int tau = rest & 1023;
    int b = rest >> 10;
    float4 a = *(const float4*)(g_o + ((size_t)(b * 1024) + tau) * CC + c4);
    float4 bb = *(const float4*)(g_o + ((size_t)((4 + b) * 1024) + (1023 - tau)) * CC + c4);
    float4 f = make_float4(0.5f * (a.x + bb.x), 0.5f * (a.y + bb.y),
                           0.5f * (a.z + bb.z), 0.5f * (a.w + bb.w));
    int i = tau >> 8;
    int t = tau & 255;
    *(float4*)(out + (((size_t)(i * 4 + b) * 256 + t) << 9) + c4) = f;
}

// ---------------------------------------------------------------------------
extern "C" void kernel_launch(void* const* d_in, const int* in_sizes, int n_in,
                              void* d_out, int out_size) {
    const float* x0hw = (const float*)d_in[0];
    const float* x1hw = (const float*)d_in[1];
    const float* x0wh = (const float*)d_in[2];
    const float* x1wh = (const float*)d_in[3];
    const float* in_w = (const float*)d_in[4];
    const float* cw   = (const float*)d_in[5];
    const float* cb   = (const float*)d_in[6];
    const float* xw   = (const float*)d_in[7];
    const float* dtw  = (const float*)d_in[8];
    const float* dtb  = (const float*)d_in[9];
    const float* alog = (const float*)d_in[10];
    const float* Dp   = (const float*)d_in[11];
    const float* ow   = (const float*)d_in[12];
    const float* lnw  = (const float*)d_in[13];
    const float* lnb  = (const float*)d_in[14];
    float* out = (float*)d_out;

    float *pxz, *px, *po;
    cudaGetSymbolAddress((void**)&pxz, g_xz);
    cudaGetSymbolAddress((void**)&px, g_x);
    cudaGetSymbolAddress((void**)&po, g_o);
    __nv_bfloat16 *pah, *pal, *pwih, *pwil, *pwoh, *pwol;
    cudaGetSymbolAddress((void**)&pah, g_ah);
    cudaGetSymbolAddress((void**)&pal, g_al);
    cudaGetSymbolAddress((void**)&pwih, g_wih);
    cudaGetSymbolAddress((void**)&pwil, g_wil);
    cudaGetSymbolAddress((void**)&pwoh, g_woh);
    cudaGetSymbolAddress((void**)&pwol, g_wol);

    static int inited = 0;
    static cudaStream_t s2;
    static cudaEvent_t evX0, evZ0, evX1, evZ1;
    if (!inited) {
        cudaFuncSetAttribute(k_mma, cudaFuncAttributeMaxDynamicSharedMemorySize,
                             3 * M2_STAGE);
        cudaStreamCreateWithFlags(&s2, cudaStreamNonBlocking);
        cudaEventCreateWithFlags(&evX0, cudaEventDisableTiming);
        cudaEventCreateWithFlags(&evZ0, cudaEventDisableTiming);
        cudaEventCreateWithFlags(&evX1, cudaEventDisableTiming);
        cudaEventCreateWithFlags(&evZ1, cudaEventDisableTiming);
        inited = 1;
    }
    const int MMSMEM = 3 * M2_STAGE;

    const int EL = RTOK * DIN;
    const int ELF = BB * 1024 * CC;
    const size_t ZW = (size_t)1024 * 512;

    // weights -> bf16 hi/lo (vectorized)
    k_cvt<<<(6 * 2048 * 512 / 4 + 255) / 256, 256>>>(in_w, pwih, pwil, 6 * 2048 * 512 / 4);
    k_cvt<<<(6 * 512 * 1024 / 4 + 255) / 256, 256>>>(ow, pwoh, pwol, 6 * 512 * 1024 / 4);

    // ---------------- layer 0 (T=512, NCH=8; compact in_proj) ---------------
    {
        const int w0 = 0, w1 = 2, w2 = 1, w3 = 3, rpg = 2048, T = 512, lg = 3;
        k_build4<<<(4096 * CC / 4 + 255) / 256, 256>>>(x0hw, x1hw, x0wh, x1wh);
        k_mma<<<dim3(4, 32), 512, MMSMEM>>>(
            pah, pal, pwih, pwil, pxz, 512, 2048, 1024, 2048 * 512, w0, w1, w2, w3);
        cudaEventRecord(evX0, 0);
        cudaStreamWaitEvent(s2, evX0, 0);
        k_mma<<<dim3(4, 32), 512, MMSMEM, s2>>>(
            pah, pal, pwih + ZW, pwil + ZW, pxz + 1024, 512, 2048,
            1024, 2048 * 512, w0, w1, w2, w3);
        cudaEventRecord(evZ0, s2);
        k_conv<<<(EL / 4 + 255) / 256, 256>>>(cw, cb, T, rpg, w0, w1, w2, w3, 1);
        k_gemm64sk<<<dim3(1, RTOK / 64, 8), 256>>>(px, xw, rpg, 64 * 1024, w0, w1, w2, w3);
        k_reduce8<<<(RTOK * 64 + 255) / 256, 256>>>();
        k_gemm64dt<<<dim3(1024 / 64, RTOK / 64), 256>>>(dtw, dtb, rpg, w0, w1, w2, w3);
        cudaStreamWaitEvent(0, evZ0, 0);   // scanF gates with z
        k_scanF<<<1024, 128>>>(alog, Dp, lg, w0, w1, w2, w3, 1);
        k_mma<<<dim3(2, 64), 512, MMSMEM>>>(
            pah, pal, pwoh, pwol, po, 1024, 512, rpg, 512 * 1024, w0, w1, w2, w3);
        k_combine<<<4096, 128>>>(x0hw, x1hw, x0wh, x1wh, lnw, lnb);
    }

    // ---------------- layer 1 (T=1024, NCH=16) ----------------
    {
        const int w0 = 4, w1 = 5, w2 = 4, w3 = 5, rpg = 4096, T = 1024, lg = 4;
        k_mma<<<dim3(4, 64), 512, MMSMEM>>>(
            pah, pal, pwih, pwil, pxz, 512, 2048, rpg, 2048 * 512, w0, w1, w2, w3);
        cudaEventRecord(evX1, 0);
        cudaStreamWaitEvent(s2, evX1, 0);
        k_mma<<<dim3(4, 64), 512, MMSMEM, s2>>>(
            pah, pal, pwih + ZW, pwil + ZW, pxz + 1024, 512, 2048,
            rpg, 2048 * 512, w0, w1, w2, w3);
        cudaEventRecord(evZ1, s2);
        k_conv<<<(EL / 4 + 255) / 256, 256>>>(cw, cb, T, rpg, w0, w1, w2, w3, 0);
        k_gemm64sk<<<dim3(1, RTOK / 64, 8), 256>>>(px, xw, rpg, 64 * 1024, w0, w1, w2, w3);
        k_reduce8<<<(RTOK * 64 + 255) / 256, 256>>>();
        k_gemm64dt<<<dim3(1024 / 64, RTOK / 64), 256>>>(dtw, dtb, rpg, w0, w1, w2, w3);
        cudaStreamWaitEvent(0, evZ1, 0);
        k_scanF<<<1024, 128>>>(alog, Dp, lg, w0, w1, w2, w3, 0);
        k_mma<<<dim3(2, 64), 512, MMSMEM>>>(
            pah, pal, pwoh, pwol, po, 1024, 512, rpg, 512 * 1024, w0, w1, w2, w3);
        k_final<<<(ELF / 4 + 255) / 256, 256>>>(out);
    }
}

// round 17
// speedup vs baseline: 1.5374x; 1.1564x over previous
#include <cuda_runtime.h>
#include <cuda_fp16.h>
#include <cstdint>

// ---------------------------------------------------------------------------
// MultiScaleMambaEncoder — mma.sync fp16 GEMMs (A single fp16, W hi/lo x2,
// fp32 accum) + single-pass decoupled-lookback chunked scan.
// Layer-0 in_proj on 4096 unique rows; z-half of in_proj on a side stream.
// ---------------------------------------------------------------------------

#define BB 4
#define CC 512
#define DIN 1024
#define RTOK 8192

// fp32 scratch
__device__ float g_xz[RTOK * 2 * DIN];
__device__ float g_x[RTOK * DIN];          // conv output, then ylin
__device__ float g_xdbl[RTOK * 64];
__device__ float g_xdblp[8 * RTOK * 64];   // split-K partials
__device__ float g_hch[16 * 128 * 1024];   // published h_out per chunk
__device__ float g_delta[RTOK * DIN];
__device__ float g_o[RTOK * CC];
__device__ int   g_flag[1024];             // lookback flags
// fp16 GEMM operands
__device__ __half g_ah[RTOK * DIN];        // A (single fp16)
__device__ __half g_wih[6 * 2048 * 512];
__device__ __half g_wil[6 * 2048 * 512];
__device__ __half g_woh[6 * 512 * 1024];
__device__ __half g_wol[6 * 512 * 1024];

__device__ __forceinline__ int wsel4(int ml, int w0, int w1, int w2, int w3) {
    return ml == 0 ? w0 : ml == 1 ? w1 : ml == 2 ? w2 : w3;
}

#define FMA2(d, a, b) asm("fma.rn.f32x2 %0, %1, %2, %0;" : "+l"(d) : "l"(a), "l"(b))
#define DUP2(d, s)    asm("mov.b64 %0, {%1, %1};" : "=l"(d) : "f"(s))

__device__ __forceinline__ uint32_t smem_u32(const void* p) {
    uint32_t a;
    asm("{ .reg .u64 t; cvta.to.shared.u64 t, %1; cvt.u32.u64 %0, t; }" : "=r"(a) : "l"(p));
    return a;
}
#define CP16(dst, src)  asm volatile("cp.async.cg.shared.global [%0], [%1], 16;" :: "r"(dst), "l"(src))
#define CP_COMMIT()     asm volatile("cp.async.commit_group;" ::: "memory")
#define CP_WAIT0()      asm volatile("cp.async.wait_group 0;" ::: "memory")
#define CP_WAIT1()      asm volatile("cp.async.wait_group 1;" ::: "memory")

#define LDM4(r0, r1, r2, r3, a) \
    asm volatile("ldmatrix.sync.aligned.m8n8.x4.shared.b16 {%0,%1,%2,%3}, [%4];" \
                 : "=r"(r0), "=r"(r1), "=r"(r2), "=r"(r3) : "r"(a))
#define LDM2(r0, r1, a) \
    asm volatile("ldmatrix.sync.aligned.m8n8.x2.shared.b16 {%0,%1}, [%2];" \
                 : "=r"(r0), "=r"(r1) : "r"(a))
#define MMAF16(d, a, b) \
    asm volatile("mma.sync.aligned.m16n8k16.row.col.f32.f16.f16.f32 " \
                 "{%0,%1,%2,%3},{%4,%5,%6,%7},{%8,%9},{%0,%1,%2,%3};" \
                 : "+f"((d)[0]), "+f"((d)[1]), "+f"((d)[2]), "+f"((d)[3]) \
                 : "r"((a)[0]), "r"((a)[1]), "r"((a)[2]), "r"((a)[3]), \
                   "r"((b)[0]), "r"((b)[1]))

__device__ __forceinline__ void hiloH(float v, __half& h, __half& l) {
    h = __float2half_rn(v);
    l = __float2half_rn(v - __half2float(h));
}
__device__ __forceinline__ unsigned short hbits(__half h) {
    return *reinterpret_cast<unsigned short*>(&h);
}
// powers: p[s] = e1^(s+1), depth-4 ladder
__device__ __forceinline__ void powers16(float e1, float* p) {
    float e2 = e1 * e1, e4 = e2 * e2, e8 = e4 * e4;
    p[0] = e1;        p[1] = e2;        p[2] = e2 * e1;   p[3] = e4;
    p[4] = e4 * e1;   p[5] = e4 * e2;   p[6] = e4 * p[2]; p[7] = e8;
    p[8] = e8 * e1;   p[9] = e8 * e2;   p[10] = e8 * p[2]; p[11] = e8 * e4;
    p[12] = e8 * p[4]; p[13] = e8 * p[5]; p[14] = e8 * p[6]; p[15] = e8 * e8;
}
// layer-0 xz row map: r in [0,8192) -> unique row in [0,4096)
__device__ __forceinline__ int xzrow(int r, int dup) {
    if (!dup) return r;
    int t = r & 511;
    int tt = t < 256 ? t : 511 - t;
    return ((r >> 9) << 8) + tt;
}

// ---------------------------------------------------------------------------
// weights: fp32 -> fp16 hi/lo, vectorized (4 elems/thread)
__global__ void k_cvt(const float* __restrict__ src, __half* __restrict__ hi,
                      __half* __restrict__ lo, int n4) {
    int i = blockIdx.x * blockDim.x + threadIdx.x;
    if (i >= n4) return;
    float4 v = ((const float4*)src)[i];
    __half h0, l0, h1, l1, h2, l2, h3, l3;
    hiloH(v.x, h0, l0); hiloH(v.y, h1, l1); hiloH(v.z, h2, l2); hiloH(v.w, h3, l3);
    ((ushort4*)hi)[i] = make_ushort4(hbits(h0), hbits(h1), hbits(h2), hbits(h3));
    ((ushort4*)lo)[i] = make_ushort4(hbits(l0), hbits(l1), hbits(l2), hbits(l3));
}

// layer-0 compact inputs: 4096 unique rows, 4 c per thread (A single fp16)
__global__ void k_build4(const float* __restrict__ s0, const float* __restrict__ s1,
                         const float* __restrict__ s2, const float* __restrict__ s3) {
    int idx = blockIdx.x * blockDim.x + threadIdx.x;
    if (idx >= 4096 * CC / 4) return;
    int r = idx >> 7;
    int slot = r >> 10;
    const float* s = slot == 0 ? s0 : slot == 1 ? s1 : slot == 2 ? s2 : s3;
    float4 v = ((const float4*)(s + (size_t)(r & 1023) * CC))[idx & 127];
    ((ushort4*)g_ah)[idx] = make_ushort4(
        hbits(__float2half_rn(v.x)), hbits(__float2half_rn(v.y)),
        hbits(__float2half_rn(v.z)), hbits(__float2half_rn(v.w)));
}

// ---------------------------------------------------------------------------
// mma.sync GEMM: C = A * W^T (A fp16, W fp16 hi/lo x2). CTA tile 128x256,
// 512 threads (16 warps, warp tile 64x32), BK=32, 3-stage cp.async.
// Stage layout: A 10240 | Wh 20480 | Wl 20480 = 51200 B.
// ---------------------------------------------------------------------------
#define M2_STAGE 51200
#define M2_ATILE 10240
#define M2_WTILE 20480

__global__ __launch_bounds__(512, 1) void k_mma(
    const __half* __restrict__ A,
    const __half* __restrict__ WhB, const __half* __restrict__ WlB,
    float* __restrict__ C, int K, int ldc,
    int rpg, int wstride, int w0, int w1, int w2, int w3) {
    extern __shared__ __align__(128) uint8_t smraw[];
    const uint32_t smb = smem_u32(smraw);
    const int tid = threadIdx.x;
    const int wid = tid >> 5;
    const int lane = tid & 31;
    const int wm = wid & 1;
    const int wn = wid >> 1;
    const int row0 = blockIdx.y * 128;
    const int col0 = blockIdx.x * 256;
    const int wsel = wsel4(row0 / rpg, w0, w1, w2, w3);
    const __half* Wh = WhB + (size_t)wsel * wstride;
    const __half* Wl = WlB + (size_t)wsel * wstride;
    const int nc = K >> 5;

    float acc[4][4][4];
#pragma unroll
    for (int i = 0; i < 4; i++)
#pragma unroll
        for (int j = 0; j < 4; j++)
#pragma unroll
            for (int q = 0; q < 4; q++) acc[i][j][q] = 0.f;

    // 2560 CP16 per stage over 512 threads = 5 each
    auto load_stage = [&](int kc, int st) {
        const int k0 = kc << 5;
        const uint32_t sb = smb + st * M2_STAGE;
#pragma unroll
        for (int p = 0; p < 5; p++) {
            int u = tid + (p << 9);
            if (u < 512) {                        // A: 128 rows x 4 segs
                int r = u >> 2, seg = u & 3;
                CP16(sb + r * 80 + seg * 16, A + (size_t)(row0 + r) * K + k0 + seg * 8);
            } else {                              // W: 2 tiles x 256 rows x 4 segs
                int u2 = u - 512;
                int tile = u2 >> 10;
                int v = u2 & 1023;
                int r = v >> 2, seg = v & 3;
                const __half* src = (tile ? Wl : Wh) + (size_t)(col0 + r) * K;
                CP16(sb + M2_ATILE + tile * M2_WTILE + r * 80 + seg * 16,
                     src + k0 + seg * 8);
            }
        }
        CP_COMMIT();
    };

    load_stage(0, 0);
    if (nc > 1) load_stage(1, 1);

    const uint32_t aRowByte = (uint32_t)(wm * 64 + (lane & 15)) * 80 + ((lane >> 4) << 4);
    const uint32_t bRowByte = (uint32_t)(wn * 32 + (lane & 7)) * 80 + (((lane >> 3) & 1) << 4);

    int st = 0;
    for (int c = 0; c < nc; c++) {
        if (c + 1 < nc) CP_WAIT1(); else CP_WAIT0();
        __syncthreads();
        if (c + 2 < nc) {
            int ns = st + 2; if (ns >= 3) ns -= 3;
            load_stage(c + 2, ns);
        }
        const uint32_t sb = smb + st * M2_STAGE;
        st = st + 1 == 3 ? 0 : st + 1;
#pragma unroll
        for (int ks = 0; ks < 2; ks++) {
            uint32_t ah[4][4], bh[4][2], bl[4][2];
            const uint32_t kb = ks * 32;
#pragma unroll
            for (int mi = 0; mi < 4; mi++) {
                uint32_t ra = sb + aRowByte + (uint32_t)mi * 16 * 80 + kb;
                LDM4(ah[mi][0], ah[mi][1], ah[mi][2], ah[mi][3], ra);
            }
#pragma unroll
            for (int ni = 0; ni < 4; ni++) {
                uint32_t rb = sb + M2_ATILE + bRowByte + (uint32_t)ni * 8 * 80 + kb;
                LDM2(bh[ni][0], bh[ni][1], rb);
                LDM2(bl[ni][0], bl[ni][1], rb + M2_WTILE);
            }
#pragma unroll
            for (int mi = 0; mi < 4; mi++)
#pragma unroll
                for (int ni = 0; ni < 4; ni++) {
                    MMAF16(acc[mi][ni], ah[mi], bh[ni]);
                    MMAF16(acc[mi][ni], ah[mi], bl[ni]);
                }
        }
    }

    const int gr = lane >> 2;
    const int gc = (lane & 3) * 2;
#pragma unroll
    for (int mi = 0; mi < 4; mi++)
#pragma unroll
        for (int ni = 0; ni < 4; ni++) {
            int row = row0 + wm * 64 + mi * 16 + gr;
            int col = col0 + wn * 32 + ni * 8 + gc;
            float* p0 = C + (size_t)row * ldc + col;
            float* p1 = C + (size_t)(row + 8) * ldc + col;
            *(float2*)p0 = make_float2(acc[mi][ni][0], acc[mi][ni][1]);
            *(float2*)p1 = make_float2(acc[mi][ni][2], acc[mi][ni][3]);
        }
}

// ---------------------------------------------------------------------------
// 64x64 FFMA2 GEMM body (x_proj split-K, dt-proj)
// ---------------------------------------------------------------------------
__device__ __forceinline__ void gemm64_accum(
    const float* A, const float* W, unsigned long long acc[4][2],
    int K, int lda, int ldb, int row0, int col0) {
    __shared__ float As[16][68];
    __shared__ float Bs[16][68];
    const int tid = threadIdx.x;
    const int tx = tid & 15, ty = tid >> 4;
    for (int k0 = 0; k0 < K; k0 += 16) {
        __syncthreads();
#pragma unroll
        for (int i = 0; i < 4; i++) {
            int idx = tid + i * 256;
            int kk = idx & 15, rr = idx >> 4;
            As[kk][rr] = A[(size_t)(row0 + rr) * lda + k0 + kk];
            Bs[kk][rr] = W[(size_t)(col0 + rr) * ldb + k0 + kk];
        }
        __syncthreads();
#pragma unroll
        for (int kk = 0; kk < 16; kk++) {
            float a[4];
            *(float4*)a = *(const float4*)&As[kk][ty * 4];
            unsigned long long b2[2];
            *(float4*)b2 = *(const float4*)&Bs[kk][tx * 4];
#pragma unroll
            for (int i = 0; i < 4; i++) {
                unsigned long long ad;
                DUP2(ad, a[i]);
                FMA2(acc[i][0], ad, b2[0]);
                FMA2(acc[i][1], ad, b2[1]);
            }
        }
    }
}

// x_proj split-K (8 slices of K=128)
__global__ __launch_bounds__(256) void k_gemm64sk(
    const float* __restrict__ A, const float* __restrict__ Wb,
    int rpg, int wstride, int w0, int w1, int w2, int w3) {
    const int row0 = blockIdx.y * 64;
    const int z = blockIdx.z;
    const int wsel = wsel4(row0 / rpg, w0, w1, w2, w3);
    const float* W = Wb + (size_t)wsel * wstride + z * 128;
    unsigned long long acc[4][2];
#pragma unroll
    for (int i = 0; i < 4; i++) { acc[i][0] = 0ull; acc[i][1] = 0ull; }
    gemm64_accum(A + z * 128, W, acc, 128, 1024, 1024, row0, 0);
    float* Cout = g_xdblp + (size_t)z * RTOK * 64;
    const int tx = threadIdx.x & 15, ty = threadIdx.x >> 4;
#pragma unroll
    for (int i = 0; i < 4; i++) {
        float* cp = Cout + (size_t)(row0 + ty * 4 + i) * 64 + tx * 4;
        *(ulonglong2*)cp = make_ulonglong2(acc[i][0], acc[i][1]);
    }
}

// reduce split-K partials; also zero lookback flags for the next scan
__global__ void k_reduce8() {
    int idx = blockIdx.x * blockDim.x + threadIdx.x;
    if (idx < 1024) g_flag[idx] = 0;
    if (idx >= RTOK * 64) return;
    const int S = RTOK * 64;
    float a0 = g_xdblp[idx] + g_xdblp[idx + S];
    float a1 = g_xdblp[idx + 2 * S] + g_xdblp[idx + 3 * S];
    float a2 = g_xdblp[idx + 4 * S] + g_xdblp[idx + 5 * S];
    float a3 = g_xdblp[idx + 6 * S] + g_xdblp[idx + 7 * S];
    g_xdbl[idx] = (a0 + a1) + (a2 + a3);
}

// dt-proj with fused +dtb and softplus -> g_delta
__global__ __launch_bounds__(256) void k_gemm64dt(
    const float* __restrict__ dtw, const float* __restrict__ dtb,
    int rpg, int w0, int w1, int w2, int w3) {
    const int row0 = blockIdx.y * 64;
    const int col0 = blockIdx.x * 64;
    const int m = wsel4(row0 / rpg, w0, w1, w2, w3);
    const float* W = dtw + (size_t)m * DIN * 32;
    unsigned long long acc[4][2];
#pragma unroll
    for (int i = 0; i < 4; i++) { acc[i][0] = 0ull; acc[i][1] = 0ull; }
    gemm64_accum(g_xdbl, W, acc, 32, 64, 32, row0, col0);
    const int tx = threadIdx.x & 15, ty = threadIdx.x >> 4;
#pragma unroll
    for (int i = 0; i < 4; i++) {
        const float* av = (const float*)acc[i];
        float r[4];
#pragma unroll
        for (int j = 0; j < 4; j++) {
            int col = col0 + tx * 4 + j;
            float x = av[j] + dtb[m * DIN + col];
            r[j] = (x > 15.f) ? x : __logf(1.f + __expf(x));
        }
        float* cp = g_delta + (size_t)(row0 + ty * 4 + i) * DIN + col0 + tx * 4;
        *(float4*)cp = make_float4(r[0], r[1], r[2], r[3]);
    }
}

// ---------------------------------------------------------------------------
// causal depthwise conv (4 taps) + bias + SiLU, 4 d per thread (float4).
// Also emits x as fp16 (A operand for x_proj is fp32; fp16 copy feeds nothing
// here — only g_x is consumed downstream, so skip).
// ---------------------------------------------------------------------------
__global__ void k_conv(const float* __restrict__ cw, const float* __restrict__ cb,
                       int T, int rpg, int w0, int w1, int w2, int w3, int dup) {
    int idx = blockIdx.x * blockDim.x + threadIdx.x;
    if (idx >= RTOK * DIN / 4) return;
    int d4 = (idx & 255) << 2;
    int r = idx >> 8;
    int t = r & (T - 1);
    int m = wsel4(r / rpg, w0, w1, w2, w3);
    const float4* cwp = (const float4*)(cw + ((size_t)m * DIN + d4) * 4);
    float4 wv0 = cwp[0], wv1 = cwp[1], wv2 = cwp[2], wv3 = cwp[3];
    float4 acc = *(const float4*)(cb + m * DIN + d4);
    const float* w0p = (const float*)&wv0;
    const float* w1p = (const float*)&wv1;
    const float* w2p = (const float*)&wv2;
    const float* w3p = (const float*)&wv3;
#pragma unroll
    for (int k = 0; k < 4; k++) {
        int tt = t - 3 + k;
        if (tt >= 0) {
            int row = xzrow(r + tt - t, dup);
            float4 xv = *(const float4*)(g_xz + (size_t)row * (2 * DIN) + d4);
            acc.x = fmaf(w0p[k], xv.x, acc.x);
            acc.y = fmaf(w1p[k], xv.y, acc.y);
            acc.z = fmaf(w2p[k], xv.z, acc.z);
            acc.w = fmaf(w3p[k], xv.w, acc.w);
        }
    }
    float4 o;
    o.x = __fdividef(acc.x, 1.f + __expf(-acc.x));
    o.y = __fdividef(acc.y, 1.f + __expf(-acc.y));
    o.z = __fdividef(acc.z, 1.f + __expf(-acc.z));
    o.w = __fdividef(acc.w, 1.f + __expf(-acc.w));
    *(float4*)(g_x + (size_t)r * DIN + d4) = o;
}

// ---------------------------------------------------------------------------
// Fused chunked scan with decoupled lookback (passes A+B+C in one kernel).
// Output y written as single fp16 into g_ah.
// ---------------------------------------------------------------------------
template <bool CHAIN>
__device__ __forceinline__ void scanF_body(int rbase, int d, int g, int j,
                                           int blk, int dup,
                                           const float Av[16], float Dv) {
    const int tid = threadIdx.x;
    float h[16];
#pragma unroll
    for (int s = 0; s < 16; s++) h[s] = 0.f;
    float dsum = 0.f;
#pragma unroll 2
    for (int t = 0; t < 64; t++) {
        int r = rbase + t;
        float delta = g_delta[(size_t)r * DIN + d];
        float xv = g_x[(size_t)r * DIN + d];
        const float4* bc = (const float4*)(g_xdbl + (size_t)r * 64 + 32);
        float4 Bq[4], Cq[4];
#pragma unroll
        for (int q = 0; q < 4; q++) { Bq[q] = bc[q]; Cq[q] = bc[q + 4]; }
        const float* Bv = (const float*)Bq;
        const float* Cv = (const float*)Cq;
        dsum += delta;
        float p[16];
        if (CHAIN) powers16(__expf(delta * Av[0]), p);
        else {
#pragma unroll
            for (int s = 0; s < 16; s++) p[s] = __expf(delta * Av[s]);
        }
        float dx = delta * xv;
        float y0 = 0.f, y1 = 0.f, y2 = 0.f, y3 = 0.f;
#pragma unroll
        for (int s = 0; s < 16; s++) {
            h[s] = fmaf(h[s], p[s], dx * Bv[s]);
            float hv = h[s] * Cv[s];
            if ((s & 3) == 0) y0 += hv;
            else if ((s & 3) == 1) y1 += hv;
            else if ((s & 3) == 2) y2 += hv;
            else y3 += hv;
        }
        g_x[(size_t)r * DIN + d] = fmaf(Dv, xv, (y0 + y1) + (y2 + y3));
    }

    float hin[16];
    if (j == 0) {
#pragma unroll
        for (int s = 0; s < 16; s++)
            g_hch[((size_t)(s * 128 + g) << 10) + d] = h[s];
        __threadfence();
        __syncthreads();
        if (tid == 0) atomicExch(&g_flag[blk], 1);
#pragma unroll 2
        for (int t = 0; t < 64; t++) {
            int r = rbase + t;
            float zv = g_xz[(size_t)xzrow(r, dup) * 2048 + 1024 + d];
            float ylin = g_x[(size_t)r * DIN + d];
            float sg = __fdividef(zv, 1.f + __expf(-zv));
            g_ah[(size_t)r * DIN + d] = __float2half_rn(ylin * sg);
        }
        return;
    }

    float P[16];
    if (CHAIN) powers16(__expf(dsum * Av[0]), P);
    else {
#pragma unroll
        for (int s = 0; s < 16; s++) P[s] = __expf(dsum * Av[s]);
    }
    if (tid == 0) {
        while (atomicAdd(&g_flag[blk - 8], 0) == 0) __nanosleep(32);
    }
    __syncthreads();
    __threadfence();
#pragma unroll
    for (int s = 0; s < 16; s++)
        hin[s] = g_hch[((size_t)(s * 128 + (g - 1)) << 10) + d];
#pragma unroll
    for (int s = 0; s < 16; s++)
        g_hch[((size_t)(s * 128 + g) << 10) + d] = fmaf(P[s], hin[s], h[s]);
    __threadfence();
    __syncthreads();
    if (tid == 0) atomicExch(&g_flag[blk], 1);

    float q[16];
#pragma unroll
    for (int s = 0; s < 16; s++) q[s] = hin[s];
#pragma unroll 2
    for (int t = 0; t < 64; t++) {
        int r = rbase + t;
        float delta = g_delta[(size_t)r * DIN + d];
        float zv = g_xz[(size_t)xzrow(r, dup) * 2048 + 1024 + d];
        float ylin = g_x[(size_t)r * DIN + d];
        const float4* cp = (const float4*)(g_xdbl + (size_t)r * 64 + 48);
        float4 Cq[4];
#pragma unroll
        for (int u = 0; u < 4; u++) Cq[u] = cp[u];
        const float* Cv = (const float*)Cq;
        float p[16];
        if (CHAIN) powers16(__expf(delta * Av[0]), p);
        else {
#pragma unroll
            for (int s = 0; s < 16; s++) p[s] = __expf(delta * Av[s]);
        }
        float c0 = 0.f, c1 = 0.f, c2 = 0.f, c3 = 0.f;
#pragma unroll
        for (int s = 0; s < 16; s++) {
            q[s] *= p[s];
            float hv = q[s] * Cv[s];
            if ((s & 3) == 0) c0 += hv;
            else if ((s & 3) == 1) c1 += hv;
            else if ((s & 3) == 2) c2 += hv;
            else c3 += hv;
        }
        float y = ylin + (c0 + c1) + (c2 + c3);
        float sg = __fdividef(zv, 1.f + __expf(-zv));
        g_ah[(size_t)r * DIN + d] = __float2half_rn(y * sg);
    }
}

__global__ __launch_bounds__(128) void k_scanF(const float* __restrict__ Alog,
                                               const float* __restrict__ Dp,
                                               int lgNCH, int w0, int w1, int w2, int w3,
                                               int dup) {
    int blk = blockIdx.x;
    int dg = blk & 7;
    int g = blk >> 3;
    int seq = g >> lgNCH;
    int j = g & ((1 << lgNCH) - 1);
    int d = (dg << 7) | threadIdx.x;
    int m = wsel4(seq >> 2, w0, w1, w2, w3);
    float Av[16];
    const float* ap = Alog + ((size_t)m * DIN + d) * 16;
#pragma unroll
    for (int s = 0; s < 16; s++) Av[s] = -__expf(ap[s]);
    bool chain = true;
#pragma unroll
    for (int s = 1; s < 16; s++)
        chain = chain &&
                (fabsf(Av[s] - (float)(s + 1) * Av[0]) <=
                 1e-3f * (float)(s + 1) * fabsf(Av[0]) + 1e-7f);
    float Dv = Dp[m * DIN + d];
    int rbase = g << 6;
    if (chain) scanF_body<true>(rbase, d, g, j, blk, dup, Av, Dv);
    else       scanF_body<false>(rbase, d, g, j, blk, dup, Av, Dv);
}

// ---------------------------------------------------------------------------
// layer-0 epilogue: fold halves, layernorm, residual; emit layer-1 GEMM input
// (forward + reversed copies) as single fp16.
// ---------------------------------------------------------------------------
__global__ __launch_bounds__(128) void k_combine(
    const float* __restrict__ s0, const float* __restrict__ s1,
    const float* __restrict__ s2, const float* __restrict__ s3,
    const float* __restrict__ lnw, const float* __restrict__ lnb) {
    int blk = blockIdx.x;
    int t = blk & 255;
    int b = (blk >> 8) & 3;
    int slot = blk >> 10;
    const float* src = slot == 0 ? s0 : slot == 1 ? s1 : slot == 2 ? s2 : s3;
    int rowA = ((slot * 4 + b) * 512 + t) * CC;
    int rowB = ((slot * 4 + b) * 512 + (511 - t)) * CC;
    int tid = threadIdx.x;
    float v[4];
#pragma unroll
    for (int j = 0; j < 4; j++) {
        int c = tid + j * 128;
        v[j] = 0.5f * (g_o[rowA + c] + g_o[rowB + c]);
    }
    __shared__ float red[8];
    int wid = tid >> 5, lane = tid & 31;
    float s = (v[0] + v[1]) + (v[2] + v[3]);
#pragma unroll
    for (int o = 16; o; o >>= 1) s += __shfl_xor_sync(~0u, s, o);
    if (lane == 0) red[wid] = s;
    __syncthreads();
    float mean = (red[0] + red[1] + red[2] + red[3]) * (1.f / 512.f);
    float q = 0.f;
#pragma unroll
    for (int j = 0; j < 4; j++) { float dd = v[j] - mean; q = fmaf(dd, dd, q); }
#pragma unroll
    for (int o = 16; o; o >>= 1) q += __shfl_xor_sync(~0u, q, o);
    if (lane == 0) red[4 + wid] = q;
    __syncthreads();
    float var = (red[4] + red[5] + red[6] + red[7]) * (1.f / 512.f);
    float rstd = rsqrtf(var + 1e-5f);
    int tau = slot * 256 + t;
#pragma unroll
    for (int j = 0; j < 4; j++) {
        int c = tid + j * 128;
        float o = (v[j] - mean) * rstd * lnw[c] + lnb[c] + src[(b * 256 + t) * CC + c];
        __half hv = __float2half_rn(o);
        g_ah[((size_t)(b * 1024) + tau) * CC + c] = hv;
        g_ah[((size_t)((4 + b) * 1024) + (1023 - tau)) * CC + c] = hv;
    }
}

// final: fused = 0.5*(o4 + reverse(o5)); float4 per thread
__global__ void k_final(float* __restrict__ out) {
    int idx = blockIdx.x * blockDim.x + threadIdx.x;
    if (idx >= BB * 1024 * CC / 4) return;
    int c4 = (idx & 127) << 2;
    int rest = idx >> 7;
    int tau = rest & 1023;
    int b = rest >> 10;
    float4 a = *(const float4*)(g_o + ((size_t)(b * 1024) + tau) * CC + c4);
    float4 bb = *(const float4*)(g_o + ((size_t)((4 + b) * 1024) + (1023 - tau)) * CC + c4);
    float4 f = make_float4(0.5f * (a.x + bb.x), 0.5f * (a.y + bb.y),
                           0.5f * (a.z + bb.z), 0.5f * (a.w + bb.w));
    int i = tau >> 8;
    int t = tau & 255;
    *(float4*)(out + (((size_t)(i * 4 + b) * 256 + t) << 9) + c4) = f;
}

// ---------------------------------------------------------------------------
extern "C" void kernel_launch(void* const* d_in, const int* in_sizes, int n_in,
                              void* d_out, int out_size) {
    const float* x0hw = (const float*)d_in[0];
    const float* x1hw = (const float*)d_in[1];
    const float* x0wh = (const float*)d_in[2];
    const float* x1wh = (const float*)d_in[3];
    const float* in_w = (const float*)d_in[4];
    const float* cw   = (const float*)d_in[5];
    const float* cb   = (const float*)d_in[6];
    const float* xw   = (const float*)d_in[7];
    const float* dtw  = (const float*)d_in[8];
    const float* dtb  = (const float*)d_in[9];
    const float* alog = (const float*)d_in[10];
    const float* Dp   = (const float*)d_in[11];
    const float* ow   = (const float*)d_in[12];
    const float* lnw  = (const float*)d_in[13];
    const float* lnb  = (const float*)d_in[14];
    float* out = (float*)d_out;

    float *pxz, *px, *po;
    cudaGetSymbolAddress((void**)&pxz, g_xz);
    cudaGetSymbolAddress((void**)&px, g_x);
    cudaGetSymbolAddress((void**)&po, g_o);
    __half *pah, *pwih, *pwil, *pwoh, *pwol;
    cudaGetSymbolAddress((void**)&pah, g_ah);
    cudaGetSymbolAddress((void**)&pwih, g_wih);
    cudaGetSymbolAddress((void**)&pwil, g_wil);
    cudaGetSymbolAddress((void**)&pwoh, g_woh);
    cudaGetSymbolAddress((void**)&pwol, g_wol);

    static int inited = 0;
    static cudaStream_t s2;
    static cudaEvent_t evX0, evZ0, evX1, evZ1;
    if (!inited) {
        cudaFuncSetAttribute(k_mma, cudaFuncAttributeMaxDynamicSharedMemorySize,
                             3 * M2_STAGE);
        cudaStreamCreateWithFlags(&s2, cudaStreamNonBlocking);
        cudaEventCreateWithFlags(&evX0, cudaEventDisableTiming);
        cudaEventCreateWithFlags(&evZ0, cudaEventDisableTiming);
        cudaEventCreateWithFlags(&evX1, cudaEventDisableTiming);
        cudaEventCreateWithFlags(&evZ1, cudaEventDisableTiming);
        inited = 1;
    }
    const int MMSMEM = 3 * M2_STAGE;

    const int EL = RTOK * DIN;
    const int ELF = BB * 1024 * CC;
    const size_t ZW = (size_t)1024 * 512;

    // weights -> fp16 hi/lo (vectorized)
    k_cvt<<<(6 * 2048 * 512 / 4 + 255) / 256, 256>>>(in_w, pwih, pwil, 6 * 2048 * 512 / 4);
    k_cvt<<<(6 * 512 * 1024 / 4 + 255) / 256, 256>>>(ow, pwoh, pwol, 6 * 512 * 1024 / 4);

    // ---------------- layer 0 (T=512, NCH=8; compact in_proj) ---------------
    {
        const int w0 = 0, w1 = 2, w2 = 1, w3 = 3, rpg = 2048, T = 512, lg = 3;
        k_build4<<<(4096 * CC / 4 + 255) / 256, 256>>>(x0hw, x1hw, x0wh, x1wh);
        k_mma<<<dim3(4, 32), 512, MMSMEM>>>(
            pah, pwih, pwil, pxz, 512, 2048, 1024, 2048 * 512, w0, w1, w2, w3);
        cudaEventRecord(evX0, 0);
        cudaStreamWaitEvent(s2, evX0, 0);
        k_mma<<<dim3(4, 32), 512, MMSMEM, s2>>>(
            pah, pwih + ZW, pwil + ZW, pxz + 1024, 512, 2048,
            1024, 2048 * 512, w0, w1, w2, w3);
        cudaEventRecord(evZ0, s2);
        k_conv<<<(EL / 4 + 255) / 256, 256>>>(cw, cb, T, rpg, w0, w1, w2, w3, 1);
        k_gemm64sk<<<dim3(1, RTOK / 64, 8), 256>>>(px, xw, rpg, 64 * 1024, w0, w1, w2, w3);
        k_reduce8<<<(RTOK * 64 + 255) / 256, 256>>>();
        k_gemm64dt<<<dim3(1024 / 64, RTOK / 64), 256>>>(dtw, dtb, rpg, w0, w1, w2, w3);
        cudaStreamWaitEvent(0, evZ0, 0);   // scanF gates with z
        k_scanF<<<1024, 128>>>(alog, Dp, lg, w0, w1, w2, w3, 1);
        k_mma<<<dim3(2, 64), 512, MMSMEM>>>(
            pah, pwoh, pwol, po, 1024, 512, rpg, 512 * 1024, w0, w1, w2, w3);
        k_combine<<<4096, 128>>>(x0hw, x1hw, x0wh, x1wh, lnw, lnb);
    }

    // ---------------- layer 1 (T=1024, NCH=16) ----------------
    {
        const int w0 = 4, w1 = 5, w2 = 4, w3 = 5, rpg = 4096, T = 1024, lg = 4;
        k_mma<<<dim3(4, 64), 512, MMSMEM>>>(
            pah, pwih, pwil, pxz, 512, 2048, rpg, 2048 * 512, w0, w1, w2, w3);
        cudaEventRecord(evX1, 0);
        cudaStreamWaitEvent(s2, evX1, 0);
        k_mma<<<dim3(4, 64), 512, MMSMEM, s2>>>(
            pah, pwih + ZW, pwil + ZW, pxz + 1024, 512, 2048,
            rpg, 2048 * 512, w0, w1, w2, w3);
        cudaEventRecord(evZ1, s2);
        k_conv<<<(EL / 4 + 255) / 256, 256>>>(cw, cb, T, rpg, w0, w1, w2, w3, 0);
        k_gemm64sk<<<dim3(1, RTOK / 64, 8), 256>>>(px, xw, rpg, 64 * 1024, w0, w1, w2, w3);
        k_reduce8<<<(RTOK * 64 + 255) / 256, 256>>>();
        k_gemm64dt<<<dim3(1024 / 64, RTOK / 64), 256>>>(dtw, dtb, rpg, w0, w1, w2, w3);
        cudaStreamWaitEvent(0, evZ1, 0);
        k_scanF<<<1024, 128>>>(alog, Dp, lg, w0, w1, w2, w3, 0);
        k_mma<<<dim3(2, 64), 512, MMSMEM>>>(
            pah, pwoh, pwol, po, 1024, 512, rpg, 512 * 1024, w0, w1, w2, w3);
        k_final<<<(ELF / 4 + 255) / 256, 256>>>(out);
    }
}